// round 8
// baseline (speedup 1.0000x reference)
#include <cuda_runtime.h>
#include <cuda_bf16.h>
#include <math.h>
#include <stdint.h>

#define BB 4
#define SS 128
#define DD 512
#define HH 8
#define DH 64
#define FF 2048
#define RR 8
#define BS (BB*SS)          // 512
#define UU 262144           // 512*512
#define THRESH 0.1f

typedef __nv_bfloat16 bf16;

// ======================= helpers =======================
__device__ __forceinline__ uint32_t smem_u32(const void* p){
    uint32_t a;
    asm("{ .reg .u64 t; cvta.to.shared.u64 t, %1; cvt.u32.u64 %0, t; }" : "=r"(a) : "l"(p));
    return a;
}
__device__ __forceinline__ void ldsm4(uint32_t& r0, uint32_t& r1, uint32_t& r2, uint32_t& r3,
                                      uint32_t addr){
    asm volatile("ldmatrix.sync.aligned.m8n8.x4.shared.b16 {%0,%1,%2,%3}, [%4];"
                 : "=r"(r0), "=r"(r1), "=r"(r2), "=r"(r3) : "r"(addr));
}
__device__ __forceinline__ void mma16816(float* d, const uint32_t* a, const uint32_t* b){
    asm volatile("mma.sync.aligned.m16n8k16.row.col.f32.bf16.bf16.f32 "
                 "{%0,%1,%2,%3}, {%4,%5,%6,%7}, {%8,%9}, {%0,%1,%2,%3};"
                 : "+f"(d[0]), "+f"(d[1]), "+f"(d[2]), "+f"(d[3])
                 : "r"(a[0]), "r"(a[1]), "r"(a[2]), "r"(a[3]), "r"(b[0]), "r"(b[1]));
}
__device__ __forceinline__ void cpa16(uint32_t s, const void* g){
    asm volatile("cp.async.cg.shared.global [%0], [%1], 16;" :: "r"(s), "l"(g));
}
__device__ __forceinline__ void cpa_commit(){
    asm volatile("cp.async.commit_group;" ::: "memory");
}
template<int N> __device__ __forceinline__ void cpa_wait(){
    asm volatile("cp.async.wait_group %0;" :: "n"(N) : "memory");
}

// ======================= scratch (device globals) =======================
__device__ bf16  g_wTh[23*UU];          // packed transposed weights, hi
__device__ bf16  g_wTl[23*UU];          // packed transposed weights, lo
__device__ float g_b3[3*DD];            // packed q/k/v biases
__device__ bf16  g_xnh[UU], g_xnl[UU];
__device__ float g_qkv[3*UU];
__device__ float g_attn[BB*HH*SS*SS];
__device__ float g_am[BB*SS*SS];
__device__ bf16  g_ctxh[UU], g_ctxl[UU];
__device__ bf16  g_aoh[UU],  g_aol[UU];
__device__ bf16  g_hidh[BS*FF], g_hidl[BS*FF];
__device__ float g_nupart[4*UU];        // split-K partials for nu
__device__ float g_nu[UU];
__device__ bf16  g_nuh[UU], g_nul[UU];
__device__ float g_abt[10*UU];          // [0,1]=a/b parts, [2..9]=trans slabs [r][n][d]
__device__ int   g_rel[BB*SS*SS];
__device__ bf16  g_rsh[UU], g_rsl[UU];
__device__ float g_nr[UU];

struct WUnit { const float* src; int ld; long dst; int dld; };
__device__ WUnit g_wu[23];

// ======================= setup: weight-unit table + packed biases =======================
__global__ void setup_k(const float* wq, const float* wk, const float* wv, const float* wo,
                        const float* w1, const float* w2, const float* rc, const float* kg,
                        const float* s2n, const float* bq, const float* bk, const float* bvv)
{
    int t = threadIdx.x;
    if (t < DD) { g_b3[t] = bq[t]; g_b3[DD+t] = bk[t]; g_b3[2*DD+t] = bvv[t]; }
    if (t == 0) {
        const float* qkv[3] = {wq, wk, wv};
        for (int u = 0; u < 3; u++) g_wu[u] = {qkv[u], DD, (long)u*UU, DD};
        g_wu[3] = {wo, DD, 3L*UU, DD};
        for (int u = 0; u < 4; u++)                       // w1 [512][2048] -> [2048][512]
            g_wu[4+u] = {w1 + u*DD, FF, 4L*UU + (long)u*UU, DD};
        for (int u = 0; u < 4; u++)                       // w2 [2048][512] -> [512][2048]
            g_wu[8+u] = {w2 + (long)u*UU, DD, 8L*UU + (long)u*DD, FF};
        for (int u = 0; u < 2; u++)
            g_wu[12+u] = {rc + (long)u*UU, DD, (12L+u)*UU, DD};
        for (int u = 0; u < 8; u++)
            g_wu[14+u] = {kg + (long)u*UU, DD, (14L+u)*UU, DD};
        g_wu[22] = {s2n, DD, 22L*UU, DD};
    }
}

// ======================= weight transpose + fp32 -> bf16 hi/lo =======================
__global__ void wconv_k()
{
    __shared__ float tile[32][33];
    WUnit u = g_wu[blockIdx.z];
    int k0 = blockIdx.y * 32, n0 = blockIdx.x * 32;
    int tx = threadIdx.x, ty = threadIdx.y;        // (32, 8)
#pragma unroll
    for (int i = 0; i < 4; i++)
        tile[ty + 8*i][tx] = __ldg(u.src + (long)(k0 + ty + 8*i) * u.ld + n0 + tx);
    __syncthreads();
#pragma unroll
    for (int i = 0; i < 4; i++) {
        int n = n0 + ty + 8*i, k = k0 + tx;
        float v = tile[tx][ty + 8*i];
        bf16 h = __float2bfloat16(v);
        bf16 l = __float2bfloat16(v - __bfloat162float(h));
        long off = u.dst + (long)n * u.dld + k;
        g_wTh[off] = h; g_wTl[off] = l;
    }
}

// ============ mma.sync bf16 3-pass GEMM, 32x64 CTA tile, cp.async 2-stage ============
#define FL_F32  1
#define FL_HILO 2
#define FL_RELU 4

#define TSTRIDE 144                      // smem row stride bytes (72 bf16)
#define OA_H 0                           // A hi: 32 rows
#define OA_L 4608                        // A lo: 32 rows
#define OB_H 9216                        // B hi: 64 rows
#define OB_L 18432                       // B lo: 64 rows
#define STAGE_B 27648
#define GSM 55296                        // 2 stages

__global__ void __launch_bounds__(256, 4)
gemm_mma(const bf16* __restrict__ Ah, const bf16* __restrict__ Al, int lda, long a_z,
         const bf16* __restrict__ Bh, const bf16* __restrict__ Bl, long b_z, int ldb,
         const float* __restrict__ bias, int bias_z,
         float* __restrict__ C, long c_z, int ldc,
         bf16* __restrict__ Ch, bf16* __restrict__ Cl, int ldch,
         int K, int flags)
{
    extern __shared__ char sm[];
    uint32_t sb = smem_u32(sm);
    const int tid = threadIdx.x, lane = tid & 31, wid = tid >> 5;
    const int wm = wid >> 2, wn = wid & 3;               // warp grid 2(m) x 4(n), warp tile 16x16
    const int m0 = blockIdx.y * 32, n0 = blockIdx.x * 64, z = blockIdx.z;
    const bf16* Ahp = Ah + (long)z * a_z;
    const bf16* Alp = Al + (long)z * a_z;
    const bf16* Bhp = Bh + (long)z * b_z;
    const bf16* Blp = Bl + (long)z * b_z;

    const int ld_r = tid >> 3, ld_c = (tid & 7) * 8;     // 32 rows x 8 col-segs
    const uint32_t s_wr = (uint32_t)(ld_r * TSTRIDE + ld_c * 2);

    const int a_r = (lane & 7) + ((lane >> 3) & 1) * 8;
    const int a_c8 = (lane >> 4) * 8;
    const uint32_t aoff = (uint32_t)((wm * 16 + a_r) * TSTRIDE + a_c8 * 2);
    const int b_r = (lane & 7) + (lane >> 4) * 8;
    const int b_c8 = ((lane >> 3) & 1) * 8;
    const uint32_t boff = (uint32_t)((wn * 16 + b_r) * TSTRIDE + b_c8 * 2);

    float acc[2][4];
#pragma unroll
    for (int j = 0; j < 2; j++)
#pragma unroll
        for (int q = 0; q < 4; q++) acc[j][q] = 0.f;

    uint32_t fah[2][4], fal[2][4], fbh[2][2][2], fbl[2][2][2];

    const int nch = K >> 6;

    auto issue = [&](int kk, int st){
        uint32_t base = sb + st * STAGE_B + s_wr;
        const bf16* ga0 = Ahp + (long)(m0 + ld_r) * lda + kk + ld_c;
        const bf16* ga1 = Alp + (long)(m0 + ld_r) * lda + kk + ld_c;
        const bf16* gb0 = Bhp + (long)(n0 + ld_r) * ldb + kk + ld_c;
        const bf16* gb1 = Blp + (long)(n0 + ld_r) * ldb + kk + ld_c;
        cpa16(base + OA_H, ga0);
        cpa16(base + OA_L, ga1);
        cpa16(base + OB_H,                gb0);
        cpa16(base + OB_H + 32 * TSTRIDE, gb0 + 32 * ldb);
        cpa16(base + OB_L,                gb1);
        cpa16(base + OB_L + 32 * TSTRIDE, gb1 + 32 * ldb);
        cpa_commit();
    };

    issue(0, 0);
    for (int i = 0; i < nch; i++) {
        if (i + 1 < nch) { issue((i + 1) << 6, (i + 1) & 1); cpa_wait<1>(); }
        else             { cpa_wait<0>(); }
        __syncthreads();

        uint32_t st = sb + (i & 1) * STAGE_B;

        // prologue fragments for ks=0
        ldsm4(fbh[0][0][0], fbh[0][0][1], fbh[0][1][0], fbh[0][1][1], st + OB_H + boff);
        ldsm4(fbl[0][0][0], fbl[0][0][1], fbl[0][1][0], fbl[0][1][1], st + OB_L + boff);
        ldsm4(fah[0][0], fah[0][1], fah[0][2], fah[0][3], st + OA_H + aoff);
        ldsm4(fal[0][0], fal[0][1], fal[0][2], fal[0][3], st + OA_L + aoff);

#pragma unroll
        for (int ks = 0; ks < 4; ks++) {
            const int cur = ks & 1, nxt = cur ^ 1;
            if (ks < 3) {
                uint32_t kb = (ks + 1) * 32;
                ldsm4(fbh[nxt][0][0], fbh[nxt][0][1], fbh[nxt][1][0], fbh[nxt][1][1],
                      st + OB_H + boff + kb);
                ldsm4(fbl[nxt][0][0], fbl[nxt][0][1], fbl[nxt][1][0], fbl[nxt][1][1],
                      st + OB_L + boff + kb);
                ldsm4(fah[nxt][0], fah[nxt][1], fah[nxt][2], fah[nxt][3],
                      st + OA_H + aoff + kb);
                ldsm4(fal[nxt][0], fal[nxt][1], fal[nxt][2], fal[nxt][3],
                      st + OA_L + aoff + kb);
            }
#pragma unroll
            for (int nf = 0; nf < 2; nf++) mma16816(acc[nf], fah[cur], fbh[cur][nf]);
#pragma unroll
            for (int nf = 0; nf < 2; nf++) mma16816(acc[nf], fah[cur], fbl[cur][nf]);
#pragma unroll
            for (int nf = 0; nf < 2; nf++) mma16816(acc[nf], fal[cur], fbh[cur][nf]);
        }
        __syncthreads();
    }

    // epilogue
    const int g = lane >> 2, tg = lane & 3;
    const float* bp = bias ? bias + (long)z * bias_z : nullptr;
    float* Cz = C ? C + (long)z * c_z : nullptr;
#pragma unroll
    for (int nf = 0; nf < 2; nf++) {
        int row = m0 + wm * 16 + g;
        int col = n0 + wn * 16 + nf * 8 + tg * 2;
        float v0 = acc[nf][0], v1 = acc[nf][1];
        float v2 = acc[nf][2], v3 = acc[nf][3];
        if (bp) {
            float bb0 = __ldg(bp + col), bb1 = __ldg(bp + col + 1);
            v0 += bb0; v1 += bb1; v2 += bb0; v3 += bb1;
        }
        if (flags & FL_RELU) {
            v0 = fmaxf(v0, 0.f); v1 = fmaxf(v1, 0.f);
            v2 = fmaxf(v2, 0.f); v3 = fmaxf(v3, 0.f);
        }
        if (flags & FL_F32) {
            *(float2*)&Cz[(long)row * ldc + col] = make_float2(v0, v1);
            *(float2*)&Cz[(long)(row + 8) * ldc + col] = make_float2(v2, v3);
        }
        if (flags & FL_HILO) {
            bf16 h0 = __float2bfloat16(v0), h1 = __float2bfloat16(v1);
            bf16 h2 = __float2bfloat16(v2), h3 = __float2bfloat16(v3);
            __nv_bfloat162 ph0; ph0.x = h0; ph0.y = h1;
            __nv_bfloat162 ph1; ph1.x = h2; ph1.y = h3;
            __nv_bfloat162 pl0, pl1;
            pl0.x = __float2bfloat16(v0 - __bfloat162float(h0));
            pl0.y = __float2bfloat16(v1 - __bfloat162float(h1));
            pl1.x = __float2bfloat16(v2 - __bfloat162float(h2));
            pl1.y = __float2bfloat16(v3 - __bfloat162float(h3));
            *(__nv_bfloat162*)&Ch[(long)row * ldch + col] = ph0;
            *(__nv_bfloat162*)&Cl[(long)row * ldch + col] = pl0;
            *(__nv_bfloat162*)&Ch[(long)(row + 8) * ldch + col] = ph1;
            *(__nv_bfloat162*)&Cl[(long)(row + 8) * ldch + col] = pl1;
        }
    }
}

// ======================= LayerNorms =======================
__global__ void ln1_k(const float* __restrict__ in, const float* __restrict__ g,
                      const float* __restrict__ b, bf16* __restrict__ oh, bf16* __restrict__ ol)
{
    int row = blockIdx.x, t = threadIdx.x;   // 256 threads
    __shared__ float rbuf[256];
    long base = (long)row * DD;
    float v0 = in[base + t], v1 = in[base + t + 256];
    rbuf[t] = v0 + v1; __syncthreads();
    for (int s = 128; s > 0; s >>= 1) { if (t < s) rbuf[t] += rbuf[t + s]; __syncthreads(); }
    float mean = rbuf[0] * (1.0f / 512.0f);
    __syncthreads();
    float d0 = v0 - mean, d1 = v1 - mean;
    rbuf[t] = d0 * d0 + d1 * d1; __syncthreads();
    for (int s = 128; s > 0; s >>= 1) { if (t < s) rbuf[t] += rbuf[t + s]; __syncthreads(); }
    float rs = rsqrtf(rbuf[0] * (1.0f / 512.0f) + 1e-5f);
    float o0 = d0 * rs * g[t] + b[t];
    float o1 = d1 * rs * g[t + 256] + b[t + 256];
    bf16 h0 = __float2bfloat16(o0), h1 = __float2bfloat16(o1);
    oh[base + t] = h0;       ol[base + t]       = __float2bfloat16(o0 - __bfloat162float(h0));
    oh[base + t + 256] = h1; ol[base + t + 256] = __float2bfloat16(o1 - __bfloat162float(h1));
}

__global__ void ln2_k(const float* __restrict__ in, const float* __restrict__ add,
                      const float* __restrict__ g, const float* __restrict__ b,
                      float* __restrict__ out)
{
    int row = blockIdx.x, t = threadIdx.x;
    __shared__ float rbuf[256];
    long base = (long)row * DD;
    float v0 = in[base + t] + add[base + t];
    float v1 = in[base + t + 256] + add[base + t + 256];
    rbuf[t] = v0 + v1; __syncthreads();
    for (int s = 128; s > 0; s >>= 1) { if (t < s) rbuf[t] += rbuf[t + s]; __syncthreads(); }
    float mean = rbuf[0] * (1.0f / 512.0f);
    __syncthreads();
    float d0 = v0 - mean, d1 = v1 - mean;
    rbuf[t] = d0 * d0 + d1 * d1; __syncthreads();
    for (int s = 128; s > 0; s >>= 1) { if (t < s) rbuf[t] += rbuf[t + s]; __syncthreads(); }
    float rs = rsqrtf(rbuf[0] * (1.0f / 512.0f) + 1e-5f);
    out[base + t]       = d0 * rs * g[t]       + b[t];
    out[base + t + 256] = d1 * rs * g[t + 256] + b[t + 256];
}

// ======================= attention: scores+softmax, 16-row tiles =======================
__global__ void attn_scores_k(const float* __restrict__ q, const float* __restrict__ k,
                              float* __restrict__ attn)
{
    int it = blockIdx.x, h = blockIdx.y, b = blockIdx.z;  // 256 thr
    int t = threadIdx.x;
    int i0 = it * 16;
    __shared__ float ks[SS][DH + 1];
    __shared__ float qs[16][DH + 1];
    __shared__ float P[16][SS];
    const float* kbase = k + (long)b * SS * DD + h * DH;
    const float* qbase = q + (long)b * SS * DD + h * DH;
    for (int idx = t; idx < SS * DH; idx += 256) {
        int j = idx >> 6, d = idx & 63;
        ks[j][d] = kbase[(long)j * DD + d];
    }
    for (int idx = t; idx < 16 * DH; idx += 256) {
        int r = idx >> 6, d = idx & 63;
        qs[r][d] = qbase[(long)(i0 + r) * DD + d];
    }
    __syncthreads();
    {
        int j = t & 127, grp = t >> 7;
#pragma unroll
        for (int r = 0; r < 8; r++) {
            int i = grp * 8 + r;
            float acc = 0.f;
#pragma unroll
            for (int d = 0; d < DH; d++) acc += qs[i][d] * ks[j][d];
            P[i][j] = acc * 0.125f;
        }
    }
    __syncthreads();
    {
        int w = t >> 5, ln = t & 31;
        long obase = (((long)(b * HH + h) * SS) + i0) * SS;
#pragma unroll
        for (int rr = 0; rr < 2; rr++) {
            int i = w * 2 + rr;
            float m = -1e30f;
#pragma unroll
            for (int c = 0; c < 4; c++) m = fmaxf(m, P[i][ln + c * 32]);
#pragma unroll
            for (int o = 16; o > 0; o >>= 1) m = fmaxf(m, __shfl_xor_sync(0xffffffffu, m, o));
            float s = 0.f, e[4];
#pragma unroll
            for (int c = 0; c < 4; c++) { e[c] = expf(P[i][ln + c * 32] - m); s += e[c]; }
#pragma unroll
            for (int o = 16; o > 0; o >>= 1) s += __shfl_xor_sync(0xffffffffu, s, o);
            float inv = 1.0f / s;
#pragma unroll
            for (int c = 0; c < 4; c++) attn[obase + (long)i * SS + ln + c * 32] = e[c] * inv;
        }
    }
}

__global__ void am_k(const float* __restrict__ attn, float* __restrict__ am)
{
    int bi = blockIdx.x;
    int b = bi >> 7, i = bi & 127, t = threadIdx.x;  // 128 thr
    float s = 0.f;
#pragma unroll
    for (int h = 0; h < HH; h++)
        s += attn[(((long)(b * HH + h) * SS) + i) * SS + t];
    am[(long)bi * SS + t] = s * 0.125f;
}

// ======================= attention: ctx = P @ V, 16-row tiles =======================
__global__ void attn_ctx_k(const float* __restrict__ attn, const float* __restrict__ v,
                           bf16* __restrict__ ch, bf16* __restrict__ cl)
{
    int it = blockIdx.x, h = blockIdx.y, b = blockIdx.z;  // 256 thr
    int t = threadIdx.x;
    int i0 = it * 16;
    int d = t & 63, ig = t >> 6;          // ig in 0..3; rows i = ig + 4*r
    __shared__ float vs[SS][DH + 1];
    __shared__ float at[16][SS];
    const float* vbase = v + (long)b * SS * DD + h * DH;
    for (int idx = t; idx < SS * DH; idx += 256) {
        int j = idx >> 6, dd = idx & 63;
        vs[j][dd] = vbase[(long)j * DD + dd];
    }
    long arow = (((long)(b * HH + h) * SS) + i0) * SS;
    for (int idx = t; idx < 16 * SS; idx += 256)
        at[idx >> 7][idx & 127] = attn[arow + (long)(idx >> 7) * SS + (idx & 127)];
    __syncthreads();

    float acc[4] = {0.f, 0.f, 0.f, 0.f};
#pragma unroll
    for (int jh = 0; jh < 2; jh++) {
        float vreg[64];
#pragma unroll
        for (int jj = 0; jj < 64; jj++) vreg[jj] = vs[jh * 64 + jj][d];
#pragma unroll
        for (int r = 0; r < 4; r++) {
            int i = ig + 4 * r;
            float a = acc[r];
#pragma unroll
            for (int jj = 0; jj < 64; jj++) a += at[i][jh * 64 + jj] * vreg[jj];
            acc[r] = a;
        }
    }
#pragma unroll
    for (int r = 0; r < 4; r++) {
        int i = ig + 4 * r;
        long o = (long)(b * SS + i0 + i) * DD + h * DH + d;
        bf16 hh = __float2bfloat16(acc[r]);
        ch[o] = hh; cl[o] = __float2bfloat16(acc[r] - __bfloat162float(hh));
    }
}

// ======================= nu: reduce split-K partials + bias + hi/lo =======================
__global__ void conv_nu_k(const float* __restrict__ P, const float* __restrict__ b2,
                          float* __restrict__ nu, bf16* __restrict__ H, bf16* __restrict__ L)
{
    int row = blockIdx.x, t = threadIdx.x;  // 256
    for (int c = t; c < DD; c += 256) {
        long i = (long)row * DD + c;
        float v = b2[c] + P[i] + P[UU + i] + P[2L*UU + i] + P[3L*UU + i];
        nu[i] = v;
        bf16 h = __float2bfloat16(v);
        H[i] = h; L[i] = __float2bfloat16(v - __bfloat162float(h));
    }
}

// ======================= pair relation classifier =======================
__global__ void pair_k(const float* __restrict__ ap, const float* __restrict__ bp,
                       const float* __restrict__ rc_b1, const float* __restrict__ rc_w2,
                       const float* __restrict__ rc_b2, const float* __restrict__ am,
                       int* __restrict__ rel)
{
    int b = blockIdx.z;
    int u0 = blockIdx.y * 16, v0 = blockIdx.x * 16;
    int t = threadIdx.x;                 // 256
    int ul = t >> 4, vl = t & 15;
    __shared__ float sA[16][65], sB[16][65], sW[64][8], sC[64];
    float acc[RR];
#pragma unroll
    for (int r = 0; r < RR; r++) acc[r] = rc_b2[r];

    for (int c0 = 0; c0 < DD; c0 += 64) {
        for (int idx = t; idx < 1024; idx += 256) {
            int rr = idx >> 6, cc = idx & 63;
            sA[rr][cc] = ap[(long)(b * SS + u0 + rr) * DD + c0 + cc];
            sB[rr][cc] = bp[(long)(b * SS + v0 + rr) * DD + c0 + cc];
        }
        for (int idx = t; idx < 512; idx += 256)
            sW[idx >> 3][idx & 7] = rc_w2[(long)(c0 + (idx >> 3)) * RR + (idx & 7)];
        if (t < 64) sC[t] = rc_b1[c0 + t];
        __syncthreads();
#pragma unroll 4
        for (int dd = 0; dd < 64; dd++) {
            float hsum = sA[ul][dd] + sB[vl][dd] + sC[dd];
            hsum = fmaxf(hsum, 0.f);
            float4 w0 = *(float4*)&sW[dd][0];
            float4 w1 = *(float4*)&sW[dd][4];
            acc[0] += hsum * w0.x; acc[1] += hsum * w0.y;
            acc[2] += hsum * w0.z; acc[3] += hsum * w0.w;
            acc[4] += hsum * w1.x; acc[5] += hsum * w1.y;
            acc[6] += hsum * w1.z; acc[7] += hsum * w1.w;
        }
        __syncthreads();
    }
    int pred = 0; float best = acc[0];
#pragma unroll
    for (int r = 1; r < RR; r++) if (acc[r] > best) { best = acc[r]; pred = r; }
    int u = u0 + ul, v = v0 + vl;
    float amv = am[((long)b * SS + u) * SS + v];
    int valid = (amv > THRESH) && (u != v) && (pred != 0);
    rel[((long)b * SS + u) * SS + v] = valid ? pred : 0;
}

// ======================= edge aggregation (trans slabs [r][n][d]) =======================
__global__ void agg_k(const int* __restrict__ rel, const float* __restrict__ trans,
                      const float* __restrict__ nu, bf16* __restrict__ rh, bf16* __restrict__ rl)
{
    int bv = blockIdx.x;                 // b*S + v
    int b = bv >> 7, v = bv & 127, t = threadIdx.x;   // 256
    __shared__ int sr[SS];
    if (t < SS) sr[t] = rel[((long)b * SS + t) * SS + v];
    __syncthreads();
    float a0 = 0.f, a1 = 0.f;
    for (int u = 0; u < SS; u++) {
        int r = sr[u];
        if (r) {
            const float* tr = trans + (long)r * UU + (long)(b * SS + u) * DD;
            a0 += tr[t]; a1 += tr[t + 256];
        }
    }
    long row = (long)bv * DD;
    float v0 = nu[row + t] + a0;
    float v1 = nu[row + t + 256] + a1;
    bf16 h0 = __float2bfloat16(v0), h1 = __float2bfloat16(v1);
    rh[row + t] = h0;       rl[row + t]       = __float2bfloat16(v0 - __bfloat162float(h0));
    rh[row + t + 256] = h1; rl[row + t + 256] = __float2bfloat16(v1 - __bfloat162float(h1));
}

// ======================= launch =======================
extern "C" void kernel_launch(void* const* d_in, const int* in_sizes, int n_in,
                              void* d_out, int out_size)
{
    const float* x     = (const float*)d_in[0];
    const float* ln1_g = (const float*)d_in[1];
    const float* ln1_b = (const float*)d_in[2];
    const float* wq    = (const float*)d_in[3];
    const float* bq    = (const float*)d_in[4];
    const float* wk    = (const float*)d_in[5];
    const float* bk    = (const float*)d_in[6];
    const float* wv    = (const float*)d_in[7];
    const float* bvv   = (const float*)d_in[8];
    const float* wo    = (const float*)d_in[9];
    const float* bo    = (const float*)d_in[10];
    const float* w1    = (const float*)d_in[11];
    const float* b1    = (const float*)d_in[12];
    const float* w2    = (const float*)d_in[13];
    const float* b2    = (const float*)d_in[14];
    const float* rc_w1 = (const float*)d_in[15];
    const float* rc_b1 = (const float*)d_in[16];
    const float* rc_w2 = (const float*)d_in[17];
    const float* rc_b2 = (const float*)d_in[18];
    const float* kg_w  = (const float*)d_in[19];
    const float* s2n_w = (const float*)d_in[20];
    const float* s2n_b = (const float*)d_in[21];
    const float* ln2_g = (const float*)d_in[22];
    const float* ln2_b = (const float*)d_in[23];
    float* out = (float*)d_out;

    bf16 *wTh, *wTl, *xnh, *xnl, *ctxh, *ctxl, *aoh, *aol, *hidh, *hidl, *nuh, *nul, *rsh, *rsl;
    float *b3, *qkv, *attn, *am, *nupart, *nu, *abt, *nr;
    int *rel;
    cudaGetSymbolAddress((void**)&wTh, g_wTh);   cudaGetSymbolAddress((void**)&wTl, g_wTl);
    cudaGetSymbolAddress((void**)&b3, g_b3);
    cudaGetSymbolAddress((void**)&xnh, g_xnh);   cudaGetSymbolAddress((void**)&xnl, g_xnl);
    cudaGetSymbolAddress((void**)&qkv, g_qkv);
    cudaGetSymbolAddress((void**)&attn, g_attn); cudaGetSymbolAddress((void**)&am, g_am);
    cudaGetSymbolAddress((void**)&ctxh, g_ctxh); cudaGetSymbolAddress((void**)&ctxl, g_ctxl);
    cudaGetSymbolAddress((void**)&aoh, g_aoh);   cudaGetSymbolAddress((void**)&aol, g_aol);
    cudaGetSymbolAddress((void**)&hidh, g_hidh); cudaGetSymbolAddress((void**)&hidl, g_hidl);
    cudaGetSymbolAddress((void**)&nupart, g_nupart);
    cudaGetSymbolAddress((void**)&nu, g_nu);
    cudaGetSymbolAddress((void**)&nuh, g_nuh);   cudaGetSymbolAddress((void**)&nul, g_nul);
    cudaGetSymbolAddress((void**)&abt, g_abt);
    cudaGetSymbolAddress((void**)&rel, g_rel);
    cudaGetSymbolAddress((void**)&rsh, g_rsh);   cudaGetSymbolAddress((void**)&rsl, g_rsl);
    cudaGetSymbolAddress((void**)&nr, g_nr);

    cudaFuncSetAttribute(gemm_mma, cudaFuncAttributeMaxDynamicSharedMemorySize, GSM);
    cudaFuncSetAttribute(gemm_mma, cudaFuncAttributePreferredSharedMemoryCarveout, 100);

    // weight prep
    setup_k<<<1, 512>>>(wq, wk, wv, wo, w1, w2, rc_w1, kg_w, s2n_w, bq, bk, bvv);
    wconv_k<<<dim3(16, 16, 23), dim3(32, 8)>>>();

    // ln1 -> xn (hi/lo)
    ln1_k<<<BS, 256>>>(x, ln1_g, ln1_b, xnh, xnl);

    // QKV (z=3), fp32 out
    gemm_mma<<<dim3(8, 16, 3), 256, GSM>>>(xnh, xnl, DD, 0, wTh, wTl, UU, DD,
                                           b3, DD, qkv, UU, DD, nullptr, nullptr, 0,
                                           DD, FL_F32);
    // attention (16-row tiled)
    attn_scores_k<<<dim3(8, HH, BB), 256>>>(qkv, qkv + UU, attn);
    am_k<<<BS, 128>>>(attn, am);
    attn_ctx_k<<<dim3(8, HH, BB), 256>>>(attn, qkv + 2 * UU, ctxh, ctxl);

    // ao = ctx @ wo + bo  (hi/lo only)
    gemm_mma<<<dim3(8, 16, 1), 256, GSM>>>(ctxh, ctxl, DD, 0, wTh + 3L*UU, wTl + 3L*UU, 0, DD,
                                           bo, 0, nullptr, 0, 0, aoh, aol, DD,
                                           DD, FL_HILO);
    // hid = relu(ao @ w1 + b1) (hi/lo only, N=2048)
    gemm_mma<<<dim3(32, 16, 1), 256, GSM>>>(aoh, aol, DD, 0, wTh + 4L*UU, wTl + 4L*UU, 0, DD,
                                            b1, 0, nullptr, 0, 0, hidh, hidl, FF,
                                            DD, FL_HILO | FL_RELU);
    // nu partials = hid @ w2  (split-K z=4 into 4 slabs)
    gemm_mma<<<dim3(8, 16, 4), 256, GSM>>>(hidh, hidl, FF, DD, wTh + 8L*UU, wTl + 8L*UU, DD, FF,
                                           nullptr, 0, nupart, UU, DD, nullptr, nullptr, 0,
                                           DD, FL_F32);
    conv_nu_k<<<BS, 256>>>(nupart, b2, nu, nuh, nul);

    // fused: a/b parts (z=0,1) + RGCN transforms (z=2..9) in one launch
    gemm_mma<<<dim3(8, 16, 10), 256, GSM>>>(nuh, nul, DD, 0, wTh + 12L*UU, wTl + 12L*UU, UU, DD,
                                            nullptr, 0, abt, UU, DD, nullptr, nullptr, 0,
                                            DD, FL_F32);
    // edges + aggregation (trans slabs start at abt + 2*UU)
    pair_k<<<dim3(8, 8, BB), 256>>>(abt, abt + UU, rc_b1, rc_w2, rc_b2, am, rel);
    agg_k<<<BS, 256>>>(rel, abt + 2L*UU, nu, rsh, rsl);

    // s2n projection, fp32
    gemm_mma<<<dim3(8, 16, 1), 256, GSM>>>(rsh, rsl, DD, 0, wTh + 22L*UU, wTl + 22L*UU, 0, DD,
                                           s2n_b, 0, nr, 0, DD, nullptr, nullptr, 0,
                                           DD, FL_F32);
    // final residual LN
    ln2_k<<<BS, 256>>>(nr, x, ln2_g, ln2_b, out);
}

// round 10
// speedup vs baseline: 1.0079x; 1.0079x over previous
#include <cuda_runtime.h>
#include <cuda_bf16.h>
#include <math.h>
#include <stdint.h>

#define BB 4
#define SS 128
#define DD 512
#define HH 8
#define DH 64
#define FF 2048
#define RR 8
#define BS (BB*SS)          // 512
#define UU 262144           // 512*512
#define THRESH 0.1f

typedef __nv_bfloat16 bf16;

// ======================= helpers =======================
__device__ __forceinline__ uint32_t smem_u32(const void* p){
    uint32_t a;
    asm("{ .reg .u64 t; cvta.to.shared.u64 t, %1; cvt.u32.u64 %0, t; }" : "=r"(a) : "l"(p));
    return a;
}
__device__ __forceinline__ void ldsm4(uint32_t& r0, uint32_t& r1, uint32_t& r2, uint32_t& r3,
                                      uint32_t addr){
    asm volatile("ldmatrix.sync.aligned.m8n8.x4.shared.b16 {%0,%1,%2,%3}, [%4];"
                 : "=r"(r0), "=r"(r1), "=r"(r2), "=r"(r3) : "r"(addr));
}
__device__ __forceinline__ void mma16816(float* d, const uint32_t* a, const uint32_t* b){
    asm volatile("mma.sync.aligned.m16n8k16.row.col.f32.bf16.bf16.f32 "
                 "{%0,%1,%2,%3}, {%4,%5,%6,%7}, {%8,%9}, {%0,%1,%2,%3};"
                 : "+f"(d[0]), "+f"(d[1]), "+f"(d[2]), "+f"(d[3])
                 : "r"(a[0]), "r"(a[1]), "r"(a[2]), "r"(a[3]), "r"(b[0]), "r"(b[1]));
}
__device__ __forceinline__ void cpa16(uint32_t s, const void* g){
    asm volatile("cp.async.cg.shared.global [%0], [%1], 16;" :: "r"(s), "l"(g));
}
__device__ __forceinline__ void cpa_commit(){
    asm volatile("cp.async.commit_group;" ::: "memory");
}
template<int N> __device__ __forceinline__ void cpa_wait(){
    asm volatile("cp.async.wait_group %0;" :: "n"(N) : "memory");
}

// ======================= scratch (device globals) =======================
__device__ bf16  g_wTh[23*UU];          // packed transposed weights, hi
__device__ bf16  g_wTl[23*UU];          // packed transposed weights, lo
__device__ float g_b3[3*DD];            // packed q/k/v biases
__device__ bf16  g_xnh[UU], g_xnl[UU];
__device__ float g_qkv[3*UU];
__device__ float g_attn[BB*HH*SS*SS];
__device__ float g_am[BB*SS*SS];
__device__ bf16  g_ctxh[UU], g_ctxl[UU];
__device__ bf16  g_aoh[UU],  g_aol[UU];
__device__ bf16  g_hidh[BS*FF], g_hidl[BS*FF];
__device__ float g_nupart[4*UU];        // split-K partials for nu
__device__ float g_nu[UU];
__device__ bf16  g_nuh[UU], g_nul[UU];
__device__ float g_abt[2*UU];           // a/b parts
__device__ int   g_rel[BB*SS*SS];
__device__ bf16  g_rsh[UU], g_rsl[UU];
__device__ float g_nr[UU];

// sparse RGCN structures
__device__ float g_transc[7*512*DD];    // compacted transforms per relation (r-1)
__device__ int   g_map[8*512];          // per-relation compacted node list
__device__ int   g_loc[BS*8];           // (node, r) -> compact position
__device__ int   g_cnt[8];              // per-relation count

struct WUnit { const float* src; int ld; long dst; int dld; };
__device__ WUnit g_wu[23];

// ======================= setup: weight-unit table + packed biases =======================
__global__ void setup_k(const float* wq, const float* wk, const float* wv, const float* wo,
                        const float* w1, const float* w2, const float* rc, const float* kg,
                        const float* s2n, const float* bq, const float* bk, const float* bvv)
{
    int t = threadIdx.x;
    if (t < DD) { g_b3[t] = bq[t]; g_b3[DD+t] = bk[t]; g_b3[2*DD+t] = bvv[t]; }
    if (t < 8) g_cnt[t] = 0;
    if (t == 0) {
        const float* qkv[3] = {wq, wk, wv};
        for (int u = 0; u < 3; u++) g_wu[u] = {qkv[u], DD, (long)u*UU, DD};
        g_wu[3] = {wo, DD, 3L*UU, DD};
        for (int u = 0; u < 4; u++)                       // w1 [512][2048] -> [2048][512]
            g_wu[4+u] = {w1 + u*DD, FF, 4L*UU + (long)u*UU, DD};
        for (int u = 0; u < 4; u++)                       // w2 [2048][512] -> [512][2048]
            g_wu[8+u] = {w2 + (long)u*UU, DD, 8L*UU + (long)u*DD, FF};
        for (int u = 0; u < 2; u++)
            g_wu[12+u] = {rc + (long)u*UU, DD, (12L+u)*UU, DD};
        for (int u = 0; u < 8; u++)
            g_wu[14+u] = {kg + (long)u*UU, DD, (14L+u)*UU, DD};
        g_wu[22] = {s2n, DD, 22L*UU, DD};
    }
}

// ======================= weight transpose + fp32 -> bf16 hi/lo =======================
__global__ void wconv_k()
{
    __shared__ float tile[32][33];
    WUnit u = g_wu[blockIdx.z];
    int k0 = blockIdx.y * 32, n0 = blockIdx.x * 32;
    int tx = threadIdx.x, ty = threadIdx.y;        // (32, 8)
#pragma unroll
    for (int i = 0; i < 4; i++)
        tile[ty + 8*i][tx] = __ldg(u.src + (long)(k0 + ty + 8*i) * u.ld + n0 + tx);
    __syncthreads();
#pragma unroll
    for (int i = 0; i < 4; i++) {
        int n = n0 + ty + 8*i, k = k0 + tx;
        float v = tile[tx][ty + 8*i];
        bf16 h = __float2bfloat16(v);
        bf16 l = __float2bfloat16(v - __bfloat162float(h));
        long off = u.dst + (long)n * u.dld + k;
        g_wTh[off] = h; g_wTl[off] = l;
    }
}

// ======================= mma.sync bf16 3-pass GEMM (64x64 tile, 2-stage) =======================
#define FL_F32  1
#define FL_HILO 2
#define FL_RELU 4

#define TSTRIDE 144                      // smem row stride bytes (72 bf16)
#define TILE_B  9216                     // 64 rows * 144 B
#define STAGE_B 36864                    // 4 tiles
#define GSM     73728                    // 2 stages

__global__ void __launch_bounds__(256, 3)
gemm_mma(const bf16* __restrict__ Ah, const bf16* __restrict__ Al, int lda, long a_z,
         const bf16* __restrict__ Bh, const bf16* __restrict__ Bl, long b_z, int ldb,
         const float* __restrict__ bias, int bias_z,
         float* __restrict__ C, long c_z, int ldc,
         bf16* __restrict__ Ch, bf16* __restrict__ Cl, int ldch,
         int K, int flags)
{
    extern __shared__ char sm[];
    uint32_t sb = smem_u32(sm);
    const int tid = threadIdx.x, lane = tid & 31, wid = tid >> 5;
    const int wm = wid >> 2, wn = wid & 3;               // warp grid 2 x 4
    const int m0 = blockIdx.y * 64, n0 = blockIdx.x * 64, z = blockIdx.z;
    const bf16* Ahp = Ah + (long)z * a_z;
    const bf16* Alp = Al + (long)z * a_z;
    const bf16* Bhp = Bh + (long)z * b_z;
    const bf16* Blp = Bl + (long)z * b_z;

    const int ld_r = tid >> 3, ld_c = (tid & 7) * 8;
    const uint32_t s_wr = (uint32_t)(ld_r * TSTRIDE + ld_c * 2);

    const int a_r = (lane & 7) + ((lane >> 3) & 1) * 8;
    const int a_c8 = (lane >> 4) * 8;
    const uint32_t aoff = (uint32_t)((wm * 32 + a_r) * TSTRIDE + a_c8 * 2);
    const int b_r = (lane & 7) + (lane >> 4) * 8;
    const int b_c8 = ((lane >> 3) & 1) * 8;
    const uint32_t boff = (uint32_t)((wn * 16 + b_r) * TSTRIDE + b_c8 * 2);

    float acc[2][2][4];
#pragma unroll
    for (int i = 0; i < 2; i++)
#pragma unroll
        for (int j = 0; j < 2; j++)
#pragma unroll
            for (int q = 0; q < 4; q++) acc[i][j][q] = 0.f;

    uint32_t fah[2][2][4], fal[2][2][4], fbh[2][2][2], fbl[2][2][2];

    const int nch = K >> 6;

    auto issue = [&](int kk, int st){
        uint32_t base = sb + st * STAGE_B + s_wr;
        const bf16* ga0 = Ahp + (long)(m0 + ld_r) * lda + kk + ld_c;
        const bf16* ga1 = Alp + (long)(m0 + ld_r) * lda + kk + ld_c;
        const bf16* gb0 = Bhp + (long)(n0 + ld_r) * ldb + kk + ld_c;
        const bf16* gb1 = Blp + (long)(n0 + ld_r) * ldb + kk + ld_c;
        cpa16(base,                         ga0);
        cpa16(base + 32 * TSTRIDE,          ga0 + 32 * lda);
        cpa16(base + TILE_B,                ga1);
        cpa16(base + TILE_B + 32 * TSTRIDE, ga1 + 32 * lda);
        cpa16(base + 2 * TILE_B,                gb0);
        cpa16(base + 2 * TILE_B + 32 * TSTRIDE, gb0 + 32 * ldb);
        cpa16(base + 3 * TILE_B,                gb1);
        cpa16(base + 3 * TILE_B + 32 * TSTRIDE, gb1 + 32 * ldb);
        cpa_commit();
    };

    issue(0, 0);
    for (int i = 0; i < nch; i++) {
        if (i + 1 < nch) { issue((i + 1) << 6, (i + 1) & 1); cpa_wait<1>(); }
        else             { cpa_wait<0>(); }
        __syncthreads();

        uint32_t st = sb + (i & 1) * STAGE_B;

        // prologue fragments for ks=0
        {
            ldsm4(fbh[0][0][0], fbh[0][0][1], fbh[0][1][0], fbh[0][1][1], st + 2*TILE_B + boff);
            ldsm4(fbl[0][0][0], fbl[0][0][1], fbl[0][1][0], fbl[0][1][1], st + 3*TILE_B + boff);
#pragma unroll
            for (int mf = 0; mf < 2; mf++)
                ldsm4(fah[0][mf][0], fah[0][mf][1], fah[0][mf][2], fah[0][mf][3],
                      st + aoff + mf * (16*TSTRIDE));
#pragma unroll
            for (int mf = 0; mf < 2; mf++)
                ldsm4(fal[0][mf][0], fal[0][mf][1], fal[0][mf][2], fal[0][mf][3],
                      st + TILE_B + aoff + mf * (16*TSTRIDE));
        }

#pragma unroll
        for (int ks = 0; ks < 4; ks++) {
            const int cur = ks & 1, nxt = cur ^ 1;
            if (ks < 3) {
                uint32_t kb = (ks + 1) * 32;
                ldsm4(fbh[nxt][0][0], fbh[nxt][0][1], fbh[nxt][1][0], fbh[nxt][1][1],
                      st + 2*TILE_B + boff + kb);
                ldsm4(fbl[nxt][0][0], fbl[nxt][0][1], fbl[nxt][1][0], fbl[nxt][1][1],
                      st + 3*TILE_B + boff + kb);
#pragma unroll
                for (int mf = 0; mf < 2; mf++)
                    ldsm4(fah[nxt][mf][0], fah[nxt][mf][1], fah[nxt][mf][2], fah[nxt][mf][3],
                          st + aoff + mf * (16*TSTRIDE) + kb);
#pragma unroll
                for (int mf = 0; mf < 2; mf++)
                    ldsm4(fal[nxt][mf][0], fal[nxt][mf][1], fal[nxt][mf][2], fal[nxt][mf][3],
                          st + TILE_B + aoff + mf * (16*TSTRIDE) + kb);
            }
#pragma unroll
            for (int mf = 0; mf < 2; mf++)
#pragma unroll
                for (int nf = 0; nf < 2; nf++) mma16816(acc[mf][nf], fah[cur][mf], fbh[cur][nf]);
#pragma unroll
            for (int mf = 0; mf < 2; mf++)
#pragma unroll
                for (int nf = 0; nf < 2; nf++) mma16816(acc[mf][nf], fah[cur][mf], fbl[cur][nf]);
#pragma unroll
            for (int mf = 0; mf < 2; mf++)
#pragma unroll
                for (int nf = 0; nf < 2; nf++) mma16816(acc[mf][nf], fal[cur][mf], fbh[cur][nf]);
        }
        __syncthreads();
    }

    // epilogue
    const int g = lane >> 2, tg = lane & 3;
    const float* bp = bias ? bias + (long)z * bias_z : nullptr;
    float* Cz = C ? C + (long)z * c_z : nullptr;
#pragma unroll
    for (int mf = 0; mf < 2; mf++) {
#pragma unroll
        for (int nf = 0; nf < 2; nf++) {
            int row = m0 + wm * 32 + mf * 16 + g;
            int col = n0 + wn * 16 + nf * 8 + tg * 2;
            float v0 = acc[mf][nf][0], v1 = acc[mf][nf][1];
            float v2 = acc[mf][nf][2], v3 = acc[mf][nf][3];
            if (bp) {
                float bb0 = __ldg(bp + col), bb1 = __ldg(bp + col + 1);
                v0 += bb0; v1 += bb1; v2 += bb0; v3 += bb1;
            }
            if (flags & FL_RELU) {
                v0 = fmaxf(v0, 0.f); v1 = fmaxf(v1, 0.f);
                v2 = fmaxf(v2, 0.f); v3 = fmaxf(v3, 0.f);
            }
            if (flags & FL_F32) {
                *(float2*)&Cz[(long)row * ldc + col] = make_float2(v0, v1);
                *(float2*)&Cz[(long)(row + 8) * ldc + col] = make_float2(v2, v3);
            }
            if (flags & FL_HILO) {
                bf16 h0 = __float2bfloat16(v0), h1 = __float2bfloat16(v1);
                bf16 h2 = __float2bfloat16(v2), h3 = __float2bfloat16(v3);
                __nv_bfloat162 ph0; ph0.x = h0; ph0.y = h1;
                __nv_bfloat162 ph1; ph1.x = h2; ph1.y = h3;
                __nv_bfloat162 pl0, pl1;
                pl0.x = __float2bfloat16(v0 - __bfloat162float(h0));
                pl0.y = __float2bfloat16(v1 - __bfloat162float(h1));
                pl1.x = __float2bfloat16(v2 - __bfloat162float(h2));
                pl1.y = __float2bfloat16(v3 - __bfloat162float(h3));
                *(__nv_bfloat162*)&Ch[(long)row * ldch + col] = ph0;
                *(__nv_bfloat162*)&Cl[(long)row * ldch + col] = pl0;
                *(__nv_bfloat162*)&Ch[(long)(row + 8) * ldch + col] = ph1;
                *(__nv_bfloat162*)&Cl[(long)(row + 8) * ldch + col] = pl1;
            }
        }
    }
}

// ======== gathered RGCN GEMM: trans_c[r-1][pos] = nu[map[r][pos]] @ kg_w[r]^T ========
__global__ void __launch_bounds__(256, 3)
gemm_kg(const bf16* __restrict__ Ah, const bf16* __restrict__ Al,
        const bf16* __restrict__ Bh, const bf16* __restrict__ Bl,   // wTh+14UU, wTl+14UU
        float* __restrict__ Cout)
{
    const int r = blockIdx.z + 1;        // relation 1..7
    const int cnt = g_cnt[r];
    const int m0 = blockIdx.y * 64;
    if (m0 >= cnt) return;

    extern __shared__ char sm[];
    uint32_t sb = smem_u32(sm);
    const int tid = threadIdx.x, lane = tid & 31, wid = tid >> 5;
    const int wm = wid >> 2, wn = wid & 3;
    const int n0 = blockIdx.x * 64;
    const bf16* Bhp = Bh + (long)r * UU;
    const bf16* Blp = Bl + (long)r * UU;

    const int ld_r = tid >> 3, ld_c = (tid & 7) * 8;
    const uint32_t s_wr = (uint32_t)(ld_r * TSTRIDE + ld_c * 2);

    // gather A row ids (clamped padding rows duplicate last valid row; outputs unused)
    int i0 = m0 + ld_r;      if (i0 > cnt - 1) i0 = cnt - 1;
    int i1 = m0 + ld_r + 32; if (i1 > cnt - 1) i1 = cnt - 1;
    const int gr0 = g_map[r * 512 + i0];
    const int gr1 = g_map[r * 512 + i1];

    const int a_r = (lane & 7) + ((lane >> 3) & 1) * 8;
    const int a_c8 = (lane >> 4) * 8;
    const uint32_t aoff = (uint32_t)((wm * 32 + a_r) * TSTRIDE + a_c8 * 2);
    const int b_r = (lane & 7) + (lane >> 4) * 8;
    const int b_c8 = ((lane >> 3) & 1) * 8;
    const uint32_t boff = (uint32_t)((wn * 16 + b_r) * TSTRIDE + b_c8 * 2);

    float acc[2][2][4];
#pragma unroll
    for (int i = 0; i < 2; i++)
#pragma unroll
        for (int j = 0; j < 2; j++)
#pragma unroll
            for (int q = 0; q < 4; q++) acc[i][j][q] = 0.f;

    uint32_t fah[2][2][4], fal[2][2][4], fbh[2][2][2], fbl[2][2][2];

    auto issue = [&](int kk, int st){
        uint32_t base = sb + st * STAGE_B + s_wr;
        cpa16(base,                         Ah + (long)gr0 * DD + kk + ld_c);
        cpa16(base + 32 * TSTRIDE,          Ah + (long)gr1 * DD + kk + ld_c);
        cpa16(base + TILE_B,                Al + (long)gr0 * DD + kk + ld_c);
        cpa16(base + TILE_B + 32 * TSTRIDE, Al + (long)gr1 * DD + kk + ld_c);
        const bf16* gb0 = Bhp + (long)(n0 + ld_r) * DD + kk + ld_c;
        const bf16* gb1 = Blp + (long)(n0 + ld_r) * DD + kk + ld_c;
        cpa16(base + 2 * TILE_B,                gb0);
        cpa16(base + 2 * TILE_B + 32 * TSTRIDE, gb0 + 32 * DD);
        cpa16(base + 3 * TILE_B,                gb1);
        cpa16(base + 3 * TILE_B + 32 * TSTRIDE, gb1 + 32 * DD);
        cpa_commit();
    };

    const int nch = DD >> 6;
    issue(0, 0);
    for (int i = 0; i < nch; i++) {
        if (i + 1 < nch) { issue((i + 1) << 6, (i + 1) & 1); cpa_wait<1>(); }
        else             { cpa_wait<0>(); }
        __syncthreads();

        uint32_t st = sb + (i & 1) * STAGE_B;
        {
            ldsm4(fbh[0][0][0], fbh[0][0][1], fbh[0][1][0], fbh[0][1][1], st + 2*TILE_B + boff);
            ldsm4(fbl[0][0][0], fbl[0][0][1], fbl[0][1][0], fbl[0][1][1], st + 3*TILE_B + boff);
#pragma unroll
            for (int mf = 0; mf < 2; mf++)
                ldsm4(fah[0][mf][0], fah[0][mf][1], fah[0][mf][2], fah[0][mf][3],
                      st + aoff + mf * (16*TSTRIDE));
#pragma unroll
            for (int mf = 0; mf < 2; mf++)
                ldsm4(fal[0][mf][0], fal[0][mf][1], fal[0][mf][2], fal[0][mf][3],
                      st + TILE_B + aoff + mf * (16*TSTRIDE));
        }
#pragma unroll
        for (int ks = 0; ks < 4; ks++) {
            const int cur = ks & 1, nxt = cur ^ 1;
            if (ks < 3) {
                uint32_t kb = (ks + 1) * 32;
                ldsm4(fbh[nxt][0][0], fbh[nxt][0][1], fbh[nxt][1][0], fbh[nxt][1][1],
                      st + 2*TILE_B + boff + kb);
                ldsm4(fbl[nxt][0][0], fbl[nxt][0][1], fbl[nxt][1][0], fbl[nxt][1][1],
                      st + 3*TILE_B + boff + kb);
#pragma unroll
                for (int mf = 0; mf < 2; mf++)
                    ldsm4(fah[nxt][mf][0], fah[nxt][mf][1], fah[nxt][mf][2], fah[nxt][mf][3],
                          st + aoff + mf * (16*TSTRIDE) + kb);
#pragma unroll
                for (int mf = 0; mf < 2; mf++)
                    ldsm4(fal[nxt][mf][0], fal[nxt][mf][1], fal[nxt][mf][2], fal[nxt][mf][3],
                          st + TILE_B + aoff + mf * (16*TSTRIDE) + kb);
            }
#pragma unroll
            for (int mf = 0; mf < 2; mf++)
#pragma unroll
                for (int nf = 0; nf < 2; nf++) mma16816(acc[mf][nf], fah[cur][mf], fbh[cur][nf]);
#pragma unroll
            for (int mf = 0; mf < 2; mf++)
#pragma unroll
                for (int nf = 0; nf < 2; nf++) mma16816(acc[mf][nf], fah[cur][mf], fbl[cur][nf]);
#pragma unroll
            for (int mf = 0; mf < 2; mf++)
#pragma unroll
                for (int nf = 0; nf < 2; nf++) mma16816(acc[mf][nf], fal[cur][mf], fbh[cur][nf]);
        }
        __syncthreads();
    }

    const int g = lane >> 2, tg = lane & 3;
    float* Cz = Cout + (long)blockIdx.z * 512 * DD;
#pragma unroll
    for (int mf = 0; mf < 2; mf++) {
#pragma unroll
        for (int nf = 0; nf < 2; nf++) {
            int row = m0 + wm * 32 + mf * 16 + g;
            int col = n0 + wn * 16 + nf * 8 + tg * 2;
            *(float2*)&Cz[(long)row * DD + col] =
                make_float2(acc[mf][nf][0], acc[mf][nf][1]);
            *(float2*)&Cz[(long)(row + 8) * DD + col] =
                make_float2(acc[mf][nf][2], acc[mf][nf][3]);
        }
    }
}

// ======================= LayerNorms =======================
__global__ void ln1_k(const float* __restrict__ in, const float* __restrict__ g,
                      const float* __restrict__ b, bf16* __restrict__ oh, bf16* __restrict__ ol)
{
    int row = blockIdx.x, t = threadIdx.x;   // 256 threads
    __shared__ float rbuf[256];
    long base = (long)row * DD;
    float v0 = in[base + t], v1 = in[base + t + 256];
    rbuf[t] = v0 + v1; __syncthreads();
    for (int s = 128; s > 0; s >>= 1) { if (t < s) rbuf[t] += rbuf[t + s]; __syncthreads(); }
    float mean = rbuf[0] * (1.0f / 512.0f);
    __syncthreads();
    float d0 = v0 - mean, d1 = v1 - mean;
    rbuf[t] = d0 * d0 + d1 * d1; __syncthreads();
    for (int s = 128; s > 0; s >>= 1) { if (t < s) rbuf[t] += rbuf[t + s]; __syncthreads(); }
    float rs = rsqrtf(rbuf[0] * (1.0f / 512.0f) + 1e-5f);
    float o0 = d0 * rs * g[t] + b[t];
    float o1 = d1 * rs * g[t + 256] + b[t + 256];
    bf16 h0 = __float2bfloat16(o0), h1 = __float2bfloat16(o1);
    oh[base + t] = h0;       ol[base + t]       = __float2bfloat16(o0 - __bfloat162float(h0));
    oh[base + t + 256] = h1; ol[base + t + 256] = __float2bfloat16(o1 - __bfloat162float(h1));
}

__global__ void ln2_k(const float* __restrict__ in, const float* __restrict__ add,
                      const float* __restrict__ g, const float* __restrict__ b,
                      float* __restrict__ out)
{
    int row = blockIdx.x, t = threadIdx.x;
    __shared__ float rbuf[256];
    long base = (long)row * DD;
    float v0 = in[base + t] + add[base + t];
    float v1 = in[base + t + 256] + add[base + t + 256];
    rbuf[t] = v0 + v1; __syncthreads();
    for (int s = 128; s > 0; s >>= 1) { if (t < s) rbuf[t] += rbuf[t + s]; __syncthreads(); }
    float mean = rbuf[0] * (1.0f / 512.0f);
    __syncthreads();
    float d0 = v0 - mean, d1 = v1 - mean;
    rbuf[t] = d0 * d0 + d1 * d1; __syncthreads();
    for (int s = 128; s > 0; s >>= 1) { if (t < s) rbuf[t] += rbuf[t + s]; __syncthreads(); }
    float rs = rsqrtf(rbuf[0] * (1.0f / 512.0f) + 1e-5f);
    out[base + t]       = d0 * rs * g[t]       + b[t];
    out[base + t + 256] = d1 * rs * g[t + 256] + b[t + 256];
}

// ======================= attention: scores+softmax, 16-row tiles =======================
__global__ void attn_scores_k(const float* __restrict__ q, const float* __restrict__ k,
                              float* __restrict__ attn)
{
    int it = blockIdx.x, h = blockIdx.y, b = blockIdx.z;  // 256 thr
    int t = threadIdx.x;
    int i0 = it * 16;
    __shared__ float ks[SS][DH + 1];
    __shared__ float qs[16][DH + 1];
    __shared__ float P[16][SS];
    const float* kbase = k + (long)b * SS * DD + h * DH;
    const float* qbase = q + (long)b * SS * DD + h * DH;
    for (int idx = t; idx < SS * DH; idx += 256) {
        int j = idx >> 6, d = idx & 63;
        ks[j][d] = kbase[(long)j * DD + d];
    }
    for (int idx = t; idx < 16 * DH; idx += 256) {
        int r = idx >> 6, d = idx & 63;
        qs[r][d] = qbase[(long)(i0 + r) * DD + d];
    }
    __syncthreads();
    {
        int j = t & 127, grp = t >> 7;
#pragma unroll
        for (int r = 0; r < 8; r++) {
            int i = grp * 8 + r;
            float acc = 0.f;
#pragma unroll
            for (int d = 0; d < DH; d++) acc += qs[i][d] * ks[j][d];
            P[i][j] = acc * 0.125f;
        }
    }
    __syncthreads();
    {
        int w = t >> 5, ln = t & 31;
        long obase = (((long)(b * HH + h) * SS) + i0) * SS;
#pragma unroll
        for (int rr = 0; rr < 2; rr++) {
            int i = w * 2 + rr;
            float m = -1e30f;
#pragma unroll
            for (int c = 0; c < 4; c++) m = fmaxf(m, P[i][ln + c * 32]);
#pragma unroll
            for (int o = 16; o > 0; o >>= 1) m = fmaxf(m, __shfl_xor_sync(0xffffffffu, m, o));
            float s = 0.f, e[4];
#pragma unroll
            for (int c = 0; c < 4; c++) { e[c] = expf(P[i][ln + c * 32] - m); s += e[c]; }
#pragma unroll
            for (int o = 16; o > 0; o >>= 1) s += __shfl_xor_sync(0xffffffffu, s, o);
            float inv = 1.0f / s;
#pragma unroll
            for (int c = 0; c < 4; c++) attn[obase + (long)i * SS + ln + c * 32] = e[c] * inv;
        }
    }
}

__global__ void am_k(const float* __restrict__ attn, float* __restrict__ am)
{
    int bi = blockIdx.x;
    int b = bi >> 7, i = bi & 127, t = threadIdx.x;  // 128 thr
    float s = 0.f;
#pragma unroll
    for (int h = 0; h < HH; h++)
        s += attn[(((long)(b * HH + h) * SS) + i) * SS + t];
    am[(long)bi * SS + t] = s * 0.125f;
}

// ======================= attention: ctx = P @ V, 16-row tiles =======================
__global__ void attn_ctx_k(const float* __restrict__ attn, const float* __restrict__ v,
                           bf16* __restrict__ ch, bf16* __restrict__ cl)
{
    int it = blockIdx.x, h = blockIdx.y, b = blockIdx.z;  // 256 thr
    int t = threadIdx.x;
    int i0 = it * 16;
    int d = t & 63, ig = t >> 6;
    __shared__ float vs[SS][DH + 1];
    __shared__ float at[16][SS];
    const float* vbase = v + (long)b * SS * DD + h * DH;
    for (int idx = t; idx < SS * DH; idx += 256) {
        int j = idx >> 6, dd = idx & 63;
        vs[j][dd] = vbase[(long)j * DD + dd];
    }
    long arow = (((long)(b * HH + h) * SS) + i0) * SS;
    for (int idx = t; idx < 16 * SS; idx += 256)
        at[idx >> 7][idx & 127] = attn[arow + (long)(idx >> 7) * SS + (idx & 127)];
    __syncthreads();

    float acc[4] = {0.f, 0.f, 0.f, 0.f};
#pragma unroll
    for (int jh = 0; jh < 2; jh++) {
        float vreg[64];
#pragma unroll
        for (int jj = 0; jj < 64; jj++) vreg[jj] = vs[jh * 64 + jj][d];
#pragma unroll
        for (int r = 0; r < 4; r++) {
            int i = ig + 4 * r;
            float a = acc[r];
#pragma unroll
            for (int jj = 0; jj < 64; jj++) a += at[i][jh * 64 + jj] * vreg[jj];
            acc[r] = a;
        }
    }
#pragma unroll
    for (int r = 0; r < 4; r++) {
        int i = ig + 4 * r;
        long o = (long)(b * SS + i0 + i) * DD + h * DH + d;
        bf16 hh = __float2bfloat16(acc[r]);
        ch[o] = hh; cl[o] = __float2bfloat16(acc[r] - __bfloat162float(hh));
    }
}

// ======================= nu: reduce split-K partials + bias + hi/lo =======================
__global__ void conv_nu_k(const float* __restrict__ P, const float* __restrict__ b2,
                          float* __restrict__ nu, bf16* __restrict__ H, bf16* __restrict__ L)
{
    int row = blockIdx.x, t = threadIdx.x;  // 256
    for (int c = t; c < DD; c += 256) {
        long i = (long)row * DD + c;
        float v = b2[c] + P[i] + P[UU + i] + P[2L*UU + i] + P[3L*UU + i];
        nu[i] = v;
        bf16 h = __float2bfloat16(v);
        H[i] = h; L[i] = __float2bfloat16(v - __bfloat162float(h));
    }
}

// ======================= pair relation classifier (early-exit on empty tiles) ===========
__global__ void pair_k(const float* __restrict__ ap, const float* __restrict__ bp,
                       const float* __restrict__ rc_b1, const float* __restrict__ rc_w2,
                       const float* __restrict__ rc_b2, const float* __restrict__ am,
                       int* __restrict__ rel)
{
    int b = blockIdx.z;
    int u0 = blockIdx.y * 16, v0 = blockIdx.x * 16;
    int t = threadIdx.x;                 // 256
    int ul = t >> 4, vl = t & 15;
    int u = u0 + ul, v = v0 + vl;
    long ridx = ((long)b * SS + u) * SS + v;

    // 16-byte-aligned shared arrays first (float4 loads from sW), flag last.
    __shared__ __align__(16) float sA[16][65];
    __shared__ __align__(16) float sB[16][65];
    __shared__ __align__(16) float sW[64][8];
    __shared__ float sC[64];
    __shared__ int any;

    if (t == 0) any = 0;
    __syncthreads();
    float amv = am[ridx];
    int adj = (amv > THRESH) && (u != v);
    if (adj) any = 1;
    __syncthreads();
    if (!any) { rel[ridx] = 0; return; }

    float acc[RR];
#pragma unroll
    for (int r = 0; r < RR; r++) acc[r] = rc_b2[r];

    for (int c0 = 0; c0 < DD; c0 += 64) {
        for (int idx = t; idx < 1024; idx += 256) {
            int rr = idx >> 6, cc = idx & 63;
            sA[rr][cc] = ap[(long)(b * SS + u0 + rr) * DD + c0 + cc];
            sB[rr][cc] = bp[(long)(b * SS + v0 + rr) * DD + c0 + cc];
        }
        for (int idx = t; idx < 512; idx += 256)
            sW[idx >> 3][idx & 7] = rc_w2[(long)(c0 + (idx >> 3)) * RR + (idx & 7)];
        if (t < 64) sC[t] = rc_b1[c0 + t];
        __syncthreads();
#pragma unroll 4
        for (int dd = 0; dd < 64; dd++) {
            float hsum = sA[ul][dd] + sB[vl][dd] + sC[dd];
            hsum = fmaxf(hsum, 0.f);
            float4 w0 = *(float4*)&sW[dd][0];
            float4 w1 = *(float4*)&sW[dd][4];
            acc[0] += hsum * w0.x; acc[1] += hsum * w0.y;
            acc[2] += hsum * w0.z; acc[3] += hsum * w0.w;
            acc[4] += hsum * w1.x; acc[5] += hsum * w1.y;
            acc[6] += hsum * w1.z; acc[7] += hsum * w1.w;
        }
        __syncthreads();
    }
    int pred = 0; float best = acc[0];
#pragma unroll
    for (int r = 1; r < RR; r++) if (acc[r] > best) { best = acc[r]; pred = r; }
    int valid = adj && (pred != 0);
    rel[ridx] = valid ? pred : 0;
}

// ======================= build compact (node, relation) lists =======================
__global__ void build_k(const int* __restrict__ rel)
{
    int bu = blockIdx.x, t = threadIdx.x;   // 128 thr
    __shared__ unsigned mask;
    if (t == 0) mask = 0;
    if (t < 8) g_loc[bu * 8 + t] = -1;
    __syncthreads();
    int r = rel[(long)bu * SS + t];
    if (r) atomicOr(&mask, 1u << r);
    __syncthreads();
    if (t >= 1 && t < 8 && ((mask >> t) & 1)) {
        int pos = atomicAdd(&g_cnt[t], 1);
        g_map[t * 512 + pos] = bu;
        g_loc[bu * 8 + t] = pos;
    }
}

// ======================= edge aggregation (compacted transforms) =======================
__global__ void agg_k(const int* __restrict__ rel, const float* __restrict__ nu,
                      bf16* __restrict__ rh, bf16* __restrict__ rl)
{
    int bv = blockIdx.x;                 // b*S + v
    int b = bv >> 7, v = bv & 127, t = threadIdx.x;   // 256
    __shared__ int sr[SS];
    if (t < SS) sr[t] = rel[((long)b * SS + t) * SS + v];
    __syncthreads();
    float a0 = 0.f, a1 = 0.f;
    for (int u = 0; u < SS; u++) {
        int r = sr[u];
        if (r) {
            int pos = g_loc[((long)(b * SS + u)) * 8 + r];
            const float* tr = g_transc + ((long)(r - 1) * 512 + pos) * DD;
            a0 += tr[t]; a1 += tr[t + 256];
        }
    }
    long row = (long)bv * DD;
    float v0 = nu[row + t] + a0;
    float v1 = nu[row + t + 256] + a1;
    bf16 h0 = __float2bfloat16(v0), h1 = __float2bfloat16(v1);
    rh[row + t] = h0;       rl[row + t]       = __float2bfloat16(v0 - __bfloat162float(h0));
    rh[row + t + 256] = h1; rl[row + t + 256] = __float2bfloat16(v1 - __bfloat162float(h1));
}

// ======================= launch =======================
extern "C" void kernel_launch(void* const* d_in, const int* in_sizes, int n_in,
                              void* d_out, int out_size)
{
    const float* x     = (const float*)d_in[0];
    const float* ln1_g = (const float*)d_in[1];
    const float* ln1_b = (const float*)d_in[2];
    const float* wq    = (const float*)d_in[3];
    const float* bq    = (const float*)d_in[4];
    const float* wk    = (const float*)d_in[5];
    const float* bk    = (const float*)d_in[6];
    const float* wv    = (const float*)d_in[7];
    const float* bvv   = (const float*)d_in[8];
    const float* wo    = (const float*)d_in[9];
    const float* bo    = (const float*)d_in[10];
    const float* w1    = (const float*)d_in[11];
    const float* b1    = (const float*)d_in[12];
    const float* w2    = (const float*)d_in[13];
    const float* b2    = (const float*)d_in[14];
    const float* rc_w1 = (const float*)d_in[15];
    const float* rc_b1 = (const float*)d_in[16];
    const float* rc_w2 = (const float*)d_in[17];
    const float* rc_b2 = (const float*)d_in[18];
    const float* kg_w  = (const float*)d_in[19];
    const float* s2n_w = (const float*)d_in[20];
    const float* s2n_b = (const float*)d_in[21];
    const float* ln2_g = (const float*)d_in[22];
    const float* ln2_b = (const float*)d_in[23];
    float* out = (float*)d_out;

    bf16 *wTh, *wTl, *xnh, *xnl, *ctxh, *ctxl, *aoh, *aol, *hidh, *hidl, *nuh, *nul, *rsh, *rsl;
    float *b3, *qkv, *attn, *am, *nupart, *nu, *abt, *nr, *transc;
    int *rel;
    cudaGetSymbolAddress((void**)&wTh, g_wTh);   cudaGetSymbolAddress((void**)&wTl, g_wTl);
    cudaGetSymbolAddress((void**)&b3, g_b3);
    cudaGetSymbolAddress((void**)&xnh, g_xnh);   cudaGetSymbolAddress((void**)&xnl, g_xnl);
    cudaGetSymbolAddress((void**)&qkv, g_qkv);
    cudaGetSymbolAddress((void**)&attn, g_attn); cudaGetSymbolAddress((void**)&am, g_am);
    cudaGetSymbolAddress((void**)&ctxh, g_ctxh); cudaGetSymbolAddress((void**)&ctxl, g_ctxl);
    cudaGetSymbolAddress((void**)&aoh, g_aoh);   cudaGetSymbolAddress((void**)&aol, g_aol);
    cudaGetSymbolAddress((void**)&hidh, g_hidh); cudaGetSymbolAddress((void**)&hidl, g_hidl);
    cudaGetSymbolAddress((void**)&nupart, g_nupart);
    cudaGetSymbolAddress((void**)&nu, g_nu);
    cudaGetSymbolAddress((void**)&nuh, g_nuh);   cudaGetSymbolAddress((void**)&nul, g_nul);
    cudaGetSymbolAddress((void**)&abt, g_abt);
    cudaGetSymbolAddress((void**)&rel, g_rel);
    cudaGetSymbolAddress((void**)&rsh, g_rsh);   cudaGetSymbolAddress((void**)&rsl, g_rsl);
    cudaGetSymbolAddress((void**)&nr, g_nr);
    cudaGetSymbolAddress((void**)&transc, g_transc);

    cudaFuncSetAttribute(gemm_mma, cudaFuncAttributeMaxDynamicSharedMemorySize, GSM);
    cudaFuncSetAttribute(gemm_mma, cudaFuncAttributePreferredSharedMemoryCarveout, 100);
    cudaFuncSetAttribute(gemm_kg, cudaFuncAttributeMaxDynamicSharedMemorySize, GSM);
    cudaFuncSetAttribute(gemm_kg, cudaFuncAttributePreferredSharedMemoryCarveout, 100);

    // weight prep (also zeroes g_cnt)
    setup_k<<<1, 512>>>(wq, wk, wv, wo, w1, w2, rc_w1, kg_w, s2n_w, bq, bk, bvv);
    wconv_k<<<dim3(16, 16, 23), dim3(32, 8)>>>();

    // ln1 -> xn (hi/lo)
    ln1_k<<<BS, 256>>>(x, ln1_g, ln1_b, xnh, xnl);

    // QKV (z=3), fp32 out
    gemm_mma<<<dim3(8, 8, 3), 256, GSM>>>(xnh, xnl, DD, 0, wTh, wTl, UU, DD,
                                          b3, DD, qkv, UU, DD, nullptr, nullptr, 0,
                                          DD, FL_F32);
    // attention (16-row tiled)
    attn_scores_k<<<dim3(8, HH, BB), 256>>>(qkv, qkv + UU, attn);
    am_k<<<BS, 128>>>(attn, am);
    attn_ctx_k<<<dim3(8, HH, BB), 256>>>(attn, qkv + 2 * UU, ctxh, ctxl);

    // ao = ctx @ wo + bo  (hi/lo only)
    gemm_mma<<<dim3(8, 8, 1), 256, GSM>>>(ctxh, ctxl, DD, 0, wTh + 3L*UU, wTl + 3L*UU, 0, DD,
                                          bo, 0, nullptr, 0, 0, aoh, aol, DD,
                                          DD, FL_HILO);
    // hid = relu(ao @ w1 + b1) (hi/lo only, N=2048)
    gemm_mma<<<dim3(32, 8, 1), 256, GSM>>>(aoh, aol, DD, 0, wTh + 4L*UU, wTl + 4L*UU, 0, DD,
                                           b1, 0, nullptr, 0, 0, hidh, hidl, FF,
                                           DD, FL_HILO | FL_RELU);
    // nu partials = hid @ w2  (split-K z=4 into 4 slabs)
    gemm_mma<<<dim3(8, 8, 4), 256, GSM>>>(hidh, hidl, FF, DD, wTh + 8L*UU, wTl + 8L*UU, DD, FF,
                                          nullptr, 0, nupart, UU, DD, nullptr, nullptr, 0,
                                          DD, FL_F32);
    conv_nu_k<<<BS, 256>>>(nupart, b2, nu, nuh, nul);

    // a/b parts (z=2)
    gemm_mma<<<dim3(8, 8, 2), 256, GSM>>>(nuh, nul, DD, 0, wTh + 12L*UU, wTl + 12L*UU, UU, DD,
                                          nullptr, 0, abt, UU, DD, nullptr, nullptr, 0,
                                          DD, FL_F32);
    // edges (early-exit tiles)
    pair_k<<<dim3(8, 8, BB), 256>>>(abt, abt + UU, rc_b1, rc_w2, rc_b2, am, rel);
    // compact (node, relation) work lists, then gathered RGCN transforms
    build_k<<<BS, 128>>>(rel);
    gemm_kg<<<dim3(8, 8, 7), 256, GSM>>>(nuh, nul, wTh + 14L*UU, wTl + 14L*UU, transc);
    // aggregation via compacted transforms
    agg_k<<<BS, 256>>>(rel, nu, rsh, rsl);

    // s2n projection, fp32
    gemm_mma<<<dim3(8, 8, 1), 256, GSM>>>(rsh, rsl, DD, 0, wTh + 22L*UU, wTl + 22L*UU, 0, DD,
                                          s2n_b, 0, nr, 0, DD, nullptr, nullptr, 0,
                                          DD, FL_F32);
    // final residual LN
    ln2_k<<<BS, 256>>>(nr, x, ln2_g, ln2_b, out);
}

// round 11
// speedup vs baseline: 1.0696x; 1.0612x over previous
#include <cuda_runtime.h>
#include <cuda_bf16.h>
#include <math.h>
#include <stdint.h>

#define BB 4
#define SS 128
#define DD 512
#define HH 8
#define DH 64
#define FF 2048
#define RR 8
#define BS (BB*SS)          // 512
#define UU 262144           // 512*512
#define THRESH 0.1f

typedef __nv_bfloat16 bf16;

// ======================= helpers =======================
__device__ __forceinline__ uint32_t smem_u32(const void* p){
    uint32_t a;
    asm("{ .reg .u64 t; cvta.to.shared.u64 t, %1; cvt.u32.u64 %0, t; }" : "=r"(a) : "l"(p));
    return a;
}
__device__ __forceinline__ void ldsm4(uint32_t& r0, uint32_t& r1, uint32_t& r2, uint32_t& r3,
                                      uint32_t addr){
    asm volatile("ldmatrix.sync.aligned.m8n8.x4.shared.b16 {%0,%1,%2,%3}, [%4];"
                 : "=r"(r0), "=r"(r1), "=r"(r2), "=r"(r3) : "r"(addr));
}
__device__ __forceinline__ void mma16816(float* d, const uint32_t* a, const uint32_t* b){
    asm volatile("mma.sync.aligned.m16n8k16.row.col.f32.bf16.bf16.f32 "
                 "{%0,%1,%2,%3}, {%4,%5,%6,%7}, {%8,%9}, {%0,%1,%2,%3};"
                 : "+f"(d[0]), "+f"(d[1]), "+f"(d[2]), "+f"(d[3])
                 : "r"(a[0]), "r"(a[1]), "r"(a[2]), "r"(a[3]), "r"(b[0]), "r"(b[1]));
}
__device__ __forceinline__ void cpa16(uint32_t s, const void* g){
    asm volatile("cp.async.cg.shared.global [%0], [%1], 16;" :: "r"(s), "l"(g));
}
__device__ __forceinline__ void cpa_commit(){
    asm volatile("cp.async.commit_group;" ::: "memory");
}
template<int N> __device__ __forceinline__ void cpa_wait(){
    asm volatile("cp.async.wait_group %0;" :: "n"(N) : "memory");
}

// ======================= scratch (device globals) =======================
__device__ bf16  g_wTh[23*UU];          // packed transposed weights, hi
__device__ bf16  g_wTl[23*UU];          // packed transposed weights, lo
__device__ float g_b3[3*DD];            // packed q/k/v biases
__device__ bf16  g_xnh[UU], g_xnl[UU];
__device__ float g_qkv[3*UU];
__device__ float g_attn[BB*HH*SS*SS];
__device__ float g_am[BB*SS*SS];
__device__ bf16  g_ctxh[UU], g_ctxl[UU];
__device__ bf16  g_aoh[UU],  g_aol[UU];
__device__ bf16  g_hidh[BS*FF], g_hidl[BS*FF];
__device__ float g_nupart[4*UU];        // split-K partials for nu
__device__ float g_nu[UU];
__device__ bf16  g_nuh[UU], g_nul[UU];
__device__ float g_abt[10*UU];          // [0,1]=a/b parts, [2..9]=trans slabs [r][n][d]
__device__ int   g_rel[BB*SS*SS];
__device__ bf16  g_rsh[UU], g_rsl[UU];
__device__ float g_nr[UU];

struct WUnit { const float* src; int ld; long dst; int dld; };
__device__ WUnit g_wu[23];

// ======================= setup: weight-unit table + packed biases =======================
__global__ void setup_k(const float* wq, const float* wk, const float* wv, const float* wo,
                        const float* w1, const float* w2, const float* rc, const float* kg,
                        const float* s2n, const float* bq, const float* bk, const float* bvv)
{
    int t = threadIdx.x;
    if (t < DD) { g_b3[t] = bq[t]; g_b3[DD+t] = bk[t]; g_b3[2*DD+t] = bvv[t]; }
    if (t == 0) {
        const float* qkv[3] = {wq, wk, wv};
        for (int u = 0; u < 3; u++) g_wu[u] = {qkv[u], DD, (long)u*UU, DD};
        g_wu[3] = {wo, DD, 3L*UU, DD};
        for (int u = 0; u < 4; u++)                       // w1 [512][2048] -> [2048][512]
            g_wu[4+u] = {w1 + u*DD, FF, 4L*UU + (long)u*UU, DD};
        for (int u = 0; u < 4; u++)                       // w2 [2048][512] -> [512][2048]
            g_wu[8+u] = {w2 + (long)u*UU, DD, 8L*UU + (long)u*DD, FF};
        for (int u = 0; u < 2; u++)
            g_wu[12+u] = {rc + (long)u*UU, DD, (12L+u)*UU, DD};
        for (int u = 0; u < 8; u++)
            g_wu[14+u] = {kg + (long)u*UU, DD, (14L+u)*UU, DD};
        g_wu[22] = {s2n, DD, 22L*UU, DD};
    }
}

// ======================= weight transpose + fp32 -> bf16 hi/lo =======================
__global__ void wconv_k()
{
    __shared__ float tile[32][33];
    WUnit u = g_wu[blockIdx.z];
    int k0 = blockIdx.y * 32, n0 = blockIdx.x * 32;
    int tx = threadIdx.x, ty = threadIdx.y;        // (32, 8)
#pragma unroll
    for (int i = 0; i < 4; i++)
        tile[ty + 8*i][tx] = __ldg(u.src + (long)(k0 + ty + 8*i) * u.ld + n0 + tx);
    __syncthreads();
#pragma unroll
    for (int i = 0; i < 4; i++) {
        int n = n0 + ty + 8*i, k = k0 + tx;
        float v = tile[tx][ty + 8*i];
        bf16 h = __float2bfloat16(v);
        bf16 l = __float2bfloat16(v - __bfloat162float(h));
        long off = u.dst + (long)n * u.dld + k;
        g_wTh[off] = h; g_wTl[off] = l;
    }
}

// ======================= mma.sync bf16 3-pass GEMM (64x64 tile, 2-stage) =======================
#define FL_F32  1
#define FL_HILO 2
#define FL_RELU 4

#define TSTRIDE 144                      // smem row stride bytes (72 bf16)
#define TILE_B  9216                     // 64 rows * 144 B
#define STAGE_B 36864                    // 4 tiles
#define GSM     73728                    // 2 stages

__global__ void __launch_bounds__(256, 3)
gemm_mma(const bf16* __restrict__ Ah, const bf16* __restrict__ Al, int lda, long a_z,
         const bf16* __restrict__ Bh, const bf16* __restrict__ Bl, long b_z, int ldb,
         const float* __restrict__ bias, int bias_z,
         float* __restrict__ C, long c_z, int ldc,
         bf16* __restrict__ Ch, bf16* __restrict__ Cl, int ldch,
         int K, int flags)
{
    extern __shared__ char sm[];
    uint32_t sb = smem_u32(sm);
    const int tid = threadIdx.x, lane = tid & 31, wid = tid >> 5;
    const int wm = wid >> 2, wn = wid & 3;               // warp grid 2 x 4
    const int m0 = blockIdx.y * 64, n0 = blockIdx.x * 64, z = blockIdx.z;
    const bf16* Ahp = Ah + (long)z * a_z;
    const bf16* Alp = Al + (long)z * a_z;
    const bf16* Bhp = Bh + (long)z * b_z;
    const bf16* Blp = Bl + (long)z * b_z;

    const int ld_r = tid >> 3, ld_c = (tid & 7) * 8;
    const uint32_t s_wr = (uint32_t)(ld_r * TSTRIDE + ld_c * 2);

    const int a_r = (lane & 7) + ((lane >> 3) & 1) * 8;
    const int a_c8 = (lane >> 4) * 8;
    const uint32_t aoff = (uint32_t)((wm * 32 + a_r) * TSTRIDE + a_c8 * 2);
    const int b_r = (lane & 7) + (lane >> 4) * 8;
    const int b_c8 = ((lane >> 3) & 1) * 8;
    const uint32_t boff = (uint32_t)((wn * 16 + b_r) * TSTRIDE + b_c8 * 2);

    float acc[2][2][4];
#pragma unroll
    for (int i = 0; i < 2; i++)
#pragma unroll
        for (int j = 0; j < 2; j++)
#pragma unroll
            for (int q = 0; q < 4; q++) acc[i][j][q] = 0.f;

    uint32_t fah[2][2][4], fal[2][2][4], fbh[2][2][2], fbl[2][2][2];

    const int nch = K >> 6;

    auto issue = [&](int kk, int st){
        uint32_t base = sb + st * STAGE_B + s_wr;
        const bf16* ga0 = Ahp + (long)(m0 + ld_r) * lda + kk + ld_c;
        const bf16* ga1 = Alp + (long)(m0 + ld_r) * lda + kk + ld_c;
        const bf16* gb0 = Bhp + (long)(n0 + ld_r) * ldb + kk + ld_c;
        const bf16* gb1 = Blp + (long)(n0 + ld_r) * ldb + kk + ld_c;
        cpa16(base,                         ga0);
        cpa16(base + 32 * TSTRIDE,          ga0 + 32 * lda);
        cpa16(base + TILE_B,                ga1);
        cpa16(base + TILE_B + 32 * TSTRIDE, ga1 + 32 * lda);
        cpa16(base + 2 * TILE_B,                gb0);
        cpa16(base + 2 * TILE_B + 32 * TSTRIDE, gb0 + 32 * ldb);
        cpa16(base + 3 * TILE_B,                gb1);
        cpa16(base + 3 * TILE_B + 32 * TSTRIDE, gb1 + 32 * ldb);
        cpa_commit();
    };

    issue(0, 0);
    for (int i = 0; i < nch; i++) {
        if (i + 1 < nch) { issue((i + 1) << 6, (i + 1) & 1); cpa_wait<1>(); }
        else             { cpa_wait<0>(); }
        __syncthreads();

        uint32_t st = sb + (i & 1) * STAGE_B;

        {
            ldsm4(fbh[0][0][0], fbh[0][0][1], fbh[0][1][0], fbh[0][1][1], st + 2*TILE_B + boff);
            ldsm4(fbl[0][0][0], fbl[0][0][1], fbl[0][1][0], fbl[0][1][1], st + 3*TILE_B + boff);
#pragma unroll
            for (int mf = 0; mf < 2; mf++)
                ldsm4(fah[0][mf][0], fah[0][mf][1], fah[0][mf][2], fah[0][mf][3],
                      st + aoff + mf * (16*TSTRIDE));
#pragma unroll
            for (int mf = 0; mf < 2; mf++)
                ldsm4(fal[0][mf][0], fal[0][mf][1], fal[0][mf][2], fal[0][mf][3],
                      st + TILE_B + aoff + mf * (16*TSTRIDE));
        }

#pragma unroll
        for (int ks = 0; ks < 4; ks++) {
            const int cur = ks & 1, nxt = cur ^ 1;
            if (ks < 3) {
                uint32_t kb = (ks + 1) * 32;
                ldsm4(fbh[nxt][0][0], fbh[nxt][0][1], fbh[nxt][1][0], fbh[nxt][1][1],
                      st + 2*TILE_B + boff + kb);
                ldsm4(fbl[nxt][0][0], fbl[nxt][0][1], fbl[nxt][1][0], fbl[nxt][1][1],
                      st + 3*TILE_B + boff + kb);
#pragma unroll
                for (int mf = 0; mf < 2; mf++)
                    ldsm4(fah[nxt][mf][0], fah[nxt][mf][1], fah[nxt][mf][2], fah[nxt][mf][3],
                          st + aoff + mf * (16*TSTRIDE) + kb);
#pragma unroll
                for (int mf = 0; mf < 2; mf++)
                    ldsm4(fal[nxt][mf][0], fal[nxt][mf][1], fal[nxt][mf][2], fal[nxt][mf][3],
                          st + TILE_B + aoff + mf * (16*TSTRIDE) + kb);
            }
#pragma unroll
            for (int mf = 0; mf < 2; mf++)
#pragma unroll
                for (int nf = 0; nf < 2; nf++) mma16816(acc[mf][nf], fah[cur][mf], fbh[cur][nf]);
#pragma unroll
            for (int mf = 0; mf < 2; mf++)
#pragma unroll
                for (int nf = 0; nf < 2; nf++) mma16816(acc[mf][nf], fah[cur][mf], fbl[cur][nf]);
#pragma unroll
            for (int mf = 0; mf < 2; mf++)
#pragma unroll
                for (int nf = 0; nf < 2; nf++) mma16816(acc[mf][nf], fal[cur][mf], fbh[cur][nf]);
        }
        __syncthreads();
    }

    const int g = lane >> 2, tg = lane & 3;
    const float* bp = bias ? bias + (long)z * bias_z : nullptr;
    float* Cz = C ? C + (long)z * c_z : nullptr;
#pragma unroll
    for (int mf = 0; mf < 2; mf++) {
#pragma unroll
        for (int nf = 0; nf < 2; nf++) {
            int row = m0 + wm * 32 + mf * 16 + g;
            int col = n0 + wn * 16 + nf * 8 + tg * 2;
            float v0 = acc[mf][nf][0], v1 = acc[mf][nf][1];
            float v2 = acc[mf][nf][2], v3 = acc[mf][nf][3];
            if (bp) {
                float bb0 = __ldg(bp + col), bb1 = __ldg(bp + col + 1);
                v0 += bb0; v1 += bb1; v2 += bb0; v3 += bb1;
            }
            if (flags & FL_RELU) {
                v0 = fmaxf(v0, 0.f); v1 = fmaxf(v1, 0.f);
                v2 = fmaxf(v2, 0.f); v3 = fmaxf(v3, 0.f);
            }
            if (flags & FL_F32) {
                *(float2*)&Cz[(long)row * ldc + col] = make_float2(v0, v1);
                *(float2*)&Cz[(long)(row + 8) * ldc + col] = make_float2(v2, v3);
            }
            if (flags & FL_HILO) {
                bf16 h0 = __float2bfloat16(v0), h1 = __float2bfloat16(v1);
                bf16 h2 = __float2bfloat16(v2), h3 = __float2bfloat16(v3);
                __nv_bfloat162 ph0; ph0.x = h0; ph0.y = h1;
                __nv_bfloat162 ph1; ph1.x = h2; ph1.y = h3;
                __nv_bfloat162 pl0, pl1;
                pl0.x = __float2bfloat16(v0 - __bfloat162float(h0));
                pl0.y = __float2bfloat16(v1 - __bfloat162float(h1));
                pl1.x = __float2bfloat16(v2 - __bfloat162float(h2));
                pl1.y = __float2bfloat16(v3 - __bfloat162float(h3));
                *(__nv_bfloat162*)&Ch[(long)row * ldch + col] = ph0;
                *(__nv_bfloat162*)&Cl[(long)row * ldch + col] = pl0;
                *(__nv_bfloat162*)&Ch[(long)(row + 8) * ldch + col] = ph1;
                *(__nv_bfloat162*)&Cl[(long)(row + 8) * ldch + col] = pl1;
            }
        }
    }
}

// ============ small-tile variant: 32x64 CTA tile (for grid-starved z=1/z=3 GEMMs) ============
#define OA_H2 0
#define OA_L2 4608
#define OB_H2 9216
#define OB_L2 18432
#define STAGE2 27648
#define GSM2 55296

__global__ void __launch_bounds__(256, 4)
gemm_sm(const bf16* __restrict__ Ah, const bf16* __restrict__ Al, int lda, long a_z,
        const bf16* __restrict__ Bh, const bf16* __restrict__ Bl, long b_z, int ldb,
        const float* __restrict__ bias, int bias_z,
        float* __restrict__ C, long c_z, int ldc,
        bf16* __restrict__ Ch, bf16* __restrict__ Cl, int ldch,
        int K, int flags)
{
    extern __shared__ char sm[];
    uint32_t sb = smem_u32(sm);
    const int tid = threadIdx.x, lane = tid & 31, wid = tid >> 5;
    const int wm = wid >> 2, wn = wid & 3;               // warp grid 2(m) x 4(n), warp tile 16x16
    const int m0 = blockIdx.y * 32, n0 = blockIdx.x * 64, z = blockIdx.z;
    const bf16* Ahp = Ah + (long)z * a_z;
    const bf16* Alp = Al + (long)z * a_z;
    const bf16* Bhp = Bh + (long)z * b_z;
    const bf16* Blp = Bl + (long)z * b_z;

    const int ld_r = tid >> 3, ld_c = (tid & 7) * 8;
    const uint32_t s_wr = (uint32_t)(ld_r * TSTRIDE + ld_c * 2);

    const int a_r = (lane & 7) + ((lane >> 3) & 1) * 8;
    const int a_c8 = (lane >> 4) * 8;
    const uint32_t aoff = (uint32_t)((wm * 16 + a_r) * TSTRIDE + a_c8 * 2);
    const int b_r = (lane & 7) + (lane >> 4) * 8;
    const int b_c8 = ((lane >> 3) & 1) * 8;
    const uint32_t boff = (uint32_t)((wn * 16 + b_r) * TSTRIDE + b_c8 * 2);

    float acc[2][4];
#pragma unroll
    for (int j = 0; j < 2; j++)
#pragma unroll
        for (int q = 0; q < 4; q++) acc[j][q] = 0.f;

    uint32_t fah[2][4], fal[2][4], fbh[2][2][2], fbl[2][2][2];

    const int nch = K >> 6;

    auto issue = [&](int kk, int st){
        uint32_t base = sb + st * STAGE2 + s_wr;
        const bf16* ga0 = Ahp + (long)(m0 + ld_r) * lda + kk + ld_c;
        const bf16* ga1 = Alp + (long)(m0 + ld_r) * lda + kk + ld_c;
        const bf16* gb0 = Bhp + (long)(n0 + ld_r) * ldb + kk + ld_c;
        const bf16* gb1 = Blp + (long)(n0 + ld_r) * ldb + kk + ld_c;
        cpa16(base + OA_H2, ga0);
        cpa16(base + OA_L2, ga1);
        cpa16(base + OB_H2,                gb0);
        cpa16(base + OB_H2 + 32 * TSTRIDE, gb0 + 32 * ldb);
        cpa16(base + OB_L2,                gb1);
        cpa16(base + OB_L2 + 32 * TSTRIDE, gb1 + 32 * ldb);
        cpa_commit();
    };

    issue(0, 0);
    for (int i = 0; i < nch; i++) {
        if (i + 1 < nch) { issue((i + 1) << 6, (i + 1) & 1); cpa_wait<1>(); }
        else             { cpa_wait<0>(); }
        __syncthreads();

        uint32_t st = sb + (i & 1) * STAGE2;

        ldsm4(fbh[0][0][0], fbh[0][0][1], fbh[0][1][0], fbh[0][1][1], st + OB_H2 + boff);
        ldsm4(fbl[0][0][0], fbl[0][0][1], fbl[0][1][0], fbl[0][1][1], st + OB_L2 + boff);
        ldsm4(fah[0][0], fah[0][1], fah[0][2], fah[0][3], st + OA_H2 + aoff);
        ldsm4(fal[0][0], fal[0][1], fal[0][2], fal[0][3], st + OA_L2 + aoff);

#pragma unroll
        for (int ks = 0; ks < 4; ks++) {
            const int cur = ks & 1, nxt = cur ^ 1;
            if (ks < 3) {
                uint32_t kb = (ks + 1) * 32;
                ldsm4(fbh[nxt][0][0], fbh[nxt][0][1], fbh[nxt][1][0], fbh[nxt][1][1],
                      st + OB_H2 + boff + kb);
                ldsm4(fbl[nxt][0][0], fbl[nxt][0][1], fbl[nxt][1][0], fbl[nxt][1][1],
                      st + OB_L2 + boff + kb);
                ldsm4(fah[nxt][0], fah[nxt][1], fah[nxt][2], fah[nxt][3],
                      st + OA_H2 + aoff + kb);
                ldsm4(fal[nxt][0], fal[nxt][1], fal[nxt][2], fal[nxt][3],
                      st + OA_L2 + aoff + kb);
            }
#pragma unroll
            for (int nf = 0; nf < 2; nf++) mma16816(acc[nf], fah[cur], fbh[cur][nf]);
#pragma unroll
            for (int nf = 0; nf < 2; nf++) mma16816(acc[nf], fah[cur], fbl[cur][nf]);
#pragma unroll
            for (int nf = 0; nf < 2; nf++) mma16816(acc[nf], fal[cur], fbh[cur][nf]);
        }
        __syncthreads();
    }

    const int g = lane >> 2, tg = lane & 3;
    const float* bp = bias ? bias + (long)z * bias_z : nullptr;
    float* Cz = C ? C + (long)z * c_z : nullptr;
#pragma unroll
    for (int nf = 0; nf < 2; nf++) {
        int row = m0 + wm * 16 + g;
        int col = n0 + wn * 16 + nf * 8 + tg * 2;
        float v0 = acc[nf][0], v1 = acc[nf][1];
        float v2 = acc[nf][2], v3 = acc[nf][3];
        if (bp) {
            float bb0 = __ldg(bp + col), bb1 = __ldg(bp + col + 1);
            v0 += bb0; v1 += bb1; v2 += bb0; v3 += bb1;
        }
        if (flags & FL_RELU) {
            v0 = fmaxf(v0, 0.f); v1 = fmaxf(v1, 0.f);
            v2 = fmaxf(v2, 0.f); v3 = fmaxf(v3, 0.f);
        }
        if (flags & FL_F32) {
            *(float2*)&Cz[(long)row * ldc + col] = make_float2(v0, v1);
            *(float2*)&Cz[(long)(row + 8) * ldc + col] = make_float2(v2, v3);
        }
        if (flags & FL_HILO) {
            bf16 h0 = __float2bfloat16(v0), h1 = __float2bfloat16(v1);
            bf16 h2 = __float2bfloat16(v2), h3 = __float2bfloat16(v3);
            __nv_bfloat162 ph0; ph0.x = h0; ph0.y = h1;
            __nv_bfloat162 ph1; ph1.x = h2; ph1.y = h3;
            __nv_bfloat162 pl0, pl1;
            pl0.x = __float2bfloat16(v0 - __bfloat162float(h0));
            pl0.y = __float2bfloat16(v1 - __bfloat162float(h1));
            pl1.x = __float2bfloat16(v2 - __bfloat162float(h2));
            pl1.y = __float2bfloat16(v3 - __bfloat162float(h3));
            *(__nv_bfloat162*)&Ch[(long)row * ldch + col] = ph0;
            *(__nv_bfloat162*)&Cl[(long)row * ldch + col] = pl0;
            *(__nv_bfloat162*)&Ch[(long)(row + 8) * ldch + col] = ph1;
            *(__nv_bfloat162*)&Cl[(long)(row + 8) * ldch + col] = pl1;
        }
    }
}

// ======================= LayerNorms =======================
__global__ void ln1_k(const float* __restrict__ in, const float* __restrict__ g,
                      const float* __restrict__ b, bf16* __restrict__ oh, bf16* __restrict__ ol)
{
    int row = blockIdx.x, t = threadIdx.x;   // 256 threads
    __shared__ float rbuf[256];
    long base = (long)row * DD;
    float v0 = in[base + t], v1 = in[base + t + 256];
    rbuf[t] = v0 + v1; __syncthreads();
    for (int s = 128; s > 0; s >>= 1) { if (t < s) rbuf[t] += rbuf[t + s]; __syncthreads(); }
    float mean = rbuf[0] * (1.0f / 512.0f);
    __syncthreads();
    float d0 = v0 - mean, d1 = v1 - mean;
    rbuf[t] = d0 * d0 + d1 * d1; __syncthreads();
    for (int s = 128; s > 0; s >>= 1) { if (t < s) rbuf[t] += rbuf[t + s]; __syncthreads(); }
    float rs = rsqrtf(rbuf[0] * (1.0f / 512.0f) + 1e-5f);
    float o0 = d0 * rs * g[t] + b[t];
    float o1 = d1 * rs * g[t + 256] + b[t + 256];
    bf16 h0 = __float2bfloat16(o0), h1 = __float2bfloat16(o1);
    oh[base + t] = h0;       ol[base + t]       = __float2bfloat16(o0 - __bfloat162float(h0));
    oh[base + t + 256] = h1; ol[base + t + 256] = __float2bfloat16(o1 - __bfloat162float(h1));
}

__global__ void ln2_k(const float* __restrict__ in, const float* __restrict__ add,
                      const float* __restrict__ g, const float* __restrict__ b,
                      float* __restrict__ out)
{
    int row = blockIdx.x, t = threadIdx.x;
    __shared__ float rbuf[256];
    long base = (long)row * DD;
    float v0 = in[base + t] + add[base + t];
    float v1 = in[base + t + 256] + add[base + t + 256];
    rbuf[t] = v0 + v1; __syncthreads();
    for (int s = 128; s > 0; s >>= 1) { if (t < s) rbuf[t] += rbuf[t + s]; __syncthreads(); }
    float mean = rbuf[0] * (1.0f / 512.0f);
    __syncthreads();
    float d0 = v0 - mean, d1 = v1 - mean;
    rbuf[t] = d0 * d0 + d1 * d1; __syncthreads();
    for (int s = 128; s > 0; s >>= 1) { if (t < s) rbuf[t] += rbuf[t + s]; __syncthreads(); }
    float rs = rsqrtf(rbuf[0] * (1.0f / 512.0f) + 1e-5f);
    out[base + t]       = d0 * rs * g[t]       + b[t];
    out[base + t + 256] = d1 * rs * g[t + 256] + b[t + 256];
}

// ======================= attention: scores+softmax, 16-row tiles =======================
__global__ void attn_scores_k(const float* __restrict__ q, const float* __restrict__ k,
                              float* __restrict__ attn)
{
    int it = blockIdx.x, h = blockIdx.y, b = blockIdx.z;  // 256 thr
    int t = threadIdx.x;
    int i0 = it * 16;
    __shared__ float ks[SS][DH + 1];
    __shared__ float qs[16][DH + 1];
    __shared__ float P[16][SS];
    const float* kbase = k + (long)b * SS * DD + h * DH;
    const float* qbase = q + (long)b * SS * DD + h * DH;
    for (int idx = t; idx < SS * DH; idx += 256) {
        int j = idx >> 6, d = idx & 63;
        ks[j][d] = kbase[(long)j * DD + d];
    }
    for (int idx = t; idx < 16 * DH; idx += 256) {
        int r = idx >> 6, d = idx & 63;
        qs[r][d] = qbase[(long)(i0 + r) * DD + d];
    }
    __syncthreads();
    {
        int j = t & 127, grp = t >> 7;
#pragma unroll
        for (int r = 0; r < 8; r++) {
            int i = grp * 8 + r;
            float acc = 0.f;
#pragma unroll
            for (int d = 0; d < DH; d++) acc += qs[i][d] * ks[j][d];
            P[i][j] = acc * 0.125f;
        }
    }
    __syncthreads();
    {
        int w = t >> 5, ln = t & 31;
        long obase = (((long)(b * HH + h) * SS) + i0) * SS;
#pragma unroll
        for (int rr = 0; rr < 2; rr++) {
            int i = w * 2 + rr;
            float m = -1e30f;
#pragma unroll
            for (int c = 0; c < 4; c++) m = fmaxf(m, P[i][ln + c * 32]);
#pragma unroll
            for (int o = 16; o > 0; o >>= 1) m = fmaxf(m, __shfl_xor_sync(0xffffffffu, m, o));
            float s = 0.f, e[4];
#pragma unroll
            for (int c = 0; c < 4; c++) { e[c] = expf(P[i][ln + c * 32] - m); s += e[c]; }
#pragma unroll
            for (int o = 16; o > 0; o >>= 1) s += __shfl_xor_sync(0xffffffffu, s, o);
            float inv = 1.0f / s;
#pragma unroll
            for (int c = 0; c < 4; c++) attn[obase + (long)i * SS + ln + c * 32] = e[c] * inv;
        }
    }
}

__global__ void am_k(const float* __restrict__ attn, float* __restrict__ am)
{
    int bi = blockIdx.x;
    int b = bi >> 7, i = bi & 127, t = threadIdx.x;  // 128 thr
    float s = 0.f;
#pragma unroll
    for (int h = 0; h < HH; h++)
        s += attn[(((long)(b * HH + h) * SS) + i) * SS + t];
    am[(long)bi * SS + t] = s * 0.125f;
}

// ======================= attention: ctx = P @ V, 16-row tiles =======================
__global__ void attn_ctx_k(const float* __restrict__ attn, const float* __restrict__ v,
                           bf16* __restrict__ ch, bf16* __restrict__ cl)
{
    int it = blockIdx.x, h = blockIdx.y, b = blockIdx.z;  // 256 thr
    int t = threadIdx.x;
    int i0 = it * 16;
    int d = t & 63, ig = t >> 6;
    __shared__ float vs[SS][DH + 1];
    __shared__ float at[16][SS];
    const float* vbase = v + (long)b * SS * DD + h * DH;
    for (int idx = t; idx < SS * DH; idx += 256) {
        int j = idx >> 6, dd = idx & 63;
        vs[j][dd] = vbase[(long)j * DD + dd];
    }
    long arow = (((long)(b * HH + h) * SS) + i0) * SS;
    for (int idx = t; idx < 16 * SS; idx += 256)
        at[idx >> 7][idx & 127] = attn[arow + (long)(idx >> 7) * SS + (idx & 127)];
    __syncthreads();

    float acc[4] = {0.f, 0.f, 0.f, 0.f};
#pragma unroll
    for (int jh = 0; jh < 2; jh++) {
        float vreg[64];
#pragma unroll
        for (int jj = 0; jj < 64; jj++) vreg[jj] = vs[jh * 64 + jj][d];
#pragma unroll
        for (int r = 0; r < 4; r++) {
            int i = ig + 4 * r;
            float a = acc[r];
#pragma unroll
            for (int jj = 0; jj < 64; jj++) a += at[i][jh * 64 + jj] * vreg[jj];
            acc[r] = a;
        }
    }
#pragma unroll
    for (int r = 0; r < 4; r++) {
        int i = ig + 4 * r;
        long o = (long)(b * SS + i0 + i) * DD + h * DH + d;
        bf16 hh = __float2bfloat16(acc[r]);
        ch[o] = hh; cl[o] = __float2bfloat16(acc[r] - __bfloat162float(hh));
    }
}

// ======================= nu: reduce split-K partials + bias + hi/lo =======================
__global__ void conv_nu_k(const float* __restrict__ P, const float* __restrict__ b2,
                          float* __restrict__ nu, bf16* __restrict__ H, bf16* __restrict__ L)
{
    int row = blockIdx.x, t = threadIdx.x;  // 256
    for (int c = t; c < DD; c += 256) {
        long i = (long)row * DD + c;
        float v = b2[c] + P[i] + P[UU + i] + P[2L*UU + i] + P[3L*UU + i];
        nu[i] = v;
        bf16 h = __float2bfloat16(v);
        H[i] = h; L[i] = __float2bfloat16(v - __bfloat162float(h));
    }
}

// ======================= pair relation classifier (early-exit on empty tiles) ===========
__global__ void pair_k(const float* __restrict__ ap, const float* __restrict__ bp,
                       const float* __restrict__ rc_b1, const float* __restrict__ rc_w2,
                       const float* __restrict__ rc_b2, const float* __restrict__ am,
                       int* __restrict__ rel)
{
    int b = blockIdx.z;
    int u0 = blockIdx.y * 16, v0 = blockIdx.x * 16;
    int t = threadIdx.x;                 // 256
    int ul = t >> 4, vl = t & 15;
    int u = u0 + ul, v = v0 + vl;
    long ridx = ((long)b * SS + u) * SS + v;

    __shared__ __align__(16) float sA[16][65];
    __shared__ __align__(16) float sB[16][65];
    __shared__ __align__(16) float sW[64][8];
    __shared__ float sC[64];
    __shared__ int any;

    if (t == 0) any = 0;
    __syncthreads();
    float amv = am[ridx];
    int adj = (amv > THRESH) && (u != v);
    if (adj) any = 1;
    __syncthreads();
    if (!any) { rel[ridx] = 0; return; }

    float acc[RR];
#pragma unroll
    for (int r = 0; r < RR; r++) acc[r] = rc_b2[r];

    for (int c0 = 0; c0 < DD; c0 += 64) {
        for (int idx = t; idx < 1024; idx += 256) {
            int rr = idx >> 6, cc = idx & 63;
            sA[rr][cc] = ap[(long)(b * SS + u0 + rr) * DD + c0 + cc];
            sB[rr][cc] = bp[(long)(b * SS + v0 + rr) * DD + c0 + cc];
        }
        for (int idx = t; idx < 512; idx += 256)
            sW[idx >> 3][idx & 7] = rc_w2[(long)(c0 + (idx >> 3)) * RR + (idx & 7)];
        if (t < 64) sC[t] = rc_b1[c0 + t];
        __syncthreads();
#pragma unroll 4
        for (int dd = 0; dd < 64; dd++) {
            float hsum = sA[ul][dd] + sB[vl][dd] + sC[dd];
            hsum = fmaxf(hsum, 0.f);
            float4 w0 = *(float4*)&sW[dd][0];
            float4 w1 = *(float4*)&sW[dd][4];
            acc[0] += hsum * w0.x; acc[1] += hsum * w0.y;
            acc[2] += hsum * w0.z; acc[3] += hsum * w0.w;
            acc[4] += hsum * w1.x; acc[5] += hsum * w1.y;
            acc[6] += hsum * w1.z; acc[7] += hsum * w1.w;
        }
        __syncthreads();
    }
    int pred = 0; float best = acc[0];
#pragma unroll
    for (int r = 1; r < RR; r++) if (acc[r] > best) { best = acc[r]; pred = r; }
    int valid = adj && (pred != 0);
    rel[ridx] = valid ? pred : 0;
}

// ======================= edge aggregation (trans slabs [r][n][d]) =======================
__global__ void agg_k(const int* __restrict__ rel, const float* __restrict__ trans,
                      const float* __restrict__ nu, bf16* __restrict__ rh, bf16* __restrict__ rl)
{
    int bv = blockIdx.x;                 // b*S + v
    int b = bv >> 7, v = bv & 127, t = threadIdx.x;   // 256
    __shared__ int sr[SS];
    if (t < SS) sr[t] = rel[((long)b * SS + t) * SS + v];
    __syncthreads();
    float a0 = 0.f, a1 = 0.f;
    for (int u = 0; u < SS; u++) {
        int r = sr[u];
        if (r) {
            const float* tr = trans + (long)r * UU + (long)(b * SS + u) * DD;
            a0 += tr[t]; a1 += tr[t + 256];
        }
    }
    long row = (long)bv * DD;
    float v0 = nu[row + t] + a0;
    float v1 = nu[row + t + 256] + a1;
    bf16 h0 = __float2bfloat16(v0), h1 = __float2bfloat16(v1);
    rh[row + t] = h0;       rl[row + t]       = __float2bfloat16(v0 - __bfloat162float(h0));
    rh[row + t + 256] = h1; rl[row + t + 256] = __float2bfloat16(v1 - __bfloat162float(h1));
}

// ======================= launch =======================
extern "C" void kernel_launch(void* const* d_in, const int* in_sizes, int n_in,
                              void* d_out, int out_size)
{
    const float* x     = (const float*)d_in[0];
    const float* ln1_g = (const float*)d_in[1];
    const float* ln1_b = (const float*)d_in[2];
    const float* wq    = (const float*)d_in[3];
    const float* bq    = (const float*)d_in[4];
    const float* wk    = (const float*)d_in[5];
    const float* bk    = (const float*)d_in[6];
    const float* wv    = (const float*)d_in[7];
    const float* bvv   = (const float*)d_in[8];
    const float* wo    = (const float*)d_in[9];
    const float* bo    = (const float*)d_in[10];
    const float* w1    = (const float*)d_in[11];
    const float* b1    = (const float*)d_in[12];
    const float* w2    = (const float*)d_in[13];
    const float* b2    = (const float*)d_in[14];
    const float* rc_w1 = (const float*)d_in[15];
    const float* rc_b1 = (const float*)d_in[16];
    const float* rc_w2 = (const float*)d_in[17];
    const float* rc_b2 = (const float*)d_in[18];
    const float* kg_w  = (const float*)d_in[19];
    const float* s2n_w = (const float*)d_in[20];
    const float* s2n_b = (const float*)d_in[21];
    const float* ln2_g = (const float*)d_in[22];
    const float* ln2_b = (const float*)d_in[23];
    float* out = (float*)d_out;

    bf16 *wTh, *wTl, *xnh, *xnl, *ctxh, *ctxl, *aoh, *aol, *hidh, *hidl, *nuh, *nul, *rsh, *rsl;
    float *b3, *qkv, *attn, *am, *nupart, *nu, *abt, *nr;
    int *rel;
    cudaGetSymbolAddress((void**)&wTh, g_wTh);   cudaGetSymbolAddress((void**)&wTl, g_wTl);
    cudaGetSymbolAddress((void**)&b3, g_b3);
    cudaGetSymbolAddress((void**)&xnh, g_xnh);   cudaGetSymbolAddress((void**)&xnl, g_xnl);
    cudaGetSymbolAddress((void**)&qkv, g_qkv);
    cudaGetSymbolAddress((void**)&attn, g_attn); cudaGetSymbolAddress((void**)&am, g_am);
    cudaGetSymbolAddress((void**)&ctxh, g_ctxh); cudaGetSymbolAddress((void**)&ctxl, g_ctxl);
    cudaGetSymbolAddress((void**)&aoh, g_aoh);   cudaGetSymbolAddress((void**)&aol, g_aol);
    cudaGetSymbolAddress((void**)&hidh, g_hidh); cudaGetSymbolAddress((void**)&hidl, g_hidl);
    cudaGetSymbolAddress((void**)&nupart, g_nupart);
    cudaGetSymbolAddress((void**)&nu, g_nu);
    cudaGetSymbolAddress((void**)&nuh, g_nuh);   cudaGetSymbolAddress((void**)&nul, g_nul);
    cudaGetSymbolAddress((void**)&abt, g_abt);
    cudaGetSymbolAddress((void**)&rel, g_rel);
    cudaGetSymbolAddress((void**)&rsh, g_rsh);   cudaGetSymbolAddress((void**)&rsl, g_rsl);
    cudaGetSymbolAddress((void**)&nr, g_nr);

    cudaFuncSetAttribute(gemm_mma, cudaFuncAttributeMaxDynamicSharedMemorySize, GSM);
    cudaFuncSetAttribute(gemm_mma, cudaFuncAttributePreferredSharedMemoryCarveout, 100);
    cudaFuncSetAttribute(gemm_sm, cudaFuncAttributeMaxDynamicSharedMemorySize, GSM2);
    cudaFuncSetAttribute(gemm_sm, cudaFuncAttributePreferredSharedMemoryCarveout, 100);

    // weight prep
    setup_k<<<1, 512>>>(wq, wk, wv, wo, w1, w2, rc_w1, kg_w, s2n_w, bq, bk, bvv);
    wconv_k<<<dim3(16, 16, 23), dim3(32, 8)>>>();

    // ln1 -> xn (hi/lo)
    ln1_k<<<BS, 256>>>(x, ln1_g, ln1_b, xnh, xnl);

    // QKV (z=3), fp32 out — small tile for 384 CTAs
    gemm_sm<<<dim3(8, 16, 3), 256, GSM2>>>(xnh, xnl, DD, 0, wTh, wTl, UU, DD,
                                           b3, DD, qkv, UU, DD, nullptr, nullptr, 0,
                                           DD, FL_F32);
    // attention (16-row tiled)
    attn_scores_k<<<dim3(8, HH, BB), 256>>>(qkv, qkv + UU, attn);
    am_k<<<BS, 128>>>(attn, am);
    attn_ctx_k<<<dim3(8, HH, BB), 256>>>(attn, qkv + 2 * UU, ctxh, ctxl);

    // ao = ctx @ wo + bo  (hi/lo only) — small tile (grid-starved z=1)
    gemm_sm<<<dim3(8, 16, 1), 256, GSM2>>>(ctxh, ctxl, DD, 0, wTh + 3L*UU, wTl + 3L*UU, 0, DD,
                                           bo, 0, nullptr, 0, 0, aoh, aol, DD,
                                           DD, FL_HILO);
    // hid = relu(ao @ w1 + b1) (hi/lo only, N=2048) — big tile (B traffic)
    gemm_mma<<<dim3(32, 8, 1), 256, GSM>>>(aoh, aol, DD, 0, wTh + 4L*UU, wTl + 4L*UU, 0, DD,
                                           b1, 0, nullptr, 0, 0, hidh, hidl, FF,
                                           DD, FL_HILO | FL_RELU);
    // nu partials = hid @ w2  (split-K z=4 into 4 slabs)
    gemm_mma<<<dim3(8, 8, 4), 256, GSM>>>(hidh, hidl, FF, DD, wTh + 8L*UU, wTl + 8L*UU, DD, FF,
                                          nullptr, 0, nupart, UU, DD, nullptr, nullptr, 0,
                                          DD, FL_F32);
    conv_nu_k<<<BS, 256>>>(nupart, b2, nu, nuh, nul);

    // fused: a/b parts (z=0,1) + RGCN transforms (z=2..9) in one launch — big tile
    gemm_mma<<<dim3(8, 8, 10), 256, GSM>>>(nuh, nul, DD, 0, wTh + 12L*UU, wTl + 12L*UU, UU, DD,
                                           nullptr, 0, abt, UU, DD, nullptr, nullptr, 0,
                                           DD, FL_F32);
    // edges (early-exit tiles) + aggregation (trans slabs start at abt + 2*UU)
    pair_k<<<dim3(8, 8, BB), 256>>>(abt, abt + UU, rc_b1, rc_w2, rc_b2, am, rel);
    agg_k<<<BS, 256>>>(rel, abt + 2L*UU, nu, rsh, rsl);

    // s2n projection, fp32 — small tile (grid-starved z=1)
    gemm_sm<<<dim3(8, 16, 1), 256, GSM2>>>(rsh, rsl, DD, 0, wTh + 22L*UU, wTl + 22L*UU, 0, DD,
                                           s2n_b, 0, nr, 0, DD, nullptr, nullptr, 0,
                                           DD, FL_F32);
    // final residual LN
    ln2_k<<<BS, 256>>>(nr, x, ln2_g, ln2_b, out);
}

// round 12
// speedup vs baseline: 1.2950x; 1.2108x over previous
#include <cuda_runtime.h>
#include <cuda_bf16.h>
#include <math.h>
#include <stdint.h>

#define BB 4
#define SS 128
#define DD 512
#define HH 8
#define DH 64
#define FF 2048
#define RR 8
#define BS (BB*SS)          // 512
#define UU 262144           // 512*512
#define THRESH 0.1f
#define MAXE 8192

typedef __nv_bfloat16 bf16;

// ======================= helpers =======================
__device__ __forceinline__ uint32_t smem_u32(const void* p){
    uint32_t a;
    asm("{ .reg .u64 t; cvta.to.shared.u64 t, %1; cvt.u32.u64 %0, t; }" : "=r"(a) : "l"(p));
    return a;
}
__device__ __forceinline__ void ldsm4(uint32_t& r0, uint32_t& r1, uint32_t& r2, uint32_t& r3,
                                      uint32_t addr){
    asm volatile("ldmatrix.sync.aligned.m8n8.x4.shared.b16 {%0,%1,%2,%3}, [%4];"
                 : "=r"(r0), "=r"(r1), "=r"(r2), "=r"(r3) : "r"(addr));
}
__device__ __forceinline__ void mma16816(float* d, const uint32_t* a, const uint32_t* b){
    asm volatile("mma.sync.aligned.m16n8k16.row.col.f32.bf16.bf16.f32 "
                 "{%0,%1,%2,%3}, {%4,%5,%6,%7}, {%8,%9}, {%0,%1,%2,%3};"
                 : "+f"(d[0]), "+f"(d[1]), "+f"(d[2]), "+f"(d[3])
                 : "r"(a[0]), "r"(a[1]), "r"(a[2]), "r"(a[3]), "r"(b[0]), "r"(b[1]));
}
__device__ __forceinline__ void cpa16(uint32_t s, const void* g){
    asm volatile("cp.async.cg.shared.global [%0], [%1], 16;" :: "r"(s), "l"(g));
}
__device__ __forceinline__ void cpa_commit(){
    asm volatile("cp.async.commit_group;" ::: "memory");
}
template<int N> __device__ __forceinline__ void cpa_wait(){
    asm volatile("cp.async.wait_group %0;" :: "n"(N) : "memory");
}

// ======================= scratch (device globals) =======================
__device__ bf16  g_wTh[23*UU];          // packed transposed weights, hi
__device__ bf16  g_wTl[23*UU];          // packed transposed weights, lo
__device__ float g_b3[3*DD];            // packed q/k/v biases
__device__ bf16  g_xnh[UU], g_xnl[UU];
__device__ float g_qkv[3*UU];
__device__ float g_attn[BB*HH*SS*SS];
__device__ bf16  g_ctxh[UU], g_ctxl[UU];
__device__ bf16  g_aoh[UU],  g_aol[UU];
__device__ bf16  g_hidh[BS*FF], g_hidl[BS*FF];
__device__ float g_nupart[4*UU];        // split-K partials for nu
__device__ float g_nu[UU];
__device__ bf16  g_nuh[UU], g_nul[UU];
__device__ float g_abt[10*UU];          // [0,1]=a/b parts, [2..9]=trans slabs [r][n][d]
__device__ int   g_rel[BB*SS*SS];
__device__ bf16  g_rsh[UU], g_rsl[UU];
__device__ float g_nr[UU];
__device__ int2  g_elist[MAXE];
__device__ int   g_ecnt;

struct WUnit { const float* src; int ld; long dst; int dld; };
__device__ WUnit g_wu[23];

// ======================= setup: weight-unit table + packed biases =======================
__global__ void setup_k(const float* wq, const float* wk, const float* wv, const float* wo,
                        const float* w1, const float* w2, const float* rc, const float* kg,
                        const float* s2n, const float* bq, const float* bk, const float* bvv)
{
    int t = threadIdx.x;
    if (t < DD) { g_b3[t] = bq[t]; g_b3[DD+t] = bk[t]; g_b3[2*DD+t] = bvv[t]; }
    if (t == 0) {
        g_ecnt = 0;
        const float* qkv[3] = {wq, wk, wv};
        for (int u = 0; u < 3; u++) g_wu[u] = {qkv[u], DD, (long)u*UU, DD};
        g_wu[3] = {wo, DD, 3L*UU, DD};
        for (int u = 0; u < 4; u++)                       // w1 [512][2048] -> [2048][512]
            g_wu[4+u] = {w1 + u*DD, FF, 4L*UU + (long)u*UU, DD};
        for (int u = 0; u < 4; u++)                       // w2 [2048][512] -> [512][2048]
            g_wu[8+u] = {w2 + (long)u*UU, DD, 8L*UU + (long)u*DD, FF};
        for (int u = 0; u < 2; u++)
            g_wu[12+u] = {rc + (long)u*UU, DD, (12L+u)*UU, DD};
        for (int u = 0; u < 8; u++)
            g_wu[14+u] = {kg + (long)u*UU, DD, (14L+u)*UU, DD};
        g_wu[22] = {s2n, DD, 22L*UU, DD};
    }
}

// ============ weight transpose + fp32 -> bf16 hi/lo (vectorized bf162 stores) ============
__global__ void wconv_k()
{
    __shared__ float tile[32][33];
    WUnit u = g_wu[blockIdx.z];
    int k0 = blockIdx.y * 32, n0 = blockIdx.x * 32;
    int tx = threadIdx.x, ty = threadIdx.y;        // (32, 8)
    int t = ty * 32 + tx;                          // 0..255
#pragma unroll
    for (int i = 0; i < 4; i++)
        tile[ty + 8*i][tx] = __ldg(u.src + (long)(k0 + ty + 8*i) * u.ld + n0 + tx);
    __syncthreads();
#pragma unroll
    for (int i = 0; i < 2; i++) {
        int p = t + i * 256;                       // pair index: n = p>>4, kp = p&15
        int n = p >> 4, kp = p & 15;
        float v0 = tile[2*kp    ][n];
        float v1 = tile[2*kp + 1][n];
        bf16 h0 = __float2bfloat16(v0), h1 = __float2bfloat16(v1);
        __nv_bfloat162 ph; ph.x = h0; ph.y = h1;
        __nv_bfloat162 pl;
        pl.x = __float2bfloat16(v0 - __bfloat162float(h0));
        pl.y = __float2bfloat16(v1 - __bfloat162float(h1));
        long off = u.dst + (long)(n0 + n) * u.dld + k0 + 2*kp;
        *(__nv_bfloat162*)&g_wTh[off] = ph;
        *(__nv_bfloat162*)&g_wTl[off] = pl;
    }
}

// ======================= mma.sync bf16 3-pass GEMM (64x64 tile, 2-stage) =======================
#define FL_F32  1
#define FL_HILO 2
#define FL_RELU 4

#define TSTRIDE 144                      // smem row stride bytes (72 bf16)
#define TILE_B  9216                     // 64 rows * 144 B
#define STAGE_B 36864                    // 4 tiles
#define GSM     73728                    // 2 stages

__global__ void __launch_bounds__(256, 3)
gemm_mma(const bf16* __restrict__ Ah, const bf16* __restrict__ Al, int lda, long a_z,
         const bf16* __restrict__ Bh, const bf16* __restrict__ Bl, long b_z, int ldb,
         const float* __restrict__ bias, int bias_z,
         float* __restrict__ C, long c_z, int ldc,
         bf16* __restrict__ Ch, bf16* __restrict__ Cl, int ldch,
         int K, int flags)
{
    extern __shared__ char sm[];
    uint32_t sb = smem_u32(sm);
    const int tid = threadIdx.x, lane = tid & 31, wid = tid >> 5;
    const int wm = wid >> 2, wn = wid & 3;               // warp grid 2 x 4
    const int m0 = blockIdx.y * 64, n0 = blockIdx.x * 64, z = blockIdx.z;
    const bf16* Ahp = Ah + (long)z * a_z;
    const bf16* Alp = Al + (long)z * a_z;
    const bf16* Bhp = Bh + (long)z * b_z;
    const bf16* Blp = Bl + (long)z * b_z;

    const int ld_r = tid >> 3, ld_c = (tid & 7) * 8;
    const uint32_t s_wr = (uint32_t)(ld_r * TSTRIDE + ld_c * 2);

    const int a_r = (lane & 7) + ((lane >> 3) & 1) * 8;
    const int a_c8 = (lane >> 4) * 8;
    const uint32_t aoff = (uint32_t)((wm * 32 + a_r) * TSTRIDE + a_c8 * 2);
    const int b_r = (lane & 7) + (lane >> 4) * 8;
    const int b_c8 = ((lane >> 3) & 1) * 8;
    const uint32_t boff = (uint32_t)((wn * 16 + b_r) * TSTRIDE + b_c8 * 2);

    float acc[2][2][4];
#pragma unroll
    for (int i = 0; i < 2; i++)
#pragma unroll
        for (int j = 0; j < 2; j++)
#pragma unroll
            for (int q = 0; q < 4; q++) acc[i][j][q] = 0.f;

    uint32_t fah[2][2][4], fal[2][2][4], fbh[2][2][2], fbl[2][2][2];

    const int nch = K >> 6;

    auto issue = [&](int kk, int st){
        uint32_t base = sb + st * STAGE_B + s_wr;
        const bf16* ga0 = Ahp + (long)(m0 + ld_r) * lda + kk + ld_c;
        const bf16* ga1 = Alp + (long)(m0 + ld_r) * lda + kk + ld_c;
        const bf16* gb0 = Bhp + (long)(n0 + ld_r) * ldb + kk + ld_c;
        const bf16* gb1 = Blp + (long)(n0 + ld_r) * ldb + kk + ld_c;
        cpa16(base,                         ga0);
        cpa16(base + 32 * TSTRIDE,          ga0 + 32 * lda);
        cpa16(base + TILE_B,                ga1);
        cpa16(base + TILE_B + 32 * TSTRIDE, ga1 + 32 * lda);
        cpa16(base + 2 * TILE_B,                gb0);
        cpa16(base + 2 * TILE_B + 32 * TSTRIDE, gb0 + 32 * ldb);
        cpa16(base + 3 * TILE_B,                gb1);
        cpa16(base + 3 * TILE_B + 32 * TSTRIDE, gb1 + 32 * ldb);
        cpa_commit();
    };

    issue(0, 0);
    for (int i = 0; i < nch; i++) {
        if (i + 1 < nch) { issue((i + 1) << 6, (i + 1) & 1); cpa_wait<1>(); }
        else             { cpa_wait<0>(); }
        __syncthreads();

        uint32_t st = sb + (i & 1) * STAGE_B;

        {
            ldsm4(fbh[0][0][0], fbh[0][0][1], fbh[0][1][0], fbh[0][1][1], st + 2*TILE_B + boff);
            ldsm4(fbl[0][0][0], fbl[0][0][1], fbl[0][1][0], fbl[0][1][1], st + 3*TILE_B + boff);
#pragma unroll
            for (int mf = 0; mf < 2; mf++)
                ldsm4(fah[0][mf][0], fah[0][mf][1], fah[0][mf][2], fah[0][mf][3],
                      st + aoff + mf * (16*TSTRIDE));
#pragma unroll
            for (int mf = 0; mf < 2; mf++)
                ldsm4(fal[0][mf][0], fal[0][mf][1], fal[0][mf][2], fal[0][mf][3],
                      st + TILE_B + aoff + mf * (16*TSTRIDE));
        }

#pragma unroll
        for (int ks = 0; ks < 4; ks++) {
            const int cur = ks & 1, nxt = cur ^ 1;
            if (ks < 3) {
                uint32_t kb = (ks + 1) * 32;
                ldsm4(fbh[nxt][0][0], fbh[nxt][0][1], fbh[nxt][1][0], fbh[nxt][1][1],
                      st + 2*TILE_B + boff + kb);
                ldsm4(fbl[nxt][0][0], fbl[nxt][0][1], fbl[nxt][1][0], fbl[nxt][1][1],
                      st + 3*TILE_B + boff + kb);
#pragma unroll
                for (int mf = 0; mf < 2; mf++)
                    ldsm4(fah[nxt][mf][0], fah[nxt][mf][1], fah[nxt][mf][2], fah[nxt][mf][3],
                          st + aoff + mf * (16*TSTRIDE) + kb);
#pragma unroll
                for (int mf = 0; mf < 2; mf++)
                    ldsm4(fal[nxt][mf][0], fal[nxt][mf][1], fal[nxt][mf][2], fal[nxt][mf][3],
                          st + TILE_B + aoff + mf * (16*TSTRIDE) + kb);
            }
#pragma unroll
            for (int mf = 0; mf < 2; mf++)
#pragma unroll
                for (int nf = 0; nf < 2; nf++) mma16816(acc[mf][nf], fah[cur][mf], fbh[cur][nf]);
#pragma unroll
            for (int mf = 0; mf < 2; mf++)
#pragma unroll
                for (int nf = 0; nf < 2; nf++) mma16816(acc[mf][nf], fah[cur][mf], fbl[cur][nf]);
#pragma unroll
            for (int mf = 0; mf < 2; mf++)
#pragma unroll
                for (int nf = 0; nf < 2; nf++) mma16816(acc[mf][nf], fal[cur][mf], fbh[cur][nf]);
        }
        __syncthreads();
    }

    const int g = lane >> 2, tg = lane & 3;
    const float* bp = bias ? bias + (long)z * bias_z : nullptr;
    float* Cz = C ? C + (long)z * c_z : nullptr;
#pragma unroll
    for (int mf = 0; mf < 2; mf++) {
#pragma unroll
        for (int nf = 0; nf < 2; nf++) {
            int row = m0 + wm * 32 + mf * 16 + g;
            int col = n0 + wn * 16 + nf * 8 + tg * 2;
            float v0 = acc[mf][nf][0], v1 = acc[mf][nf][1];
            float v2 = acc[mf][nf][2], v3 = acc[mf][nf][3];
            if (bp) {
                float bb0 = __ldg(bp + col), bb1 = __ldg(bp + col + 1);
                v0 += bb0; v1 += bb1; v2 += bb0; v3 += bb1;
            }
            if (flags & FL_RELU) {
                v0 = fmaxf(v0, 0.f); v1 = fmaxf(v1, 0.f);
                v2 = fmaxf(v2, 0.f); v3 = fmaxf(v3, 0.f);
            }
            if (flags & FL_F32) {
                *(float2*)&Cz[(long)row * ldc + col] = make_float2(v0, v1);
                *(float2*)&Cz[(long)(row + 8) * ldc + col] = make_float2(v2, v3);
            }
            if (flags & FL_HILO) {
                bf16 h0 = __float2bfloat16(v0), h1 = __float2bfloat16(v1);
                bf16 h2 = __float2bfloat16(v2), h3 = __float2bfloat16(v3);
                __nv_bfloat162 ph0; ph0.x = h0; ph0.y = h1;
                __nv_bfloat162 ph1; ph1.x = h2; ph1.y = h3;
                __nv_bfloat162 pl0, pl1;
                pl0.x = __float2bfloat16(v0 - __bfloat162float(h0));
                pl0.y = __float2bfloat16(v1 - __bfloat162float(h1));
                pl1.x = __float2bfloat16(v2 - __bfloat162float(h2));
                pl1.y = __float2bfloat16(v3 - __bfloat162float(h3));
                *(__nv_bfloat162*)&Ch[(long)row * ldch + col] = ph0;
                *(__nv_bfloat162*)&Cl[(long)row * ldch + col] = pl0;
                *(__nv_bfloat162*)&Ch[(long)(row + 8) * ldch + col] = ph1;
                *(__nv_bfloat162*)&Cl[(long)(row + 8) * ldch + col] = pl1;
            }
        }
    }
}

// ============ small-tile variant: 32x64 CTA tile (for grid-starved z=1/z=3 GEMMs) ============
#define OA_H2 0
#define OA_L2 4608
#define OB_H2 9216
#define OB_L2 18432
#define STAGE2 27648
#define GSM2 55296

__global__ void __launch_bounds__(256, 4)
gemm_sm(const bf16* __restrict__ Ah, const bf16* __restrict__ Al, int lda, long a_z,
        const bf16* __restrict__ Bh, const bf16* __restrict__ Bl, long b_z, int ldb,
        const float* __restrict__ bias, int bias_z,
        float* __restrict__ C, long c_z, int ldc,
        bf16* __restrict__ Ch, bf16* __restrict__ Cl, int ldch,
        int K, int flags)
{
    extern __shared__ char sm[];
    uint32_t sb = smem_u32(sm);
    const int tid = threadIdx.x, lane = tid & 31, wid = tid >> 5;
    const int wm = wid >> 2, wn = wid & 3;               // warp grid 2(m) x 4(n), warp tile 16x16
    const int m0 = blockIdx.y * 32, n0 = blockIdx.x * 64, z = blockIdx.z;
    const bf16* Ahp = Ah + (long)z * a_z;
    const bf16* Alp = Al + (long)z * a_z;
    const bf16* Bhp = Bh + (long)z * b_z;
    const bf16* Blp = Bl + (long)z * b_z;

    const int ld_r = tid >> 3, ld_c = (tid & 7) * 8;
    const uint32_t s_wr = (uint32_t)(ld_r * TSTRIDE + ld_c * 2);

    const int a_r = (lane & 7) + ((lane >> 3) & 1) * 8;
    const int a_c8 = (lane >> 4) * 8;
    const uint32_t aoff = (uint32_t)((wm * 16 + a_r) * TSTRIDE + a_c8 * 2);
    const int b_r = (lane & 7) + (lane >> 4) * 8;
    const int b_c8 = ((lane >> 3) & 1) * 8;
    const uint32_t boff = (uint32_t)((wn * 16 + b_r) * TSTRIDE + b_c8 * 2);

    float acc[2][4];
#pragma unroll
    for (int j = 0; j < 2; j++)
#pragma unroll
        for (int q = 0; q < 4; q++) acc[j][q] = 0.f;

    uint32_t fah[2][4], fal[2][4], fbh[2][2][2], fbl[2][2][2];

    const int nch = K >> 6;

    auto issue = [&](int kk, int st){
        uint32_t base = sb + st * STAGE2 + s_wr;
        const bf16* ga0 = Ahp + (long)(m0 + ld_r) * lda + kk + ld_c;
        const bf16* ga1 = Alp + (long)(m0 + ld_r) * lda + kk + ld_c;
        const bf16* gb0 = Bhp + (long)(n0 + ld_r) * ldb + kk + ld_c;
        const bf16* gb1 = Blp + (long)(n0 + ld_r) * ldb + kk + ld_c;
        cpa16(base + OA_H2, ga0);
        cpa16(base + OA_L2, ga1);
        cpa16(base + OB_H2,                gb0);
        cpa16(base + OB_H2 + 32 * TSTRIDE, gb0 + 32 * ldb);
        cpa16(base + OB_L2,                gb1);
        cpa16(base + OB_L2 + 32 * TSTRIDE, gb1 + 32 * ldb);
        cpa_commit();
    };

    issue(0, 0);
    for (int i = 0; i < nch; i++) {
        if (i + 1 < nch) { issue((i + 1) << 6, (i + 1) & 1); cpa_wait<1>(); }
        else             { cpa_wait<0>(); }
        __syncthreads();

        uint32_t st = sb + (i & 1) * STAGE2;

        ldsm4(fbh[0][0][0], fbh[0][0][1], fbh[0][1][0], fbh[0][1][1], st + OB_H2 + boff);
        ldsm4(fbl[0][0][0], fbl[0][0][1], fbl[0][1][0], fbl[0][1][1], st + OB_L2 + boff);
        ldsm4(fah[0][0], fah[0][1], fah[0][2], fah[0][3], st + OA_H2 + aoff);
        ldsm4(fal[0][0], fal[0][1], fal[0][2], fal[0][3], st + OA_L2 + aoff);

#pragma unroll
        for (int ks = 0; ks < 4; ks++) {
            const int cur = ks & 1, nxt = cur ^ 1;
            if (ks < 3) {
                uint32_t kb = (ks + 1) * 32;
                ldsm4(fbh[nxt][0][0], fbh[nxt][0][1], fbh[nxt][1][0], fbh[nxt][1][1],
                      st + OB_H2 + boff + kb);
                ldsm4(fbl[nxt][0][0], fbl[nxt][0][1], fbl[nxt][1][0], fbl[nxt][1][1],
                      st + OB_L2 + boff + kb);
                ldsm4(fah[nxt][0], fah[nxt][1], fah[nxt][2], fah[nxt][3],
                      st + OA_H2 + aoff + kb);
                ldsm4(fal[nxt][0], fal[nxt][1], fal[nxt][2], fal[nxt][3],
                      st + OA_L2 + aoff + kb);
            }
#pragma unroll
            for (int nf = 0; nf < 2; nf++) mma16816(acc[nf], fah[cur], fbh[cur][nf]);
#pragma unroll
            for (int nf = 0; nf < 2; nf++) mma16816(acc[nf], fah[cur], fbl[cur][nf]);
#pragma unroll
            for (int nf = 0; nf < 2; nf++) mma16816(acc[nf], fal[cur], fbh[cur][nf]);
        }
        __syncthreads();
    }

    const int g = lane >> 2, tg = lane & 3;
    const float* bp = bias ? bias + (long)z * bias_z : nullptr;
    float* Cz = C ? C + (long)z * c_z : nullptr;
#pragma unroll
    for (int nf = 0; nf < 2; nf++) {
        int row = m0 + wm * 16 + g;
        int col = n0 + wn * 16 + nf * 8 + tg * 2;
        float v0 = acc[nf][0], v1 = acc[nf][1];
        float v2 = acc[nf][2], v3 = acc[nf][3];
        if (bp) {
            float bb0 = __ldg(bp + col), bb1 = __ldg(bp + col + 1);
            v0 += bb0; v1 += bb1; v2 += bb0; v3 += bb1;
        }
        if (flags & FL_RELU) {
            v0 = fmaxf(v0, 0.f); v1 = fmaxf(v1, 0.f);
            v2 = fmaxf(v2, 0.f); v3 = fmaxf(v3, 0.f);
        }
        if (flags & FL_F32) {
            *(float2*)&Cz[(long)row * ldc + col] = make_float2(v0, v1);
            *(float2*)&Cz[(long)(row + 8) * ldc + col] = make_float2(v2, v3);
        }
        if (flags & FL_HILO) {
            bf16 h0 = __float2bfloat16(v0), h1 = __float2bfloat16(v1);
            bf16 h2 = __float2bfloat16(v2), h3 = __float2bfloat16(v3);
            __nv_bfloat162 ph0; ph0.x = h0; ph0.y = h1;
            __nv_bfloat162 ph1; ph1.x = h2; ph1.y = h3;
            __nv_bfloat162 pl0, pl1;
            pl0.x = __float2bfloat16(v0 - __bfloat162float(h0));
            pl0.y = __float2bfloat16(v1 - __bfloat162float(h1));
            pl1.x = __float2bfloat16(v2 - __bfloat162float(h2));
            pl1.y = __float2bfloat16(v3 - __bfloat162float(h3));
            *(__nv_bfloat162*)&Ch[(long)row * ldch + col] = ph0;
            *(__nv_bfloat162*)&Cl[(long)row * ldch + col] = pl0;
            *(__nv_bfloat162*)&Ch[(long)(row + 8) * ldch + col] = ph1;
            *(__nv_bfloat162*)&Cl[(long)(row + 8) * ldch + col] = pl1;
        }
    }
}

// ======================= LayerNorms =======================
__global__ void ln1_k(const float* __restrict__ in, const float* __restrict__ g,
                      const float* __restrict__ b, bf16* __restrict__ oh, bf16* __restrict__ ol)
{
    int row = blockIdx.x, t = threadIdx.x;   // 256 threads
    __shared__ float rbuf[256];
    long base = (long)row * DD;
    float v0 = in[base + t], v1 = in[base + t + 256];
    rbuf[t] = v0 + v1; __syncthreads();
    for (int s = 128; s > 0; s >>= 1) { if (t < s) rbuf[t] += rbuf[t + s]; __syncthreads(); }
    float mean = rbuf[0] * (1.0f / 512.0f);
    __syncthreads();
    float d0 = v0 - mean, d1 = v1 - mean;
    rbuf[t] = d0 * d0 + d1 * d1; __syncthreads();
    for (int s = 128; s > 0; s >>= 1) { if (t < s) rbuf[t] += rbuf[t + s]; __syncthreads(); }
    float rs = rsqrtf(rbuf[0] * (1.0f / 512.0f) + 1e-5f);
    float o0 = d0 * rs * g[t] + b[t];
    float o1 = d1 * rs * g[t + 256] + b[t + 256];
    bf16 h0 = __float2bfloat16(o0), h1 = __float2bfloat16(o1);
    oh[base + t] = h0;       ol[base + t]       = __float2bfloat16(o0 - __bfloat162float(h0));
    oh[base + t + 256] = h1; ol[base + t + 256] = __float2bfloat16(o1 - __bfloat162float(h1));
}

__global__ void ln2_k(const float* __restrict__ in, const float* __restrict__ add,
                      const float* __restrict__ g, const float* __restrict__ b,
                      float* __restrict__ out)
{
    int row = blockIdx.x, t = threadIdx.x;
    __shared__ float rbuf[256];
    long base = (long)row * DD;
    float v0 = in[base + t] + add[base + t];
    float v1 = in[base + t + 256] + add[base + t + 256];
    rbuf[t] = v0 + v1; __syncthreads();
    for (int s = 128; s > 0; s >>= 1) { if (t < s) rbuf[t] += rbuf[t + s]; __syncthreads(); }
    float mean = rbuf[0] * (1.0f / 512.0f);
    __syncthreads();
    float d0 = v0 - mean, d1 = v1 - mean;
    rbuf[t] = d0 * d0 + d1 * d1; __syncthreads();
    for (int s = 128; s > 0; s >>= 1) { if (t < s) rbuf[t] += rbuf[t + s]; __syncthreads(); }
    float rs = rsqrtf(rbuf[0] * (1.0f / 512.0f) + 1e-5f);
    out[base + t]       = d0 * rs * g[t]       + b[t];
    out[base + t + 256] = d1 * rs * g[t + 256] + b[t + 256];
}

// ======================= attention: scores+softmax, 16-row tiles =======================
__global__ void attn_scores_k(const float* __restrict__ q, const float* __restrict__ k,
                              float* __restrict__ attn)
{
    int it = blockIdx.x, h = blockIdx.y, b = blockIdx.z;  // 256 thr
    int t = threadIdx.x;
    int i0 = it * 16;
    __shared__ float ks[SS][DH + 1];
    __shared__ float qs[16][DH + 1];
    __shared__ float P[16][SS];
    const float* kbase = k + (long)b * SS * DD + h * DH;
    const float* qbase = q + (long)b * SS * DD + h * DH;
    for (int idx = t; idx < SS * DH; idx += 256) {
        int j = idx >> 6, d = idx & 63;
        ks[j][d] = kbase[(long)j * DD + d];
    }
    for (int idx = t; idx < 16 * DH; idx += 256) {
        int r = idx >> 6, d = idx & 63;
        qs[r][d] = qbase[(long)(i0 + r) * DD + d];
    }
    __syncthreads();
    {
        int j = t & 127, grp = t >> 7;
#pragma unroll
        for (int r = 0; r < 8; r++) {
            int i = grp * 8 + r;
            float acc = 0.f;
#pragma unroll
            for (int d = 0; d < DH; d++) acc += qs[i][d] * ks[j][d];
            P[i][j] = acc * 0.125f;
        }
    }
    __syncthreads();
    {
        int w = t >> 5, ln = t & 31;
        long obase = (((long)(b * HH + h) * SS) + i0) * SS;
#pragma unroll
        for (int rr = 0; rr < 2; rr++) {
            int i = w * 2 + rr;
            float m = -1e30f;
#pragma unroll
            for (int c = 0; c < 4; c++) m = fmaxf(m, P[i][ln + c * 32]);
#pragma unroll
            for (int o = 16; o > 0; o >>= 1) m = fmaxf(m, __shfl_xor_sync(0xffffffffu, m, o));
            float s = 0.f, e[4];
#pragma unroll
            for (int c = 0; c < 4; c++) { e[c] = expf(P[i][ln + c * 32] - m); s += e[c]; }
#pragma unroll
            for (int o = 16; o > 0; o >>= 1) s += __shfl_xor_sync(0xffffffffu, s, o);
            float inv = 1.0f / s;
#pragma unroll
            for (int c = 0; c < 4; c++) attn[obase + (long)i * SS + ln + c * 32] = e[c] * inv;
        }
    }
}

// ======== edges: head-mean + threshold + compact edge list (replaces am_k + tiles) ========
__global__ void edges_k(const float* __restrict__ attn, int* __restrict__ rel,
                        int2* __restrict__ elist, int* __restrict__ ecnt)
{
    int bu = blockIdx.x;                 // b*S + u
    int b = bu >> 7, u = bu & 127, v = threadIdx.x;  // 128 thr
    float s = 0.f;
#pragma unroll
    for (int h = 0; h < HH; h++)
        s += attn[(((long)(b * HH + h) * SS) + u) * SS + v];
    s *= 0.125f;
    long ridx = (long)bu * SS + v;
    rel[ridx] = 0;
    if ((s > THRESH) && (u != v)) {
        int p = atomicAdd(ecnt, 1);
        if (p < MAXE) elist[p] = make_int2(bu, v);
    }
}

// ======== pair classifier on compacted edges: one warp per edge ========
__global__ void __launch_bounds__(256)
pair2_k(const float* __restrict__ ap, const float* __restrict__ bp,
        const float* __restrict__ rc_b1, const float* __restrict__ rc_w2,
        const float* __restrict__ rc_b2,
        const int2* __restrict__ elist, const int* __restrict__ ecnt,
        int* __restrict__ rel)
{
    int total = *ecnt; if (total > MAXE) total = MAXE;
    int wg = blockIdx.x * 8 + (threadIdx.x >> 5);
    int nw = gridDim.x * 8;
    int lane = threadIdx.x & 31;

    for (int e = wg; e < total; e += nw) {
        int2 ed = elist[e];
        int bu = ed.x, v = ed.y;
        int bb = bu >> 7;
        const float* A = ap + (long)bu * DD;
        const float* B = bp + ((long)(bb * SS + v)) * DD;
        float acc[RR];
#pragma unroll
        for (int r = 0; r < RR; r++) acc[r] = 0.f;
#pragma unroll
        for (int c = 0; c < 4; c++) {
            int d = c * 128 + lane * 4;
            float4 a4 = *(const float4*)(A + d);
            float4 b4 = *(const float4*)(B + d);
            float4 c4 = *(const float4*)(rc_b1 + d);
            float hs[4];
            hs[0] = fmaxf(a4.x + b4.x + c4.x, 0.f);
            hs[1] = fmaxf(a4.y + b4.y + c4.y, 0.f);
            hs[2] = fmaxf(a4.z + b4.z + c4.z, 0.f);
            hs[3] = fmaxf(a4.w + b4.w + c4.w, 0.f);
#pragma unroll
            for (int j = 0; j < 4; j++) {
                float4 w0 = *(const float4*)(rc_w2 + (long)(d + j) * RR);
                float4 w1 = *(const float4*)(rc_w2 + (long)(d + j) * RR + 4);
                acc[0] += hs[j] * w0.x; acc[1] += hs[j] * w0.y;
                acc[2] += hs[j] * w0.z; acc[3] += hs[j] * w0.w;
                acc[4] += hs[j] * w1.x; acc[5] += hs[j] * w1.y;
                acc[6] += hs[j] * w1.z; acc[7] += hs[j] * w1.w;
            }
        }
#pragma unroll
        for (int r = 0; r < RR; r++)
#pragma unroll
            for (int o = 16; o > 0; o >>= 1)
                acc[r] += __shfl_xor_sync(0xffffffffu, acc[r], o);
        if (lane == 0) {
            int pred = 0; float best = acc[0] + rc_b2[0];
#pragma unroll
            for (int r = 1; r < RR; r++) {
                float lg = acc[r] + rc_b2[r];
                if (lg > best) { best = lg; pred = r; }
            }
            if (pred != 0) rel[(long)bu * SS + v] = pred;
        }
    }
}

// ======================= attention: ctx = P @ V, 16-row tiles =======================
__global__ void attn_ctx_k(const float* __restrict__ attn, const float* __restrict__ v,
                           bf16* __restrict__ ch, bf16* __restrict__ cl)
{
    int it = blockIdx.x, h = blockIdx.y, b = blockIdx.z;  // 256 thr
    int t = threadIdx.x;
    int i0 = it * 16;
    int d = t & 63, ig = t >> 6;
    __shared__ float vs[SS][DH + 1];
    __shared__ float at[16][SS];
    const float* vbase = v + (long)b * SS * DD + h * DH;
    for (int idx = t; idx < SS * DH; idx += 256) {
        int j = idx >> 6, dd = idx & 63;
        vs[j][dd] = vbase[(long)j * DD + dd];
    }
    long arow = (((long)(b * HH + h) * SS) + i0) * SS;
    for (int idx = t; idx < 16 * SS; idx += 256)
        at[idx >> 7][idx & 127] = attn[arow + (long)(idx >> 7) * SS + (idx & 127)];
    __syncthreads();

    float acc[4] = {0.f, 0.f, 0.f, 0.f};
#pragma unroll
    for (int jh = 0; jh < 2; jh++) {
        float vreg[64];
#pragma unroll
        for (int jj = 0; jj < 64; jj++) vreg[jj] = vs[jh * 64 + jj][d];
#pragma unroll
        for (int r = 0; r < 4; r++) {
            int i = ig + 4 * r;
            float a = acc[r];
#pragma unroll
            for (int jj = 0; jj < 64; jj++) a += at[i][jh * 64 + jj] * vreg[jj];
            acc[r] = a;
        }
    }
#pragma unroll
    for (int r = 0; r < 4; r++) {
        int i = ig + 4 * r;
        long o = (long)(b * SS + i0 + i) * DD + h * DH + d;
        bf16 hh = __float2bfloat16(acc[r]);
        ch[o] = hh; cl[o] = __float2bfloat16(acc[r] - __bfloat162float(hh));
    }
}

// ======================= nu: reduce split-K partials + bias + hi/lo =======================
__global__ void conv_nu_k(const float* __restrict__ P, const float* __restrict__ b2,
                          float* __restrict__ nu, bf16* __restrict__ H, bf16* __restrict__ L)
{
    int row = blockIdx.x, t = threadIdx.x;  // 256
    for (int c = t; c < DD; c += 256) {
        long i = (long)row * DD + c;
        float v = b2[c] + P[i] + P[UU + i] + P[2L*UU + i] + P[3L*UU + i];
        nu[i] = v;
        bf16 h = __float2bfloat16(v);
        H[i] = h; L[i] = __float2bfloat16(v - __bfloat162float(h));
    }
}

// ======================= edge aggregation (trans slabs [r][n][d]) =======================
__global__ void agg_k(const int* __restrict__ rel, const float* __restrict__ trans,
                      const float* __restrict__ nu, bf16* __restrict__ rh, bf16* __restrict__ rl)
{
    int bv = blockIdx.x;                 // b*S + v
    int b = bv >> 7, v = bv & 127, t = threadIdx.x;   // 256
    __shared__ int sr[SS];
    if (t < SS) sr[t] = rel[((long)b * SS + t) * SS + v];
    __syncthreads();
    float a0 = 0.f, a1 = 0.f;
    for (int u = 0; u < SS; u++) {
        int r = sr[u];
        if (r) {
            const float* tr = trans + (long)r * UU + (long)(b * SS + u) * DD;
            a0 += tr[t]; a1 += tr[t + 256];
        }
    }
    long row = (long)bv * DD;
    float v0 = nu[row + t] + a0;
    float v1 = nu[row + t + 256] + a1;
    bf16 h0 = __float2bfloat16(v0), h1 = __float2bfloat16(v1);
    rh[row + t] = h0;       rl[row + t]       = __float2bfloat16(v0 - __bfloat162float(h0));
    rh[row + t + 256] = h1; rl[row + t + 256] = __float2bfloat16(v1 - __bfloat162float(h1));
}

// ======================= launch =======================
extern "C" void kernel_launch(void* const* d_in, const int* in_sizes, int n_in,
                              void* d_out, int out_size)
{
    const float* x     = (const float*)d_in[0];
    const float* ln1_g = (const float*)d_in[1];
    const float* ln1_b = (const float*)d_in[2];
    const float* wq    = (const float*)d_in[3];
    const float* bq    = (const float*)d_in[4];
    const float* wk    = (const float*)d_in[5];
    const float* bk    = (const float*)d_in[6];
    const float* wv    = (const float*)d_in[7];
    const float* bvv   = (const float*)d_in[8];
    const float* wo    = (const float*)d_in[9];
    const float* bo    = (const float*)d_in[10];
    const float* w1    = (const float*)d_in[11];
    const float* b1    = (const float*)d_in[12];
    const float* w2    = (const float*)d_in[13];
    const float* b2    = (const float*)d_in[14];
    const float* rc_w1 = (const float*)d_in[15];
    const float* rc_b1 = (const float*)d_in[16];
    const float* rc_w2 = (const float*)d_in[17];
    const float* rc_b2 = (const float*)d_in[18];
    const float* kg_w  = (const float*)d_in[19];
    const float* s2n_w = (const float*)d_in[20];
    const float* s2n_b = (const float*)d_in[21];
    const float* ln2_g = (const float*)d_in[22];
    const float* ln2_b = (const float*)d_in[23];
    float* out = (float*)d_out;

    bf16 *wTh, *wTl, *xnh, *xnl, *ctxh, *ctxl, *aoh, *aol, *hidh, *hidl, *nuh, *nul, *rsh, *rsl;
    float *b3, *qkv, *attn, *nupart, *nu, *abt, *nr;
    int *rel, *ecnt;
    int2 *elist;
    cudaGetSymbolAddress((void**)&wTh, g_wTh);   cudaGetSymbolAddress((void**)&wTl, g_wTl);
    cudaGetSymbolAddress((void**)&b3, g_b3);
    cudaGetSymbolAddress((void**)&xnh, g_xnh);   cudaGetSymbolAddress((void**)&xnl, g_xnl);
    cudaGetSymbolAddress((void**)&qkv, g_qkv);
    cudaGetSymbolAddress((void**)&attn, g_attn);
    cudaGetSymbolAddress((void**)&ctxh, g_ctxh); cudaGetSymbolAddress((void**)&ctxl, g_ctxl);
    cudaGetSymbolAddress((void**)&aoh, g_aoh);   cudaGetSymbolAddress((void**)&aol, g_aol);
    cudaGetSymbolAddress((void**)&hidh, g_hidh); cudaGetSymbolAddress((void**)&hidl, g_hidl);
    cudaGetSymbolAddress((void**)&nupart, g_nupart);
    cudaGetSymbolAddress((void**)&nu, g_nu);
    cudaGetSymbolAddress((void**)&nuh, g_nuh);   cudaGetSymbolAddress((void**)&nul, g_nul);
    cudaGetSymbolAddress((void**)&abt, g_abt);
    cudaGetSymbolAddress((void**)&rel, g_rel);
    cudaGetSymbolAddress((void**)&rsh, g_rsh);   cudaGetSymbolAddress((void**)&rsl, g_rsl);
    cudaGetSymbolAddress((void**)&nr, g_nr);
    cudaGetSymbolAddress((void**)&elist, g_elist);
    cudaGetSymbolAddress((void**)&ecnt, g_ecnt);

    cudaFuncSetAttribute(gemm_mma, cudaFuncAttributeMaxDynamicSharedMemorySize, GSM);
    cudaFuncSetAttribute(gemm_mma, cudaFuncAttributePreferredSharedMemoryCarveout, 100);
    cudaFuncSetAttribute(gemm_sm, cudaFuncAttributeMaxDynamicSharedMemorySize, GSM2);
    cudaFuncSetAttribute(gemm_sm, cudaFuncAttributePreferredSharedMemoryCarveout, 100);

    // weight prep (also zeroes g_ecnt)
    setup_k<<<1, 512>>>(wq, wk, wv, wo, w1, w2, rc_w1, kg_w, s2n_w, bq, bk, bvv);
    wconv_k<<<dim3(16, 16, 23), dim3(32, 8)>>>();

    // ln1 -> xn (hi/lo)
    ln1_k<<<BS, 256>>>(x, ln1_g, ln1_b, xnh, xnl);

    // QKV (z=3), fp32 out — small tile for 384 CTAs
    gemm_sm<<<dim3(8, 16, 3), 256, GSM2>>>(xnh, xnl, DD, 0, wTh, wTl, UU, DD,
                                           b3, DD, qkv, UU, DD, nullptr, nullptr, 0,
                                           DD, FL_F32);
    // attention (16-row tiled) + compact edge extraction
    attn_scores_k<<<dim3(8, HH, BB), 256>>>(qkv, qkv + UU, attn);
    edges_k<<<BS, 128>>>(attn, rel, elist, ecnt);
    attn_ctx_k<<<dim3(8, HH, BB), 256>>>(attn, qkv + 2 * UU, ctxh, ctxl);

    // ao = ctx @ wo + bo  (hi/lo only) — small tile (grid-starved z=1)
    gemm_sm<<<dim3(8, 16, 1), 256, GSM2>>>(ctxh, ctxl, DD, 0, wTh + 3L*UU, wTl + 3L*UU, 0, DD,
                                           bo, 0, nullptr, 0, 0, aoh, aol, DD,
                                           DD, FL_HILO);
    // hid = relu(ao @ w1 + b1) (hi/lo only, N=2048) — big tile (B traffic)
    gemm_mma<<<dim3(32, 8, 1), 256, GSM>>>(aoh, aol, DD, 0, wTh + 4L*UU, wTl + 4L*UU, 0, DD,
                                           b1, 0, nullptr, 0, 0, hidh, hidl, FF,
                                           DD, FL_HILO | FL_RELU);
    // nu partials = hid @ w2  (split-K z=4 into 4 slabs)
    gemm_mma<<<dim3(8, 8, 4), 256, GSM>>>(hidh, hidl, FF, DD, wTh + 8L*UU, wTl + 8L*UU, DD, FF,
                                          nullptr, 0, nupart, UU, DD, nullptr, nullptr, 0,
                                          DD, FL_F32);
    conv_nu_k<<<BS, 256>>>(nupart, b2, nu, nuh, nul);

    // fused: a/b parts (z=0,1) + RGCN transforms (z=2..9) in one launch — big tile
    gemm_mma<<<dim3(8, 8, 10), 256, GSM>>>(nuh, nul, DD, 0, wTh + 12L*UU, wTl + 12L*UU, UU, DD,
                                           nullptr, 0, abt, UU, DD, nullptr, nullptr, 0,
                                           DD, FL_F32);
    // relation classifier on compacted edges only
    pair2_k<<<64, 256>>>(abt, abt + UU, rc_b1, rc_w2, rc_b2, elist, ecnt, rel);
    // aggregation (trans slabs start at abt + 2*UU)
    agg_k<<<BS, 256>>>(rel, abt + 2L*UU, nu, rsh, rsl);

    // s2n projection, fp32 — small tile (grid-starved z=1)
    gemm_sm<<<dim3(8, 16, 1), 256, GSM2>>>(rsh, rsl, DD, 0, wTh + 22L*UU, wTl + 22L*UU, 0, DD,
                                           s2n_b, 0, nr, 0, DD, nullptr, nullptr, 0,
                                           DD, FL_F32);
    // final residual LN
    ln2_k<<<BS, 256>>>(nr, x, ln2_g, ln2_b, out);
}

// round 13
// speedup vs baseline: 1.4155x; 1.0930x over previous
#include <cuda_runtime.h>
#include <cuda_bf16.h>
#include <cuda_fp16.h>
#include <math.h>
#include <stdint.h>

#define BB 4
#define SS 128
#define DD 512
#define HH 8
#define DH 64
#define FF 2048
#define RR 8
#define BS (BB*SS)          // 512
#define UU 262144           // 512*512
#define THRESH 0.1f
#define MAXE 8192

typedef __nv_bfloat16 bf16;

// ======================= helpers =======================
__device__ __forceinline__ uint32_t smem_u32(const void* p){
    uint32_t a;
    asm("{ .reg .u64 t; cvta.to.shared.u64 t, %1; cvt.u32.u64 %0, t; }" : "=r"(a) : "l"(p));
    return a;
}
__device__ __forceinline__ void ldsm4(uint32_t& r0, uint32_t& r1, uint32_t& r2, uint32_t& r3,
                                      uint32_t addr){
    asm volatile("ldmatrix.sync.aligned.m8n8.x4.shared.b16 {%0,%1,%2,%3}, [%4];"
                 : "=r"(r0), "=r"(r1), "=r"(r2), "=r"(r3) : "r"(addr));
}
__device__ __forceinline__ void mma16816(float* d, const uint32_t* a, const uint32_t* b){
    asm volatile("mma.sync.aligned.m16n8k16.row.col.f32.bf16.bf16.f32 "
                 "{%0,%1,%2,%3}, {%4,%5,%6,%7}, {%8,%9}, {%0,%1,%2,%3};"
                 : "+f"(d[0]), "+f"(d[1]), "+f"(d[2]), "+f"(d[3])
                 : "r"(a[0]), "r"(a[1]), "r"(a[2]), "r"(a[3]), "r"(b[0]), "r"(b[1]));
}
__device__ __forceinline__ void mma16816h(float* d, const uint32_t* a, const uint32_t* b){
    asm volatile("mma.sync.aligned.m16n8k16.row.col.f32.f16.f16.f32 "
                 "{%0,%1,%2,%3}, {%4,%5,%6,%7}, {%8,%9}, {%0,%1,%2,%3};"
                 : "+f"(d[0]), "+f"(d[1]), "+f"(d[2]), "+f"(d[3])
                 : "r"(a[0]), "r"(a[1]), "r"(a[2]), "r"(a[3]), "r"(b[0]), "r"(b[1]));
}
__device__ __forceinline__ void cpa16(uint32_t s, const void* g){
    asm volatile("cp.async.cg.shared.global [%0], [%1], 16;" :: "r"(s), "l"(g));
}
__device__ __forceinline__ void cpa_commit(){
    asm volatile("cp.async.commit_group;" ::: "memory");
}
template<int N> __device__ __forceinline__ void cpa_wait(){
    asm volatile("cp.async.wait_group %0;" :: "n"(N) : "memory");
}

// ======================= scratch (device globals) =======================
__device__ bf16  g_wTh[14*UU];          // bf16 hi weights (units 0..13)
__device__ bf16  g_wTl[14*UU];          // bf16 lo weights
__device__ __half g_wT16[9*UU];         // fp16 weights: kg relations 0..7 (units 0..7), s2n (unit 8)
__device__ float g_b3[3*DD];            // packed q/k/v biases
__device__ bf16  g_xnh[UU], g_xnl[UU];
__device__ float g_qkv[3*UU];
__device__ float g_attn[BB*HH*SS*SS];
__device__ bf16  g_ctxh[UU], g_ctxl[UU];
__device__ bf16  g_aoh[UU],  g_aol[UU];
__device__ bf16  g_hidh[BS*FF], g_hidl[BS*FF];
__device__ float g_nupart[4*UU];        // split-K partials for nu
__device__ float g_nu[UU];
__device__ bf16  g_nuh[UU], g_nul[UU];
__device__ __half g_nu16[UU];
__device__ float g_ab[2*UU];            // a/b parts
__device__ float g_trans[8*UU];         // RGCN transform slabs [r][n][d], r=1..7 used
__device__ int   g_rel[BB*SS*SS];
__device__ __half g_rs16[UU];           // reasoned, fp16
__device__ float g_nr[UU];
__device__ int2  g_elist[MAXE];
__device__ int   g_ecnt;

struct WUnit { const float* src; int ld; long dst; int dld; };
__device__ WUnit g_wu[23];

// ======================= setup: weight-unit table + packed biases =======================
__global__ void setup_k(const float* wq, const float* wk, const float* wv, const float* wo,
                        const float* w1, const float* w2, const float* rc, const float* kg,
                        const float* s2n, const float* bq, const float* bk, const float* bvv)
{
    int t = threadIdx.x;
    if (t < DD) { g_b3[t] = bq[t]; g_b3[DD+t] = bk[t]; g_b3[2*DD+t] = bvv[t]; }
    if (t == 0) {
        g_ecnt = 0;
        const float* qkv[3] = {wq, wk, wv};
        for (int u = 0; u < 3; u++) g_wu[u] = {qkv[u], DD, (long)u*UU, DD};
        g_wu[3] = {wo, DD, 3L*UU, DD};
        for (int u = 0; u < 4; u++)                       // w1 [512][2048] -> [2048][512]
            g_wu[4+u] = {w1 + u*DD, FF, 4L*UU + (long)u*UU, DD};
        for (int u = 0; u < 4; u++)                       // w2 [2048][512] -> [512][2048]
            g_wu[8+u] = {w2 + (long)u*UU, DD, 8L*UU + (long)u*DD, FF};
        for (int u = 0; u < 2; u++)
            g_wu[12+u] = {rc + (long)u*UU, DD, (12L+u)*UU, DD};
        for (int u = 0; u < 8; u++)                       // kg relations -> fp16 units 0..7
            g_wu[14+u] = {kg + (long)u*UU, DD, (long)u*UU, DD};
        g_wu[22] = {s2n, DD, 8L*UU, DD};                  // s2n -> fp16 unit 8
    }
}

// ============ weight transpose: bf16 hi/lo (units 0..13) or fp16 (units 14..22) ============
__global__ void wconv_k()
{
    __shared__ float tile[32][33];
    WUnit u = g_wu[blockIdx.z];
    int k0 = blockIdx.y * 32, n0 = blockIdx.x * 32;
    int tx = threadIdx.x, ty = threadIdx.y;        // (32, 8)
    int t = ty * 32 + tx;                          // 0..255
#pragma unroll
    for (int i = 0; i < 4; i++)
        tile[ty + 8*i][tx] = __ldg(u.src + (long)(k0 + ty + 8*i) * u.ld + n0 + tx);
    __syncthreads();
    bool f16 = blockIdx.z >= 14;
#pragma unroll
    for (int i = 0; i < 2; i++) {
        int p = t + i * 256;                       // pair index: n = p>>4, kp = p&15
        int n = p >> 4, kp = p & 15;
        float v0 = tile[2*kp    ][n];
        float v1 = tile[2*kp + 1][n];
        long off = u.dst + (long)(n0 + n) * u.dld + k0 + 2*kp;
        if (f16) {
            __half2 ph; ph.x = __float2half(v0); ph.y = __float2half(v1);
            *(__half2*)&g_wT16[off] = ph;
        } else {
            bf16 h0 = __float2bfloat16(v0), h1 = __float2bfloat16(v1);
            __nv_bfloat162 ph; ph.x = h0; ph.y = h1;
            __nv_bfloat162 pl;
            pl.x = __float2bfloat16(v0 - __bfloat162float(h0));
            pl.y = __float2bfloat16(v1 - __bfloat162float(h1));
            *(__nv_bfloat162*)&g_wTh[off] = ph;
            *(__nv_bfloat162*)&g_wTl[off] = pl;
        }
    }
}

// ======================= mma.sync bf16 3-pass GEMM (64x64 tile, 2-stage) =======================
#define FL_F32  1
#define FL_HILO 2
#define FL_RELU 4

#define TSTRIDE 144                      // smem row stride bytes (72 elements)
#define TILE_B  9216                     // 64 rows * 144 B
#define STAGE_B 36864                    // 4 tiles
#define GSM     73728                    // 2 stages

__global__ void __launch_bounds__(256, 3)
gemm_mma(const bf16* __restrict__ Ah, const bf16* __restrict__ Al, int lda, long a_z,
         const bf16* __restrict__ Bh, const bf16* __restrict__ Bl, long b_z, int ldb,
         const float* __restrict__ bias, int bias_z,
         float* __restrict__ C, long c_z, int ldc,
         bf16* __restrict__ Ch, bf16* __restrict__ Cl, int ldch,
         int K, int flags)
{
    extern __shared__ char sm[];
    uint32_t sb = smem_u32(sm);
    const int tid = threadIdx.x, lane = tid & 31, wid = tid >> 5;
    const int wm = wid >> 2, wn = wid & 3;               // warp grid 2 x 4
    const int m0 = blockIdx.y * 64, n0 = blockIdx.x * 64, z = blockIdx.z;
    const bf16* Ahp = Ah + (long)z * a_z;
    const bf16* Alp = Al + (long)z * a_z;
    const bf16* Bhp = Bh + (long)z * b_z;
    const bf16* Blp = Bl + (long)z * b_z;

    const int ld_r = tid >> 3, ld_c = (tid & 7) * 8;
    const uint32_t s_wr = (uint32_t)(ld_r * TSTRIDE + ld_c * 2);

    const int a_r = (lane & 7) + ((lane >> 3) & 1) * 8;
    const int a_c8 = (lane >> 4) * 8;
    const uint32_t aoff = (uint32_t)((wm * 32 + a_r) * TSTRIDE + a_c8 * 2);
    const int b_r = (lane & 7) + (lane >> 4) * 8;
    const int b_c8 = ((lane >> 3) & 1) * 8;
    const uint32_t boff = (uint32_t)((wn * 16 + b_r) * TSTRIDE + b_c8 * 2);

    float acc[2][2][4];
#pragma unroll
    for (int i = 0; i < 2; i++)
#pragma unroll
        for (int j = 0; j < 2; j++)
#pragma unroll
            for (int q = 0; q < 4; q++) acc[i][j][q] = 0.f;

    uint32_t fah[2][2][4], fal[2][2][4], fbh[2][2][2], fbl[2][2][2];

    const int nch = K >> 6;

    auto issue = [&](int kk, int st){
        uint32_t base = sb + st * STAGE_B + s_wr;
        const bf16* ga0 = Ahp + (long)(m0 + ld_r) * lda + kk + ld_c;
        const bf16* ga1 = Alp + (long)(m0 + ld_r) * lda + kk + ld_c;
        const bf16* gb0 = Bhp + (long)(n0 + ld_r) * ldb + kk + ld_c;
        const bf16* gb1 = Blp + (long)(n0 + ld_r) * ldb + kk + ld_c;
        cpa16(base,                         ga0);
        cpa16(base + 32 * TSTRIDE,          ga0 + 32 * lda);
        cpa16(base + TILE_B,                ga1);
        cpa16(base + TILE_B + 32 * TSTRIDE, ga1 + 32 * lda);
        cpa16(base + 2 * TILE_B,                gb0);
        cpa16(base + 2 * TILE_B + 32 * TSTRIDE, gb0 + 32 * ldb);
        cpa16(base + 3 * TILE_B,                gb1);
        cpa16(base + 3 * TILE_B + 32 * TSTRIDE, gb1 + 32 * ldb);
        cpa_commit();
    };

    issue(0, 0);
    for (int i = 0; i < nch; i++) {
        if (i + 1 < nch) { issue((i + 1) << 6, (i + 1) & 1); cpa_wait<1>(); }
        else             { cpa_wait<0>(); }
        __syncthreads();

        uint32_t st = sb + (i & 1) * STAGE_B;

        {
            ldsm4(fbh[0][0][0], fbh[0][0][1], fbh[0][1][0], fbh[0][1][1], st + 2*TILE_B + boff);
            ldsm4(fbl[0][0][0], fbl[0][0][1], fbl[0][1][0], fbl[0][1][1], st + 3*TILE_B + boff);
#pragma unroll
            for (int mf = 0; mf < 2; mf++)
                ldsm4(fah[0][mf][0], fah[0][mf][1], fah[0][mf][2], fah[0][mf][3],
                      st + aoff + mf * (16*TSTRIDE));
#pragma unroll
            for (int mf = 0; mf < 2; mf++)
                ldsm4(fal[0][mf][0], fal[0][mf][1], fal[0][mf][2], fal[0][mf][3],
                      st + TILE_B + aoff + mf * (16*TSTRIDE));
        }

#pragma unroll
        for (int ks = 0; ks < 4; ks++) {
            const int cur = ks & 1, nxt = cur ^ 1;
            if (ks < 3) {
                uint32_t kb = (ks + 1) * 32;
                ldsm4(fbh[nxt][0][0], fbh[nxt][0][1], fbh[nxt][1][0], fbh[nxt][1][1],
                      st + 2*TILE_B + boff + kb);
                ldsm4(fbl[nxt][0][0], fbl[nxt][0][1], fbl[nxt][1][0], fbl[nxt][1][1],
                      st + 3*TILE_B + boff + kb);
#pragma unroll
                for (int mf = 0; mf < 2; mf++)
                    ldsm4(fah[nxt][mf][0], fah[nxt][mf][1], fah[nxt][mf][2], fah[nxt][mf][3],
                          st + aoff + mf * (16*TSTRIDE) + kb);
#pragma unroll
                for (int mf = 0; mf < 2; mf++)
                    ldsm4(fal[nxt][mf][0], fal[nxt][mf][1], fal[nxt][mf][2], fal[nxt][mf][3],
                          st + TILE_B + aoff + mf * (16*TSTRIDE) + kb);
            }
#pragma unroll
            for (int mf = 0; mf < 2; mf++)
#pragma unroll
                for (int nf = 0; nf < 2; nf++) mma16816(acc[mf][nf], fah[cur][mf], fbh[cur][nf]);
#pragma unroll
            for (int mf = 0; mf < 2; mf++)
#pragma unroll
                for (int nf = 0; nf < 2; nf++) mma16816(acc[mf][nf], fah[cur][mf], fbl[cur][nf]);
#pragma unroll
            for (int mf = 0; mf < 2; mf++)
#pragma unroll
                for (int nf = 0; nf < 2; nf++) mma16816(acc[mf][nf], fal[cur][mf], fbh[cur][nf]);
        }
        __syncthreads();
    }

    const int g = lane >> 2, tg = lane & 3;
    const float* bp = bias ? bias + (long)z * bias_z : nullptr;
    float* Cz = C ? C + (long)z * c_z : nullptr;
#pragma unroll
    for (int mf = 0; mf < 2; mf++) {
#pragma unroll
        for (int nf = 0; nf < 2; nf++) {
            int row = m0 + wm * 32 + mf * 16 + g;
            int col = n0 + wn * 16 + nf * 8 + tg * 2;
            float v0 = acc[mf][nf][0], v1 = acc[mf][nf][1];
            float v2 = acc[mf][nf][2], v3 = acc[mf][nf][3];
            if (bp) {
                float bb0 = __ldg(bp + col), bb1 = __ldg(bp + col + 1);
                v0 += bb0; v1 += bb1; v2 += bb0; v3 += bb1;
            }
            if (flags & FL_RELU) {
                v0 = fmaxf(v0, 0.f); v1 = fmaxf(v1, 0.f);
                v2 = fmaxf(v2, 0.f); v3 = fmaxf(v3, 0.f);
            }
            if (flags & FL_F32) {
                *(float2*)&Cz[(long)row * ldc + col] = make_float2(v0, v1);
                *(float2*)&Cz[(long)(row + 8) * ldc + col] = make_float2(v2, v3);
            }
            if (flags & FL_HILO) {
                bf16 h0 = __float2bfloat16(v0), h1 = __float2bfloat16(v1);
                bf16 h2 = __float2bfloat16(v2), h3 = __float2bfloat16(v3);
                __nv_bfloat162 ph0; ph0.x = h0; ph0.y = h1;
                __nv_bfloat162 ph1; ph1.x = h2; ph1.y = h3;
                __nv_bfloat162 pl0, pl1;
                pl0.x = __float2bfloat16(v0 - __bfloat162float(h0));
                pl0.y = __float2bfloat16(v1 - __bfloat162float(h1));
                pl1.x = __float2bfloat16(v2 - __bfloat162float(h2));
                pl1.y = __float2bfloat16(v3 - __bfloat162float(h3));
                *(__nv_bfloat162*)&Ch[(long)row * ldch + col] = ph0;
                *(__nv_bfloat162*)&Cl[(long)row * ldch + col] = pl0;
                *(__nv_bfloat162*)&Ch[(long)(row + 8) * ldch + col] = ph1;
                *(__nv_bfloat162*)&Cl[(long)(row + 8) * ldch + col] = pl1;
            }
        }
    }
}

// ============ small-tile bf16 variant: 32x64 CTA tile ============
#define OA_H2 0
#define OA_L2 4608
#define OB_H2 9216
#define OB_L2 18432
#define STAGE2 27648
#define GSM2 55296

__global__ void __launch_bounds__(256, 4)
gemm_sm(const bf16* __restrict__ Ah, const bf16* __restrict__ Al, int lda, long a_z,
        const bf16* __restrict__ Bh, const bf16* __restrict__ Bl, long b_z, int ldb,
        const float* __restrict__ bias, int bias_z,
        float* __restrict__ C, long c_z, int ldc,
        bf16* __restrict__ Ch, bf16* __restrict__ Cl, int ldch,
        int K, int flags)
{
    extern __shared__ char sm[];
    uint32_t sb = smem_u32(sm);
    const int tid = threadIdx.x, lane = tid & 31, wid = tid >> 5;
    const int wm = wid >> 2, wn = wid & 3;
    const int m0 = blockIdx.y * 32, n0 = blockIdx.x * 64, z = blockIdx.z;
    const bf16* Ahp = Ah + (long)z * a_z;
    const bf16* Alp = Al + (long)z * a_z;
    const bf16* Bhp = Bh + (long)z * b_z;
    const bf16* Blp = Bl + (long)z * b_z;

    const int ld_r = tid >> 3, ld_c = (tid & 7) * 8;
    const uint32_t s_wr = (uint32_t)(ld_r * TSTRIDE + ld_c * 2);

    const int a_r = (lane & 7) + ((lane >> 3) & 1) * 8;
    const int a_c8 = (lane >> 4) * 8;
    const uint32_t aoff = (uint32_t)((wm * 16 + a_r) * TSTRIDE + a_c8 * 2);
    const int b_r = (lane & 7) + (lane >> 4) * 8;
    const int b_c8 = ((lane >> 3) & 1) * 8;
    const uint32_t boff = (uint32_t)((wn * 16 + b_r) * TSTRIDE + b_c8 * 2);

    float acc[2][4];
#pragma unroll
    for (int j = 0; j < 2; j++)
#pragma unroll
        for (int q = 0; q < 4; q++) acc[j][q] = 0.f;

    uint32_t fah[2][4], fal[2][4], fbh[2][2][2], fbl[2][2][2];

    const int nch = K >> 6;

    auto issue = [&](int kk, int st){
        uint32_t base = sb + st * STAGE2 + s_wr;
        const bf16* ga0 = Ahp + (long)(m0 + ld_r) * lda + kk + ld_c;
        const bf16* ga1 = Alp + (long)(m0 + ld_r) * lda + kk + ld_c;
        const bf16* gb0 = Bhp + (long)(n0 + ld_r) * ldb + kk + ld_c;
        const bf16* gb1 = Blp + (long)(n0 + ld_r) * ldb + kk + ld_c;
        cpa16(base + OA_H2, ga0);
        cpa16(base + OA_L2, ga1);
        cpa16(base + OB_H2,                gb0);
        cpa16(base + OB_H2 + 32 * TSTRIDE, gb0 + 32 * ldb);
        cpa16(base + OB_L2,                gb1);
        cpa16(base + OB_L2 + 32 * TSTRIDE, gb1 + 32 * ldb);
        cpa_commit();
    };

    issue(0, 0);
    for (int i = 0; i < nch; i++) {
        if (i + 1 < nch) { issue((i + 1) << 6, (i + 1) & 1); cpa_wait<1>(); }
        else             { cpa_wait<0>(); }
        __syncthreads();

        uint32_t st = sb + (i & 1) * STAGE2;

        ldsm4(fbh[0][0][0], fbh[0][0][1], fbh[0][1][0], fbh[0][1][1], st + OB_H2 + boff);
        ldsm4(fbl[0][0][0], fbl[0][0][1], fbl[0][1][0], fbl[0][1][1], st + OB_L2 + boff);
        ldsm4(fah[0][0], fah[0][1], fah[0][2], fah[0][3], st + OA_H2 + aoff);
        ldsm4(fal[0][0], fal[0][1], fal[0][2], fal[0][3], st + OA_L2 + aoff);

#pragma unroll
        for (int ks = 0; ks < 4; ks++) {
            const int cur = ks & 1, nxt = cur ^ 1;
            if (ks < 3) {
                uint32_t kb = (ks + 1) * 32;
                ldsm4(fbh[nxt][0][0], fbh[nxt][0][1], fbh[nxt][1][0], fbh[nxt][1][1],
                      st + OB_H2 + boff + kb);
                ldsm4(fbl[nxt][0][0], fbl[nxt][0][1], fbl[nxt][1][0], fbl[nxt][1][1],
                      st + OB_L2 + boff + kb);
                ldsm4(fah[nxt][0], fah[nxt][1], fah[nxt][2], fah[nxt][3],
                      st + OA_H2 + aoff + kb);
                ldsm4(fal[nxt][0], fal[nxt][1], fal[nxt][2], fal[nxt][3],
                      st + OA_L2 + aoff + kb);
            }
#pragma unroll
            for (int nf = 0; nf < 2; nf++) mma16816(acc[nf], fah[cur], fbh[cur][nf]);
#pragma unroll
            for (int nf = 0; nf < 2; nf++) mma16816(acc[nf], fah[cur], fbl[cur][nf]);
#pragma unroll
            for (int nf = 0; nf < 2; nf++) mma16816(acc[nf], fal[cur], fbh[cur][nf]);
        }
        __syncthreads();
    }

    const int g = lane >> 2, tg = lane & 3;
    const float* bp = bias ? bias + (long)z * bias_z : nullptr;
    float* Cz = C ? C + (long)z * c_z : nullptr;
#pragma unroll
    for (int nf = 0; nf < 2; nf++) {
        int row = m0 + wm * 16 + g;
        int col = n0 + wn * 16 + nf * 8 + tg * 2;
        float v0 = acc[nf][0], v1 = acc[nf][1];
        float v2 = acc[nf][2], v3 = acc[nf][3];
        if (bp) {
            float bb0 = __ldg(bp + col), bb1 = __ldg(bp + col + 1);
            v0 += bb0; v1 += bb1; v2 += bb0; v3 += bb1;
        }
        if (flags & FL_RELU) {
            v0 = fmaxf(v0, 0.f); v1 = fmaxf(v1, 0.f);
            v2 = fmaxf(v2, 0.f); v3 = fmaxf(v3, 0.f);
        }
        if (flags & FL_F32) {
            *(float2*)&Cz[(long)row * ldc + col] = make_float2(v0, v1);
            *(float2*)&Cz[(long)(row + 8) * ldc + col] = make_float2(v2, v3);
        }
        if (flags & FL_HILO) {
            bf16 h0 = __float2bfloat16(v0), h1 = __float2bfloat16(v1);
            bf16 h2 = __float2bfloat16(v2), h3 = __float2bfloat16(v3);
            __nv_bfloat162 ph0; ph0.x = h0; ph0.y = h1;
            __nv_bfloat162 ph1; ph1.x = h2; ph1.y = h3;
            __nv_bfloat162 pl0, pl1;
            pl0.x = __float2bfloat16(v0 - __bfloat162float(h0));
            pl0.y = __float2bfloat16(v1 - __bfloat162float(h1));
            pl1.x = __float2bfloat16(v2 - __bfloat162float(h2));
            pl1.y = __float2bfloat16(v3 - __bfloat162float(h3));
            *(__nv_bfloat162*)&Ch[(long)row * ldch + col] = ph0;
            *(__nv_bfloat162*)&Cl[(long)row * ldch + col] = pl0;
            *(__nv_bfloat162*)&Ch[(long)(row + 8) * ldch + col] = ph1;
            *(__nv_bfloat162*)&Cl[(long)(row + 8) * ldch + col] = pl1;
        }
    }
}

// ============ fp16 SINGLE-pass GEMM, 32x64 CTA tile (continuous-path GEMMs) ============
#define HOA 0
#define HOB 4608
#define HSTAGE 13824
#define GSMH 27648

__global__ void __launch_bounds__(256, 4)
gemm_h1(const __half* __restrict__ A, const __half* __restrict__ B, long b_z,
        const float* __restrict__ bias, float* __restrict__ C, long c_z, int K)
{
    extern __shared__ char sm[];
    uint32_t sb = smem_u32(sm);
    const int tid = threadIdx.x, lane = tid & 31, wid = tid >> 5;
    const int wm = wid >> 2, wn = wid & 3;
    const int m0 = blockIdx.y * 32, n0 = blockIdx.x * 64, z = blockIdx.z;
    const __half* Bp = B + (long)z * b_z;

    const int ld_r = tid >> 3, ld_c = (tid & 7) * 8;
    const uint32_t s_wr = (uint32_t)(ld_r * TSTRIDE + ld_c * 2);

    const int a_r = (lane & 7) + ((lane >> 3) & 1) * 8;
    const int a_c8 = (lane >> 4) * 8;
    const uint32_t aoff = (uint32_t)((wm * 16 + a_r) * TSTRIDE + a_c8 * 2);
    const int b_r = (lane & 7) + (lane >> 4) * 8;
    const int b_c8 = ((lane >> 3) & 1) * 8;
    const uint32_t boff = (uint32_t)((wn * 16 + b_r) * TSTRIDE + b_c8 * 2);

    float acc[2][4];
#pragma unroll
    for (int j = 0; j < 2; j++)
#pragma unroll
        for (int q = 0; q < 4; q++) acc[j][q] = 0.f;

    uint32_t fa[2][4], fb[2][2][2];

    const int nch = K >> 6;

    auto issue = [&](int kk, int st){
        uint32_t base = sb + st * HSTAGE + s_wr;
        cpa16(base + HOA, A + (long)(m0 + ld_r) * K + kk + ld_c);
        const __half* gb = Bp + (long)(n0 + ld_r) * K + kk + ld_c;
        cpa16(base + HOB,                gb);
        cpa16(base + HOB + 32 * TSTRIDE, gb + 32 * K);
        cpa_commit();
    };

    issue(0, 0);
    for (int i = 0; i < nch; i++) {
        if (i + 1 < nch) { issue((i + 1) << 6, (i + 1) & 1); cpa_wait<1>(); }
        else             { cpa_wait<0>(); }
        __syncthreads();

        uint32_t st = sb + (i & 1) * HSTAGE;

        ldsm4(fb[0][0][0], fb[0][0][1], fb[0][1][0], fb[0][1][1], st + HOB + boff);
        ldsm4(fa[0][0], fa[0][1], fa[0][2], fa[0][3], st + HOA + aoff);

#pragma unroll
        for (int ks = 0; ks < 4; ks++) {
            const int cur = ks & 1, nxt = cur ^ 1;
            if (ks < 3) {
                uint32_t kb = (ks + 1) * 32;
                ldsm4(fb[nxt][0][0], fb[nxt][0][1], fb[nxt][1][0], fb[nxt][1][1],
                      st + HOB + boff + kb);
                ldsm4(fa[nxt][0], fa[nxt][1], fa[nxt][2], fa[nxt][3],
                      st + HOA + aoff + kb);
            }
#pragma unroll
            for (int nf = 0; nf < 2; nf++) mma16816h(acc[nf], fa[cur], fb[cur][nf]);
        }
        __syncthreads();
    }

    const int g = lane >> 2, tg = lane & 3;
    float* Cz = C + (long)z * c_z;
#pragma unroll
    for (int nf = 0; nf < 2; nf++) {
        int row = m0 + wm * 16 + g;
        int col = n0 + wn * 16 + nf * 8 + tg * 2;
        float v0 = acc[nf][0], v1 = acc[nf][1];
        float v2 = acc[nf][2], v3 = acc[nf][3];
        if (bias) {
            float bb0 = __ldg(bias + col), bb1 = __ldg(bias + col + 1);
            v0 += bb0; v1 += bb1; v2 += bb0; v3 += bb1;
        }
        *(float2*)&Cz[(long)row * DD + col] = make_float2(v0, v1);
        *(float2*)&Cz[(long)(row + 8) * DD + col] = make_float2(v2, v3);
    }
}

// ======================= LayerNorms =======================
__global__ void ln1_k(const float* __restrict__ in, const float* __restrict__ g,
                      const float* __restrict__ b, bf16* __restrict__ oh, bf16* __restrict__ ol)
{
    int row = blockIdx.x, t = threadIdx.x;   // 256 threads
    __shared__ float rbuf[256];
    long base = (long)row * DD;
    float v0 = in[base + t], v1 = in[base + t + 256];
    rbuf[t] = v0 + v1; __syncthreads();
    for (int s = 128; s > 0; s >>= 1) { if (t < s) rbuf[t] += rbuf[t + s]; __syncthreads(); }
    float mean = rbuf[0] * (1.0f / 512.0f);
    __syncthreads();
    float d0 = v0 - mean, d1 = v1 - mean;
    rbuf[t] = d0 * d0 + d1 * d1; __syncthreads();
    for (int s = 128; s > 0; s >>= 1) { if (t < s) rbuf[t] += rbuf[t + s]; __syncthreads(); }
    float rs = rsqrtf(rbuf[0] * (1.0f / 512.0f) + 1e-5f);
    float o0 = d0 * rs * g[t] + b[t];
    float o1 = d1 * rs * g[t + 256] + b[t + 256];
    bf16 h0 = __float2bfloat16(o0), h1 = __float2bfloat16(o1);
    oh[base + t] = h0;       ol[base + t]       = __float2bfloat16(o0 - __bfloat162float(h0));
    oh[base + t + 256] = h1; ol[base + t + 256] = __float2bfloat16(o1 - __bfloat162float(h1));
}

__global__ void ln2_k(const float* __restrict__ in, const float* __restrict__ add,
                      const float* __restrict__ g, const float* __restrict__ b,
                      float* __restrict__ out)
{
    int row = blockIdx.x, t = threadIdx.x;
    __shared__ float rbuf[256];
    long base = (long)row * DD;
    float v0 = in[base + t] + add[base + t];
    float v1 = in[base + t + 256] + add[base + t + 256];
    rbuf[t] = v0 + v1; __syncthreads();
    for (int s = 128; s > 0; s >>= 1) { if (t < s) rbuf[t] += rbuf[t + s]; __syncthreads(); }
    float mean = rbuf[0] * (1.0f / 512.0f);
    __syncthreads();
    float d0 = v0 - mean, d1 = v1 - mean;
    rbuf[t] = d0 * d0 + d1 * d1; __syncthreads();
    for (int s = 128; s > 0; s >>= 1) { if (t < s) rbuf[t] += rbuf[t + s]; __syncthreads(); }
    float rs = rsqrtf(rbuf[0] * (1.0f / 512.0f) + 1e-5f);
    out[base + t]       = d0 * rs * g[t]       + b[t];
    out[base + t + 256] = d1 * rs * g[t + 256] + b[t + 256];
}

// ======================= attention: scores+softmax, 16-row tiles =======================
__global__ void attn_scores_k(const float* __restrict__ q, const float* __restrict__ k,
                              float* __restrict__ attn)
{
    int it = blockIdx.x, h = blockIdx.y, b = blockIdx.z;  // 256 thr
    int t = threadIdx.x;
    int i0 = it * 16;
    __shared__ float ks[SS][DH + 1];
    __shared__ float qs[16][DH + 1];
    __shared__ float P[16][SS];
    const float* kbase = k + (long)b * SS * DD + h * DH;
    const float* qbase = q + (long)b * SS * DD + h * DH;
    for (int idx = t; idx < SS * DH; idx += 256) {
        int j = idx >> 6, d = idx & 63;
        ks[j][d] = kbase[(long)j * DD + d];
    }
    for (int idx = t; idx < 16 * DH; idx += 256) {
        int r = idx >> 6, d = idx & 63;
        qs[r][d] = qbase[(long)(i0 + r) * DD + d];
    }
    __syncthreads();
    {
        int j = t & 127, grp = t >> 7;
#pragma unroll
        for (int r = 0; r < 8; r++) {
            int i = grp * 8 + r;
            float acc = 0.f;
#pragma unroll
            for (int d = 0; d < DH; d++) acc += qs[i][d] * ks[j][d];
            P[i][j] = acc * 0.125f;
        }
    }
    __syncthreads();
    {
        int w = t >> 5, ln = t & 31;
        long obase = (((long)(b * HH + h) * SS) + i0) * SS;
#pragma unroll
        for (int rr = 0; rr < 2; rr++) {
            int i = w * 2 + rr;
            float m = -1e30f;
#pragma unroll
            for (int c = 0; c < 4; c++) m = fmaxf(m, P[i][ln + c * 32]);
#pragma unroll
            for (int o = 16; o > 0; o >>= 1) m = fmaxf(m, __shfl_xor_sync(0xffffffffu, m, o));
            float s = 0.f, e[4];
#pragma unroll
            for (int c = 0; c < 4; c++) { e[c] = expf(P[i][ln + c * 32] - m); s += e[c]; }
#pragma unroll
            for (int o = 16; o > 0; o >>= 1) s += __shfl_xor_sync(0xffffffffu, s, o);
            float inv = 1.0f / s;
#pragma unroll
            for (int c = 0; c < 4; c++) attn[obase + (long)i * SS + ln + c * 32] = e[c] * inv;
        }
    }
}

// ======== edges: head-mean + threshold + compact edge list ========
__global__ void edges_k(const float* __restrict__ attn, int* __restrict__ rel,
                        int2* __restrict__ elist, int* __restrict__ ecnt)
{
    int bu = blockIdx.x;                 // b*S + u
    int b = bu >> 7, u = bu & 127, v = threadIdx.x;  // 128 thr
    float s = 0.f;
#pragma unroll
    for (int h = 0; h < HH; h++)
        s += attn[(((long)(b * HH + h) * SS) + u) * SS + v];
    s *= 0.125f;
    long ridx = (long)bu * SS + v;
    rel[ridx] = 0;
    if ((s > THRESH) && (u != v)) {
        int p = atomicAdd(ecnt, 1);
        if (p < MAXE) elist[p] = make_int2(bu, v);
    }
}

// ======== pair classifier on compacted edges: one warp per edge ========
__global__ void __launch_bounds__(256)
pair2_k(const float* __restrict__ ap, const float* __restrict__ bp,
        const float* __restrict__ rc_b1, const float* __restrict__ rc_w2,
        const float* __restrict__ rc_b2,
        const int2* __restrict__ elist, const int* __restrict__ ecnt,
        int* __restrict__ rel)
{
    int total = *ecnt; if (total > MAXE) total = MAXE;
    int wg = blockIdx.x * 8 + (threadIdx.x >> 5);
    int nw = gridDim.x * 8;
    int lane = threadIdx.x & 31;

    for (int e = wg; e < total; e += nw) {
        int2 ed = elist[e];
        int bu = ed.x, v = ed.y;
        int bb = bu >> 7;
        const float* A = ap + (long)bu * DD;
        const float* B = bp + ((long)(bb * SS + v)) * DD;
        float acc[RR];
#pragma unroll
        for (int r = 0; r < RR; r++) acc[r] = 0.f;
#pragma unroll
        for (int c = 0; c < 4; c++) {
            int d = c * 128 + lane * 4;
            float4 a4 = *(const float4*)(A + d);
            float4 b4 = *(const float4*)(B + d);
            float4 c4 = *(const float4*)(rc_b1 + d);
            float hs[4];
            hs[0] = fmaxf(a4.x + b4.x + c4.x, 0.f);
            hs[1] = fmaxf(a4.y + b4.y + c4.y, 0.f);
            hs[2] = fmaxf(a4.z + b4.z + c4.z, 0.f);
            hs[3] = fmaxf(a4.w + b4.w + c4.w, 0.f);
#pragma unroll
            for (int j = 0; j < 4; j++) {
                float4 w0 = *(const float4*)(rc_w2 + (long)(d + j) * RR);
                float4 w1 = *(const float4*)(rc_w2 + (long)(d + j) * RR + 4);
                acc[0] += hs[j] * w0.x; acc[1] += hs[j] * w0.y;
                acc[2] += hs[j] * w0.z; acc[3] += hs[j] * w0.w;
                acc[4] += hs[j] * w1.x; acc[5] += hs[j] * w1.y;
                acc[6] += hs[j] * w1.z; acc[7] += hs[j] * w1.w;
            }
        }
#pragma unroll
        for (int r = 0; r < RR; r++)
#pragma unroll
            for (int o = 16; o > 0; o >>= 1)
                acc[r] += __shfl_xor_sync(0xffffffffu, acc[r], o);
        if (lane == 0) {
            int pred = 0; float best = acc[0] + rc_b2[0];
#pragma unroll
            for (int r = 1; r < RR; r++) {
                float lg = acc[r] + rc_b2[r];
                if (lg > best) { best = lg; pred = r; }
            }
            if (pred != 0) rel[(long)bu * SS + v] = pred;
        }
    }
}

// ======================= attention: ctx = P @ V, 16-row tiles =======================
__global__ void attn_ctx_k(const float* __restrict__ attn, const float* __restrict__ v,
                           bf16* __restrict__ ch, bf16* __restrict__ cl)
{
    int it = blockIdx.x, h = blockIdx.y, b = blockIdx.z;  // 256 thr
    int t = threadIdx.x;
    int i0 = it * 16;
    int d = t & 63, ig = t >> 6;
    __shared__ float vs[SS][DH + 1];
    __shared__ float at[16][SS];
    const float* vbase = v + (long)b * SS * DD + h * DH;
    for (int idx = t; idx < SS * DH; idx += 256) {
        int j = idx >> 6, dd = idx & 63;
        vs[j][dd] = vbase[(long)j * DD + dd];
    }
    long arow = (((long)(b * HH + h) * SS) + i0) * SS;
    for (int idx = t; idx < 16 * SS; idx += 256)
        at[idx >> 7][idx & 127] = attn[arow + (long)(idx >> 7) * SS + (idx & 127)];
    __syncthreads();

    float acc[4] = {0.f, 0.f, 0.f, 0.f};
#pragma unroll
    for (int jh = 0; jh < 2; jh++) {
        float vreg[64];
#pragma unroll
        for (int jj = 0; jj < 64; jj++) vreg[jj] = vs[jh * 64 + jj][d];
#pragma unroll
        for (int r = 0; r < 4; r++) {
            int i = ig + 4 * r;
            float a = acc[r];
#pragma unroll
            for (int jj = 0; jj < 64; jj++) a += at[i][jh * 64 + jj] * vreg[jj];
            acc[r] = a;
        }
    }
#pragma unroll
    for (int r = 0; r < 4; r++) {
        int i = ig + 4 * r;
        long o = (long)(b * SS + i0 + i) * DD + h * DH + d;
        bf16 hh = __float2bfloat16(acc[r]);
        ch[o] = hh; cl[o] = __float2bfloat16(acc[r] - __bfloat162float(hh));
    }
}

// ============= nu: reduce split-K partials + bias + bf16 hi/lo + fp16 =============
__global__ void conv_nu_k(const float* __restrict__ P, const float* __restrict__ b2,
                          float* __restrict__ nu, bf16* __restrict__ H, bf16* __restrict__ L,
                          __half* __restrict__ N16)
{
    int row = blockIdx.x, t = threadIdx.x;  // 256
    for (int c = t; c < DD; c += 256) {
        long i = (long)row * DD + c;
        float v = b2[c] + P[i] + P[UU + i] + P[2L*UU + i] + P[3L*UU + i];
        nu[i] = v;
        bf16 h = __float2bfloat16(v);
        H[i] = h; L[i] = __float2bfloat16(v - __bfloat162float(h));
        N16[i] = __float2half(v);
    }
}

// ======================= edge aggregation (writes reasoned fp16) =======================
__global__ void agg_k(const int* __restrict__ rel, const float* __restrict__ trans,
                      const float* __restrict__ nu, __half* __restrict__ r16)
{
    int bv = blockIdx.x;                 // b*S + v
    int b = bv >> 7, v = bv & 127, t = threadIdx.x;   // 256
    __shared__ int sr[SS];
    if (t < SS) sr[t] = rel[((long)b * SS + t) * SS + v];
    __syncthreads();
    float a0 = 0.f, a1 = 0.f;
    for (int u = 0; u < SS; u++) {
        int r = sr[u];
        if (r) {
            const float* tr = trans + (long)r * UU + (long)(b * SS + u) * DD;
            a0 += tr[t]; a1 += tr[t + 256];
        }
    }
    long row = (long)bv * DD;
    r16[row + t]       = __float2half(nu[row + t] + a0);
    r16[row + t + 256] = __float2half(nu[row + t + 256] + a1);
}

// ======================= launch =======================
extern "C" void kernel_launch(void* const* d_in, const int* in_sizes, int n_in,
                              void* d_out, int out_size)
{
    const float* x     = (const float*)d_in[0];
    const float* ln1_g = (const float*)d_in[1];
    const float* ln1_b = (const float*)d_in[2];
    const float* wq    = (const float*)d_in[3];
    const float* bq    = (const float*)d_in[4];
    const float* wk    = (const float*)d_in[5];
    const float* bk    = (const float*)d_in[6];
    const float* wv    = (const float*)d_in[7];
    const float* bvv   = (const float*)d_in[8];
    const float* wo    = (const float*)d_in[9];
    const float* bo    = (const float*)d_in[10];
    const float* w1    = (const float*)d_in[11];
    const float* b1    = (const float*)d_in[12];
    const float* w2    = (const float*)d_in[13];
    const float* b2    = (const float*)d_in[14];
    const float* rc_w1 = (const float*)d_in[15];
    const float* rc_b1 = (const float*)d_in[16];
    const float* rc_w2 = (const float*)d_in[17];
    const float* rc_b2 = (const float*)d_in[18];
    const float* kg_w  = (const float*)d_in[19];
    const float* s2n_w = (const float*)d_in[20];
    const float* s2n_b = (const float*)d_in[21];
    const float* ln2_g = (const float*)d_in[22];
    const float* ln2_b = (const float*)d_in[23];
    float* out = (float*)d_out;

    bf16 *wTh, *wTl, *xnh, *xnl, *ctxh, *ctxl, *aoh, *aol, *hidh, *hidl, *nuh, *nul;
    __half *wT16, *nu16, *rs16;
    float *b3, *qkv, *attn, *nupart, *nu, *ab, *trans, *nr;
    int *rel, *ecnt;
    int2 *elist;
    cudaGetSymbolAddress((void**)&wTh, g_wTh);   cudaGetSymbolAddress((void**)&wTl, g_wTl);
    cudaGetSymbolAddress((void**)&wT16, g_wT16);
    cudaGetSymbolAddress((void**)&b3, g_b3);
    cudaGetSymbolAddress((void**)&xnh, g_xnh);   cudaGetSymbolAddress((void**)&xnl, g_xnl);
    cudaGetSymbolAddress((void**)&qkv, g_qkv);
    cudaGetSymbolAddress((void**)&attn, g_attn);
    cudaGetSymbolAddress((void**)&ctxh, g_ctxh); cudaGetSymbolAddress((void**)&ctxl, g_ctxl);
    cudaGetSymbolAddress((void**)&aoh, g_aoh);   cudaGetSymbolAddress((void**)&aol, g_aol);
    cudaGetSymbolAddress((void**)&hidh, g_hidh); cudaGetSymbolAddress((void**)&hidl, g_hidl);
    cudaGetSymbolAddress((void**)&nupart, g_nupart);
    cudaGetSymbolAddress((void**)&nu, g_nu);
    cudaGetSymbolAddress((void**)&nuh, g_nuh);   cudaGetSymbolAddress((void**)&nul, g_nul);
    cudaGetSymbolAddress((void**)&nu16, g_nu16);
    cudaGetSymbolAddress((void**)&ab, g_ab);
    cudaGetSymbolAddress((void**)&trans, g_trans);
    cudaGetSymbolAddress((void**)&rel, g_rel);
    cudaGetSymbolAddress((void**)&rs16, g_rs16);
    cudaGetSymbolAddress((void**)&nr, g_nr);
    cudaGetSymbolAddress((void**)&elist, g_elist);
    cudaGetSymbolAddress((void**)&ecnt, g_ecnt);

    cudaFuncSetAttribute(gemm_mma, cudaFuncAttributeMaxDynamicSharedMemorySize, GSM);
    cudaFuncSetAttribute(gemm_mma, cudaFuncAttributePreferredSharedMemoryCarveout, 100);
    cudaFuncSetAttribute(gemm_sm, cudaFuncAttributeMaxDynamicSharedMemorySize, GSM2);
    cudaFuncSetAttribute(gemm_sm, cudaFuncAttributePreferredSharedMemoryCarveout, 100);
    cudaFuncSetAttribute(gemm_h1, cudaFuncAttributeMaxDynamicSharedMemorySize, GSMH);
    cudaFuncSetAttribute(gemm_h1, cudaFuncAttributePreferredSharedMemoryCarveout, 100);

    // weight prep (also zeroes g_ecnt)
    setup_k<<<1, 512>>>(wq, wk, wv, wo, w1, w2, rc_w1, kg_w, s2n_w, bq, bk, bvv);
    wconv_k<<<dim3(16, 16, 23), dim3(32, 8)>>>();

    // ln1 -> xn (hi/lo)
    ln1_k<<<BS, 256>>>(x, ln1_g, ln1_b, xnh, xnl);

    // QKV (z=3), fp32 out — small tile for 384 CTAs
    gemm_sm<<<dim3(8, 16, 3), 256, GSM2>>>(xnh, xnl, DD, 0, wTh, wTl, UU, DD,
                                           b3, DD, qkv, UU, DD, nullptr, nullptr, 0,
                                           DD, FL_F32);
    // attention (16-row tiled) + compact edge extraction
    attn_scores_k<<<dim3(8, HH, BB), 256>>>(qkv, qkv + UU, attn);
    edges_k<<<BS, 128>>>(attn, rel, elist, ecnt);
    attn_ctx_k<<<dim3(8, HH, BB), 256>>>(attn, qkv + 2 * UU, ctxh, ctxl);

    // ao = ctx @ wo + bo  (hi/lo only) — small tile
    gemm_sm<<<dim3(8, 16, 1), 256, GSM2>>>(ctxh, ctxl, DD, 0, wTh + 3L*UU, wTl + 3L*UU, 0, DD,
                                           bo, 0, nullptr, 0, 0, aoh, aol, DD,
                                           DD, FL_HILO);
    // hid = relu(ao @ w1 + b1) (hi/lo only, N=2048) — big tile
    gemm_mma<<<dim3(32, 8, 1), 256, GSM>>>(aoh, aol, DD, 0, wTh + 4L*UU, wTl + 4L*UU, 0, DD,
                                           b1, 0, nullptr, 0, 0, hidh, hidl, FF,
                                           DD, FL_HILO | FL_RELU);
    // nu partials = hid @ w2  (split-K z=4 into 4 slabs)
    gemm_mma<<<dim3(8, 8, 4), 256, GSM>>>(hidh, hidl, FF, DD, wTh + 8L*UU, wTl + 8L*UU, DD, FF,
                                          nullptr, 0, nupart, UU, DD, nullptr, nullptr, 0,
                                          DD, FL_F32);
    conv_nu_k<<<BS, 256>>>(nupart, b2, nu, nuh, nul, nu16);

    // a/b parts (z=2), bf16 3-pass — feeds discrete argmax
    gemm_mma<<<dim3(8, 8, 2), 256, GSM>>>(nuh, nul, DD, 0, wTh + 12L*UU, wTl + 12L*UU, UU, DD,
                                          nullptr, 0, ab, UU, DD, nullptr, nullptr, 0,
                                          DD, FL_F32);
    // relation classifier on compacted edges only
    pair2_k<<<64, 256>>>(ab, ab + UU, rc_b1, rc_w2, rc_b2, elist, ecnt, rel);

    // RGCN transforms: relations 1..7 only, fp16 single pass (continuous path)
    gemm_h1<<<dim3(8, 16, 7), 256, GSMH>>>(nu16, wT16 + UU, UU,
                                           nullptr, trans + UU, UU, DD);
    // aggregation -> reasoned fp16
    agg_k<<<BS, 256>>>(rel, trans, nu, rs16);

    // s2n projection, fp16 single pass (continuous path)
    gemm_h1<<<dim3(8, 16, 1), 256, GSMH>>>(rs16, wT16 + 8L*UU, 0,
                                           s2n_b, nr, 0, DD);
    // final residual LN
    ln2_k<<<BS, 256>>>(nr, x, ln2_g, ln2_b, out);
}

// round 14
// speedup vs baseline: 1.4643x; 1.0345x over previous
#include <cuda_runtime.h>
#include <cuda_bf16.h>
#include <cuda_fp16.h>
#include <math.h>
#include <stdint.h>

#define BB 4
#define SS 128
#define DD 512
#define HH 8
#define DH 64
#define FF 2048
#define RR 8
#define BS (BB*SS)          // 512
#define UU 262144           // 512*512
#define THRESH 0.1f
#define MAXE 8192

typedef __nv_bfloat16 bf16;

// ======================= helpers =======================
__device__ __forceinline__ uint32_t smem_u32(const void* p){
    uint32_t a;
    asm("{ .reg .u64 t; cvta.to.shared.u64 t, %1; cvt.u32.u64 %0, t; }" : "=r"(a) : "l"(p));
    return a;
}
__device__ __forceinline__ void ldsm4(uint32_t& r0, uint32_t& r1, uint32_t& r2, uint32_t& r3,
                                      uint32_t addr){
    asm volatile("ldmatrix.sync.aligned.m8n8.x4.shared.b16 {%0,%1,%2,%3}, [%4];"
                 : "=r"(r0), "=r"(r1), "=r"(r2), "=r"(r3) : "r"(addr));
}
__device__ __forceinline__ void mma16816(float* d, const uint32_t* a, const uint32_t* b){
    asm volatile("mma.sync.aligned.m16n8k16.row.col.f32.bf16.bf16.f32 "
                 "{%0,%1,%2,%3}, {%4,%5,%6,%7}, {%8,%9}, {%0,%1,%2,%3};"
                 : "+f"(d[0]), "+f"(d[1]), "+f"(d[2]), "+f"(d[3])
                 : "r"(a[0]), "r"(a[1]), "r"(a[2]), "r"(a[3]), "r"(b[0]), "r"(b[1]));
}
__device__ __forceinline__ void mma16816h(float* d, const uint32_t* a, const uint32_t* b){
    asm volatile("mma.sync.aligned.m16n8k16.row.col.f32.f16.f16.f32 "
                 "{%0,%1,%2,%3}, {%4,%5,%6,%7}, {%8,%9}, {%0,%1,%2,%3};"
                 : "+f"(d[0]), "+f"(d[1]), "+f"(d[2]), "+f"(d[3])
                 : "r"(a[0]), "r"(a[1]), "r"(a[2]), "r"(a[3]), "r"(b[0]), "r"(b[1]));
}
__device__ __forceinline__ void cpa16(uint32_t s, const void* g){
    asm volatile("cp.async.cg.shared.global [%0], [%1], 16;" :: "r"(s), "l"(g));
}
__device__ __forceinline__ void cpa_commit(){
    asm volatile("cp.async.commit_group;" ::: "memory");
}
template<int N> __device__ __forceinline__ void cpa_wait(){
    asm volatile("cp.async.wait_group %0;" :: "n"(N) : "memory");
}

// ======================= scratch (device globals) =======================
__device__ bf16  g_wTh[14*UU];          // bf16 hi weights (units 0..13)
__device__ bf16  g_wTl[14*UU];          // bf16 lo weights
__device__ __half g_wT16[9*UU];         // fp16 weights: kg relations 0..7, s2n (unit 8)
__device__ float g_b3[3*DD];            // packed q/k/v biases
__device__ bf16  g_xnh[UU], g_xnl[UU];
__device__ float g_qkv[3*UU];
__device__ float g_attn[BB*HH*SS*SS];
__device__ bf16  g_ctxh[UU], g_ctxl[UU];
__device__ bf16  g_aoh[UU],  g_aol[UU];
__device__ bf16  g_hidh[BS*FF], g_hidl[BS*FF];
__device__ float g_nupart[4*UU];        // split-K partials for nu
__device__ float g_nu[UU];
__device__ bf16  g_nuh[UU], g_nul[UU];
__device__ __half g_nu16[UU];
__device__ float g_ab[2*UU];            // a/b parts
__device__ float g_trans[8*UU];         // RGCN transform slabs [r][n][d], r=1..7 used
__device__ int   g_rel[BB*SS*SS];
__device__ __half g_rs16[UU];           // reasoned, fp16
__device__ float g_nr[UU];
__device__ int2  g_elist[MAXE];
__device__ int   g_ecnt;

// ========== prep: fused weight transpose/convert + ln1 + bias pack + counter reset ==========
// blocks 0..5887: wconv (z = bid/256, 16x16 xy tiles); blocks 5888..6399: ln1 rows
#define WBLK 5888

__global__ void prep_k(const float* __restrict__ wq, const float* __restrict__ wk,
                       const float* __restrict__ wv, const float* __restrict__ wo,
                       const float* __restrict__ w1, const float* __restrict__ w2,
                       const float* __restrict__ rc, const float* __restrict__ kg,
                       const float* __restrict__ s2n,
                       const float* __restrict__ bq, const float* __restrict__ bk,
                       const float* __restrict__ bvv,
                       const float* __restrict__ x, const float* __restrict__ g,
                       const float* __restrict__ b,
                       bf16* __restrict__ oh, bf16* __restrict__ ol)
{
    __shared__ float tile[32][33];
    __shared__ float rbuf[256];
    int bid = blockIdx.x, t = threadIdx.x;

    if (bid < WBLK) {
        int z = bid >> 8, rem = bid & 255;
        int bx = rem & 15, by = rem >> 4;
        const float* src; int ld; long dst; int dld;
        if (z < 3)       { const float* q3[3] = {wq, wk, wv};
                           src = q3[z]; ld = DD; dst = (long)z*UU; dld = DD; }
        else if (z == 3) { src = wo; ld = DD; dst = 3L*UU; dld = DD; }
        else if (z < 8)  { int u = z-4; src = w1 + u*DD; ld = FF; dst = 4L*UU + (long)u*UU; dld = DD; }
        else if (z < 12) { int u = z-8; src = w2 + (long)u*UU; ld = DD; dst = 8L*UU + (long)u*DD; dld = FF; }
        else if (z < 14) { int u = z-12; src = rc + (long)u*UU; ld = DD; dst = (12L+u)*UU; dld = DD; }
        else if (z < 22) { int u = z-14; src = kg + (long)u*UU; ld = DD; dst = (long)u*UU; dld = DD; }
        else             { src = s2n; ld = DD; dst = 8L*UU; dld = DD; }

        int k0 = by * 32, n0 = bx * 32;
        int tx = t & 31, ty = t >> 5;          // (32, 8)
#pragma unroll
        for (int i = 0; i < 4; i++)
            tile[ty + 8*i][tx] = __ldg(src + (long)(k0 + ty + 8*i) * ld + n0 + tx);
        __syncthreads();
        bool f16 = z >= 14;
#pragma unroll
        for (int i = 0; i < 2; i++) {
            int p = t + i * 256;
            int n = p >> 4, kp = p & 15;
            float v0 = tile[2*kp    ][n];
            float v1 = tile[2*kp + 1][n];
            long off = dst + (long)(n0 + n) * dld + k0 + 2*kp;
            if (f16) {
                __half2 ph; ph.x = __float2half(v0); ph.y = __float2half(v1);
                *(__half2*)&g_wT16[off] = ph;
            } else {
                bf16 h0 = __float2bfloat16(v0), h1 = __float2bfloat16(v1);
                __nv_bfloat162 ph; ph.x = h0; ph.y = h1;
                __nv_bfloat162 pl;
                pl.x = __float2bfloat16(v0 - __bfloat162float(h0));
                pl.y = __float2bfloat16(v1 - __bfloat162float(h1));
                *(__nv_bfloat162*)&g_wTh[off] = ph;
                *(__nv_bfloat162*)&g_wTl[off] = pl;
            }
        }
        return;
    }

    int row = bid - WBLK;                      // 0..511, ln1
    if (row == 0) {                            // extra init work on first LN block
        for (int i = t; i < DD; i += 256) {
            g_b3[i] = bq[i]; g_b3[DD+i] = bk[i]; g_b3[2*DD+i] = bvv[i];
        }
        if (t == 0) g_ecnt = 0;
    }
    long base = (long)row * DD;
    float v0 = x[base + t], v1 = x[base + t + 256];
    rbuf[t] = v0 + v1; __syncthreads();
    for (int s = 128; s > 0; s >>= 1) { if (t < s) rbuf[t] += rbuf[t + s]; __syncthreads(); }
    float mean = rbuf[0] * (1.0f / 512.0f);
    __syncthreads();
    float d0 = v0 - mean, d1 = v1 - mean;
    rbuf[t] = d0 * d0 + d1 * d1; __syncthreads();
    for (int s = 128; s > 0; s >>= 1) { if (t < s) rbuf[t] += rbuf[t + s]; __syncthreads(); }
    float rs = rsqrtf(rbuf[0] * (1.0f / 512.0f) + 1e-5f);
    float o0 = d0 * rs * g[t] + b[t];
    float o1 = d1 * rs * g[t + 256] + b[t + 256];
    bf16 h0 = __float2bfloat16(o0), h1 = __float2bfloat16(o1);
    oh[base + t] = h0;       ol[base + t]       = __float2bfloat16(o0 - __bfloat162float(h0));
    oh[base + t + 256] = h1; ol[base + t + 256] = __float2bfloat16(o1 - __bfloat162float(h1));
}

// ======================= mma.sync bf16 3-pass GEMM (64x64 tile, 2-stage) =======================
#define FL_F32  1
#define FL_HILO 2
#define FL_RELU 4

#define TSTRIDE 144
#define TILE_B  9216
#define STAGE_B 36864
#define GSM     73728

__global__ void __launch_bounds__(256, 3)
gemm_mma(const bf16* __restrict__ Ah, const bf16* __restrict__ Al, int lda, long a_z,
         const bf16* __restrict__ Bh, const bf16* __restrict__ Bl, long b_z, int ldb,
         const float* __restrict__ bias, int bias_z,
         float* __restrict__ C, long c_z, int ldc,
         bf16* __restrict__ Ch, bf16* __restrict__ Cl, int ldch,
         int K, int flags)
{
    extern __shared__ char sm[];
    uint32_t sb = smem_u32(sm);
    const int tid = threadIdx.x, lane = tid & 31, wid = tid >> 5;
    const int wm = wid >> 2, wn = wid & 3;
    const int m0 = blockIdx.y * 64, n0 = blockIdx.x * 64, z = blockIdx.z;
    const bf16* Ahp = Ah + (long)z * a_z;
    const bf16* Alp = Al + (long)z * a_z;
    const bf16* Bhp = Bh + (long)z * b_z;
    const bf16* Blp = Bl + (long)z * b_z;

    const int ld_r = tid >> 3, ld_c = (tid & 7) * 8;
    const uint32_t s_wr = (uint32_t)(ld_r * TSTRIDE + ld_c * 2);

    const int a_r = (lane & 7) + ((lane >> 3) & 1) * 8;
    const int a_c8 = (lane >> 4) * 8;
    const uint32_t aoff = (uint32_t)((wm * 32 + a_r) * TSTRIDE + a_c8 * 2);
    const int b_r = (lane & 7) + (lane >> 4) * 8;
    const int b_c8 = ((lane >> 3) & 1) * 8;
    const uint32_t boff = (uint32_t)((wn * 16 + b_r) * TSTRIDE + b_c8 * 2);

    float acc[2][2][4];
#pragma unroll
    for (int i = 0; i < 2; i++)
#pragma unroll
        for (int j = 0; j < 2; j++)
#pragma unroll
            for (int q = 0; q < 4; q++) acc[i][j][q] = 0.f;

    uint32_t fah[2][2][4], fal[2][2][4], fbh[2][2][2], fbl[2][2][2];

    const int nch = K >> 6;

    auto issue = [&](int kk, int st){
        uint32_t base = sb + st * STAGE_B + s_wr;
        const bf16* ga0 = Ahp + (long)(m0 + ld_r) * lda + kk + ld_c;
        const bf16* ga1 = Alp + (long)(m0 + ld_r) * lda + kk + ld_c;
        const bf16* gb0 = Bhp + (long)(n0 + ld_r) * ldb + kk + ld_c;
        const bf16* gb1 = Blp + (long)(n0 + ld_r) * ldb + kk + ld_c;
        cpa16(base,                         ga0);
        cpa16(base + 32 * TSTRIDE,          ga0 + 32 * lda);
        cpa16(base + TILE_B,                ga1);
        cpa16(base + TILE_B + 32 * TSTRIDE, ga1 + 32 * lda);
        cpa16(base + 2 * TILE_B,                gb0);
        cpa16(base + 2 * TILE_B + 32 * TSTRIDE, gb0 + 32 * ldb);
        cpa16(base + 3 * TILE_B,                gb1);
        cpa16(base + 3 * TILE_B + 32 * TSTRIDE, gb1 + 32 * ldb);
        cpa_commit();
    };

    issue(0, 0);
    for (int i = 0; i < nch; i++) {
        if (i + 1 < nch) { issue((i + 1) << 6, (i + 1) & 1); cpa_wait<1>(); }
        else             { cpa_wait<0>(); }
        __syncthreads();

        uint32_t st = sb + (i & 1) * STAGE_B;

        {
            ldsm4(fbh[0][0][0], fbh[0][0][1], fbh[0][1][0], fbh[0][1][1], st + 2*TILE_B + boff);
            ldsm4(fbl[0][0][0], fbl[0][0][1], fbl[0][1][0], fbl[0][1][1], st + 3*TILE_B + boff);
#pragma unroll
            for (int mf = 0; mf < 2; mf++)
                ldsm4(fah[0][mf][0], fah[0][mf][1], fah[0][mf][2], fah[0][mf][3],
                      st + aoff + mf * (16*TSTRIDE));
#pragma unroll
            for (int mf = 0; mf < 2; mf++)
                ldsm4(fal[0][mf][0], fal[0][mf][1], fal[0][mf][2], fal[0][mf][3],
                      st + TILE_B + aoff + mf * (16*TSTRIDE));
        }

#pragma unroll
        for (int ks = 0; ks < 4; ks++) {
            const int cur = ks & 1, nxt = cur ^ 1;
            if (ks < 3) {
                uint32_t kb = (ks + 1) * 32;
                ldsm4(fbh[nxt][0][0], fbh[nxt][0][1], fbh[nxt][1][0], fbh[nxt][1][1],
                      st + 2*TILE_B + boff + kb);
                ldsm4(fbl[nxt][0][0], fbl[nxt][0][1], fbl[nxt][1][0], fbl[nxt][1][1],
                      st + 3*TILE_B + boff + kb);
#pragma unroll
                for (int mf = 0; mf < 2; mf++)
                    ldsm4(fah[nxt][mf][0], fah[nxt][mf][1], fah[nxt][mf][2], fah[nxt][mf][3],
                          st + aoff + mf * (16*TSTRIDE) + kb);
#pragma unroll
                for (int mf = 0; mf < 2; mf++)
                    ldsm4(fal[nxt][mf][0], fal[nxt][mf][1], fal[nxt][mf][2], fal[nxt][mf][3],
                          st + TILE_B + aoff + mf * (16*TSTRIDE) + kb);
            }
#pragma unroll
            for (int mf = 0; mf < 2; mf++)
#pragma unroll
                for (int nf = 0; nf < 2; nf++) mma16816(acc[mf][nf], fah[cur][mf], fbh[cur][nf]);
#pragma unroll
            for (int mf = 0; mf < 2; mf++)
#pragma unroll
                for (int nf = 0; nf < 2; nf++) mma16816(acc[mf][nf], fah[cur][mf], fbl[cur][nf]);
#pragma unroll
            for (int mf = 0; mf < 2; mf++)
#pragma unroll
                for (int nf = 0; nf < 2; nf++) mma16816(acc[mf][nf], fal[cur][mf], fbh[cur][nf]);
        }
        __syncthreads();
    }

    const int g = lane >> 2, tg = lane & 3;
    const float* bp = bias ? bias + (long)z * bias_z : nullptr;
    float* Cz = C ? C + (long)z * c_z : nullptr;
#pragma unroll
    for (int mf = 0; mf < 2; mf++) {
#pragma unroll
        for (int nf = 0; nf < 2; nf++) {
            int row = m0 + wm * 32 + mf * 16 + g;
            int col = n0 + wn * 16 + nf * 8 + tg * 2;
            float v0 = acc[mf][nf][0], v1 = acc[mf][nf][1];
            float v2 = acc[mf][nf][2], v3 = acc[mf][nf][3];
            if (bp) {
                float bb0 = __ldg(bp + col), bb1 = __ldg(bp + col + 1);
                v0 += bb0; v1 += bb1; v2 += bb0; v3 += bb1;
            }
            if (flags & FL_RELU) {
                v0 = fmaxf(v0, 0.f); v1 = fmaxf(v1, 0.f);
                v2 = fmaxf(v2, 0.f); v3 = fmaxf(v3, 0.f);
            }
            if (flags & FL_F32) {
                *(float2*)&Cz[(long)row * ldc + col] = make_float2(v0, v1);
                *(float2*)&Cz[(long)(row + 8) * ldc + col] = make_float2(v2, v3);
            }
            if (flags & FL_HILO) {
                bf16 h0 = __float2bfloat16(v0), h1 = __float2bfloat16(v1);
                bf16 h2 = __float2bfloat16(v2), h3 = __float2bfloat16(v3);
                __nv_bfloat162 ph0; ph0.x = h0; ph0.y = h1;
                __nv_bfloat162 ph1; ph1.x = h2; ph1.y = h3;
                __nv_bfloat162 pl0, pl1;
                pl0.x = __float2bfloat16(v0 - __bfloat162float(h0));
                pl0.y = __float2bfloat16(v1 - __bfloat162float(h1));
                pl1.x = __float2bfloat16(v2 - __bfloat162float(h2));
                pl1.y = __float2bfloat16(v3 - __bfloat162float(h3));
                *(__nv_bfloat162*)&Ch[(long)row * ldch + col] = ph0;
                *(__nv_bfloat162*)&Cl[(long)row * ldch + col] = pl0;
                *(__nv_bfloat162*)&Ch[(long)(row + 8) * ldch + col] = ph1;
                *(__nv_bfloat162*)&Cl[(long)(row + 8) * ldch + col] = pl1;
            }
        }
    }
}

// ============ small-tile bf16 variant: 32x64 CTA tile ============
#define OA_H2 0
#define OA_L2 4608
#define OB_H2 9216
#define OB_L2 18432
#define STAGE2 27648
#define GSM2 55296

__global__ void __launch_bounds__(256, 4)
gemm_sm(const bf16* __restrict__ Ah, const bf16* __restrict__ Al, int lda, long a_z,
        const bf16* __restrict__ Bh, const bf16* __restrict__ Bl, long b_z, int ldb,
        const float* __restrict__ bias, int bias_z,
        float* __restrict__ C, long c_z, int ldc,
        bf16* __restrict__ Ch, bf16* __restrict__ Cl, int ldch,
        int K, int flags)
{
    extern __shared__ char sm[];
    uint32_t sb = smem_u32(sm);
    const int tid = threadIdx.x, lane = tid & 31, wid = tid >> 5;
    const int wm = wid >> 2, wn = wid & 3;
    const int m0 = blockIdx.y * 32, n0 = blockIdx.x * 64, z = blockIdx.z;
    const bf16* Ahp = Ah + (long)z * a_z;
    const bf16* Alp = Al + (long)z * a_z;
    const bf16* Bhp = Bh + (long)z * b_z;
    const bf16* Blp = Bl + (long)z * b_z;

    const int ld_r = tid >> 3, ld_c = (tid & 7) * 8;
    const uint32_t s_wr = (uint32_t)(ld_r * TSTRIDE + ld_c * 2);

    const int a_r = (lane & 7) + ((lane >> 3) & 1) * 8;
    const int a_c8 = (lane >> 4) * 8;
    const uint32_t aoff = (uint32_t)((wm * 16 + a_r) * TSTRIDE + a_c8 * 2);
    const int b_r = (lane & 7) + (lane >> 4) * 8;
    const int b_c8 = ((lane >> 3) & 1) * 8;
    const uint32_t boff = (uint32_t)((wn * 16 + b_r) * TSTRIDE + b_c8 * 2);

    float acc[2][4];
#pragma unroll
    for (int j = 0; j < 2; j++)
#pragma unroll
        for (int q = 0; q < 4; q++) acc[j][q] = 0.f;

    uint32_t fah[2][4], fal[2][4], fbh[2][2][2], fbl[2][2][2];

    const int nch = K >> 6;

    auto issue = [&](int kk, int st){
        uint32_t base = sb + st * STAGE2 + s_wr;
        const bf16* ga0 = Ahp + (long)(m0 + ld_r) * lda + kk + ld_c;
        const bf16* ga1 = Alp + (long)(m0 + ld_r) * lda + kk + ld_c;
        const bf16* gb0 = Bhp + (long)(n0 + ld_r) * ldb + kk + ld_c;
        const bf16* gb1 = Blp + (long)(n0 + ld_r) * ldb + kk + ld_c;
        cpa16(base + OA_H2, ga0);
        cpa16(base + OA_L2, ga1);
        cpa16(base + OB_H2,                gb0);
        cpa16(base + OB_H2 + 32 * TSTRIDE, gb0 + 32 * ldb);
        cpa16(base + OB_L2,                gb1);
        cpa16(base + OB_L2 + 32 * TSTRIDE, gb1 + 32 * ldb);
        cpa_commit();
    };

    issue(0, 0);
    for (int i = 0; i < nch; i++) {
        if (i + 1 < nch) { issue((i + 1) << 6, (i + 1) & 1); cpa_wait<1>(); }
        else             { cpa_wait<0>(); }
        __syncthreads();

        uint32_t st = sb + (i & 1) * STAGE2;

        ldsm4(fbh[0][0][0], fbh[0][0][1], fbh[0][1][0], fbh[0][1][1], st + OB_H2 + boff);
        ldsm4(fbl[0][0][0], fbl[0][0][1], fbl[0][1][0], fbl[0][1][1], st + OB_L2 + boff);
        ldsm4(fah[0][0], fah[0][1], fah[0][2], fah[0][3], st + OA_H2 + aoff);
        ldsm4(fal[0][0], fal[0][1], fal[0][2], fal[0][3], st + OA_L2 + aoff);

#pragma unroll
        for (int ks = 0; ks < 4; ks++) {
            const int cur = ks & 1, nxt = cur ^ 1;
            if (ks < 3) {
                uint32_t kb = (ks + 1) * 32;
                ldsm4(fbh[nxt][0][0], fbh[nxt][0][1], fbh[nxt][1][0], fbh[nxt][1][1],
                      st + OB_H2 + boff + kb);
                ldsm4(fbl[nxt][0][0], fbl[nxt][0][1], fbl[nxt][1][0], fbl[nxt][1][1],
                      st + OB_L2 + boff + kb);
                ldsm4(fah[nxt][0], fah[nxt][1], fah[nxt][2], fah[nxt][3],
                      st + OA_H2 + aoff + kb);
                ldsm4(fal[nxt][0], fal[nxt][1], fal[nxt][2], fal[nxt][3],
                      st + OA_L2 + aoff + kb);
            }
#pragma unroll
            for (int nf = 0; nf < 2; nf++) mma16816(acc[nf], fah[cur], fbh[cur][nf]);
#pragma unroll
            for (int nf = 0; nf < 2; nf++) mma16816(acc[nf], fah[cur], fbl[cur][nf]);
#pragma unroll
            for (int nf = 0; nf < 2; nf++) mma16816(acc[nf], fal[cur], fbh[cur][nf]);
        }
        __syncthreads();
    }

    const int g = lane >> 2, tg = lane & 3;
    const float* bp = bias ? bias + (long)z * bias_z : nullptr;
    float* Cz = C ? C + (long)z * c_z : nullptr;
#pragma unroll
    for (int nf = 0; nf < 2; nf++) {
        int row = m0 + wm * 16 + g;
        int col = n0 + wn * 16 + nf * 8 + tg * 2;
        float v0 = acc[nf][0], v1 = acc[nf][1];
        float v2 = acc[nf][2], v3 = acc[nf][3];
        if (bp) {
            float bb0 = __ldg(bp + col), bb1 = __ldg(bp + col + 1);
            v0 += bb0; v1 += bb1; v2 += bb0; v3 += bb1;
        }
        if (flags & FL_RELU) {
            v0 = fmaxf(v0, 0.f); v1 = fmaxf(v1, 0.f);
            v2 = fmaxf(v2, 0.f); v3 = fmaxf(v3, 0.f);
        }
        if (flags & FL_F32) {
            *(float2*)&Cz[(long)row * ldc + col] = make_float2(v0, v1);
            *(float2*)&Cz[(long)(row + 8) * ldc + col] = make_float2(v2, v3);
        }
        if (flags & FL_HILO) {
            bf16 h0 = __float2bfloat16(v0), h1 = __float2bfloat16(v1);
            bf16 h2 = __float2bfloat16(v2), h3 = __float2bfloat16(v3);
            __nv_bfloat162 ph0; ph0.x = h0; ph0.y = h1;
            __nv_bfloat162 ph1; ph1.x = h2; ph1.y = h3;
            __nv_bfloat162 pl0, pl1;
            pl0.x = __float2bfloat16(v0 - __bfloat162float(h0));
            pl0.y = __float2bfloat16(v1 - __bfloat162float(h1));
            pl1.x = __float2bfloat16(v2 - __bfloat162float(h2));
            pl1.y = __float2bfloat16(v3 - __bfloat162float(h3));
            *(__nv_bfloat162*)&Ch[(long)row * ldch + col] = ph0;
            *(__nv_bfloat162*)&Cl[(long)row * ldch + col] = pl0;
            *(__nv_bfloat162*)&Ch[(long)(row + 8) * ldch + col] = ph1;
            *(__nv_bfloat162*)&Cl[(long)(row + 8) * ldch + col] = pl1;
        }
    }
}

// ============ fp16 SINGLE-pass GEMM, 32x64 CTA tile (continuous-path GEMMs) ============
#define HOA 0
#define HOB 4608
#define HSTAGE 13824
#define GSMH 27648

__global__ void __launch_bounds__(256, 4)
gemm_h1(const __half* __restrict__ A, const __half* __restrict__ B, long b_z,
        const float* __restrict__ bias, float* __restrict__ C, long c_z, int K)
{
    extern __shared__ char sm[];
    uint32_t sb = smem_u32(sm);
    const int tid = threadIdx.x, lane = tid & 31, wid = tid >> 5;
    const int wm = wid >> 2, wn = wid & 3;
    const int m0 = blockIdx.y * 32, n0 = blockIdx.x * 64, z = blockIdx.z;
    const __half* Bp = B + (long)z * b_z;

    const int ld_r = tid >> 3, ld_c = (tid & 7) * 8;
    const uint32_t s_wr = (uint32_t)(ld_r * TSTRIDE + ld_c * 2);

    const int a_r = (lane & 7) + ((lane >> 3) & 1) * 8;
    const int a_c8 = (lane >> 4) * 8;
    const uint32_t aoff = (uint32_t)((wm * 16 + a_r) * TSTRIDE + a_c8 * 2);
    const int b_r = (lane & 7) + (lane >> 4) * 8;
    const int b_c8 = ((lane >> 3) & 1) * 8;
    const uint32_t boff = (uint32_t)((wn * 16 + b_r) * TSTRIDE + b_c8 * 2);

    float acc[2][4];
#pragma unroll
    for (int j = 0; j < 2; j++)
#pragma unroll
        for (int q = 0; q < 4; q++) acc[j][q] = 0.f;

    uint32_t fa[2][4], fb[2][2][2];

    const int nch = K >> 6;

    auto issue = [&](int kk, int st){
        uint32_t base = sb + st * HSTAGE + s_wr;
        cpa16(base + HOA, A + (long)(m0 + ld_r) * K + kk + ld_c);
        const __half* gb = Bp + (long)(n0 + ld_r) * K + kk + ld_c;
        cpa16(base + HOB,                gb);
        cpa16(base + HOB + 32 * TSTRIDE, gb + 32 * K);
        cpa_commit();
    };

    issue(0, 0);
    for (int i = 0; i < nch; i++) {
        if (i + 1 < nch) { issue((i + 1) << 6, (i + 1) & 1); cpa_wait<1>(); }
        else             { cpa_wait<0>(); }
        __syncthreads();

        uint32_t st = sb + (i & 1) * HSTAGE;

        ldsm4(fb[0][0][0], fb[0][0][1], fb[0][1][0], fb[0][1][1], st + HOB + boff);
        ldsm4(fa[0][0], fa[0][1], fa[0][2], fa[0][3], st + HOA + aoff);

#pragma unroll
        for (int ks = 0; ks < 4; ks++) {
            const int cur = ks & 1, nxt = cur ^ 1;
            if (ks < 3) {
                uint32_t kb = (ks + 1) * 32;
                ldsm4(fb[nxt][0][0], fb[nxt][0][1], fb[nxt][1][0], fb[nxt][1][1],
                      st + HOB + boff + kb);
                ldsm4(fa[nxt][0], fa[nxt][1], fa[nxt][2], fa[nxt][3],
                      st + HOA + aoff + kb);
            }
#pragma unroll
            for (int nf = 0; nf < 2; nf++) mma16816h(acc[nf], fa[cur], fb[cur][nf]);
        }
        __syncthreads();
    }

    const int g = lane >> 2, tg = lane & 3;
    float* Cz = C + (long)z * c_z;
#pragma unroll
    for (int nf = 0; nf < 2; nf++) {
        int row = m0 + wm * 16 + g;
        int col = n0 + wn * 16 + nf * 8 + tg * 2;
        float v0 = acc[nf][0], v1 = acc[nf][1];
        float v2 = acc[nf][2], v3 = acc[nf][3];
        if (bias) {
            float bb0 = __ldg(bias + col), bb1 = __ldg(bias + col + 1);
            v0 += bb0; v1 += bb1; v2 += bb0; v3 += bb1;
        }
        *(float2*)&Cz[(long)row * DD + col] = make_float2(v0, v1);
        *(float2*)&Cz[(long)(row + 8) * DD + col] = make_float2(v2, v3);
    }
}

// ======================= LayerNorm 2 (residual, fp32 out) =======================
__global__ void ln2_k(const float* __restrict__ in, const float* __restrict__ add,
                      const float* __restrict__ g, const float* __restrict__ b,
                      float* __restrict__ out)
{
    int row = blockIdx.x, t = threadIdx.x;
    __shared__ float rbuf[256];
    long base = (long)row * DD;
    float v0 = in[base + t] + add[base + t];
    float v1 = in[base + t + 256] + add[base + t + 256];
    rbuf[t] = v0 + v1; __syncthreads();
    for (int s = 128; s > 0; s >>= 1) { if (t < s) rbuf[t] += rbuf[t + s]; __syncthreads(); }
    float mean = rbuf[0] * (1.0f / 512.0f);
    __syncthreads();
    float d0 = v0 - mean, d1 = v1 - mean;
    rbuf[t] = d0 * d0 + d1 * d1; __syncthreads();
    for (int s = 128; s > 0; s >>= 1) { if (t < s) rbuf[t] += rbuf[t + s]; __syncthreads(); }
    float rs = rsqrtf(rbuf[0] * (1.0f / 512.0f) + 1e-5f);
    out[base + t]       = d0 * rs * g[t]       + b[t];
    out[base + t + 256] = d1 * rs * g[t + 256] + b[t + 256];
}

// ========== fused attention: scores + softmax + ctx, 16-row tiles ==========
__global__ void attn_fused_k(const float* __restrict__ q, const float* __restrict__ k,
                             const float* __restrict__ v, float* __restrict__ attn,
                             bf16* __restrict__ ch, bf16* __restrict__ cl)
{
    int it = blockIdx.x, h = blockIdx.y, b = blockIdx.z;  // 256 thr
    int t = threadIdx.x;
    int i0 = it * 16;
    __shared__ float ks[SS][DH + 1];      // K tile, later reused for V tile
    __shared__ float qs[16][DH + 1];
    __shared__ float P[16][SS];
    const float* kbase = k + (long)b * SS * DD + h * DH;
    const float* qbase = q + (long)b * SS * DD + h * DH;
    for (int idx = t; idx < SS * DH; idx += 256) {
        int j = idx >> 6, d = idx & 63;
        ks[j][d] = kbase[(long)j * DD + d];
    }
    for (int idx = t; idx < 16 * DH; idx += 256) {
        int r = idx >> 6, d = idx & 63;
        qs[r][d] = qbase[(long)(i0 + r) * DD + d];
    }
    __syncthreads();
    // scores
    {
        int j = t & 127, grp = t >> 7;
#pragma unroll
        for (int r = 0; r < 8; r++) {
            int i = grp * 8 + r;
            float acc = 0.f;
#pragma unroll
            for (int d = 0; d < DH; d++) acc += qs[i][d] * ks[j][d];
            P[i][j] = acc * 0.125f;
        }
    }
    __syncthreads();
    // softmax: warp w handles rows 2w, 2w+1; writes attn + keeps P normalized
    {
        int w = t >> 5, ln = t & 31;
        long obase = (((long)(b * HH + h) * SS) + i0) * SS;
#pragma unroll
        for (int rr = 0; rr < 2; rr++) {
            int i = w * 2 + rr;
            float m = -1e30f;
#pragma unroll
            for (int c = 0; c < 4; c++) m = fmaxf(m, P[i][ln + c * 32]);
#pragma unroll
            for (int o = 16; o > 0; o >>= 1) m = fmaxf(m, __shfl_xor_sync(0xffffffffu, m, o));
            float s = 0.f, e[4];
#pragma unroll
            for (int c = 0; c < 4; c++) { e[c] = expf(P[i][ln + c * 32] - m); s += e[c]; }
#pragma unroll
            for (int o = 16; o > 0; o >>= 1) s += __shfl_xor_sync(0xffffffffu, s, o);
            float inv = 1.0f / s;
#pragma unroll
            for (int c = 0; c < 4; c++) {
                float pv = e[c] * inv;
                P[i][ln + c * 32] = pv;
                attn[obase + (long)i * SS + ln + c * 32] = pv;
            }
        }
    }
    __syncthreads();
    // load V into the dead K tile
    const float* vbase = v + (long)b * SS * DD + h * DH;
    for (int idx = t; idx < SS * DH; idx += 256) {
        int j = idx >> 6, dd = idx & 63;
        ks[j][dd] = vbase[(long)j * DD + dd];
    }
    __syncthreads();
    // ctx = P @ V
    {
        int d = t & 63, ig = t >> 6;
        float acc[4] = {0.f, 0.f, 0.f, 0.f};
#pragma unroll
        for (int jh = 0; jh < 2; jh++) {
            float vreg[64];
#pragma unroll
            for (int jj = 0; jj < 64; jj++) vreg[jj] = ks[jh * 64 + jj][d];
#pragma unroll
            for (int r = 0; r < 4; r++) {
                int i = ig + 4 * r;
                float a = acc[r];
#pragma unroll
                for (int jj = 0; jj < 64; jj++) a += P[i][jh * 64 + jj] * vreg[jj];
                acc[r] = a;
            }
        }
#pragma unroll
        for (int r = 0; r < 4; r++) {
            int i = ig + 4 * r;
            long o = (long)(b * SS + i0 + i) * DD + h * DH + d;
            bf16 hh = __float2bfloat16(acc[r]);
            ch[o] = hh; cl[o] = __float2bfloat16(acc[r] - __bfloat162float(hh));
        }
    }
}

// ======== edges: head-mean + threshold + compact edge list ========
__global__ void edges_k(const float* __restrict__ attn, int* __restrict__ rel,
                        int2* __restrict__ elist, int* __restrict__ ecnt)
{
    int bu = blockIdx.x;                 // b*S + u
    int b = bu >> 7, u = bu & 127, v = threadIdx.x;  // 128 thr
    float s = 0.f;
#pragma unroll
    for (int h = 0; h < HH; h++)
        s += attn[(((long)(b * HH + h) * SS) + u) * SS + v];
    s *= 0.125f;
    long ridx = (long)bu * SS + v;
    rel[ridx] = 0;
    if ((s > THRESH) && (u != v)) {
        int p = atomicAdd(ecnt, 1);
        if (p < MAXE) elist[p] = make_int2(bu, v);
    }
}

// ======== pair classifier on compacted edges: one warp per edge ========
__global__ void __launch_bounds__(256)
pair2_k(const float* __restrict__ ap, const float* __restrict__ bp,
        const float* __restrict__ rc_b1, const float* __restrict__ rc_w2,
        const float* __restrict__ rc_b2,
        const int2* __restrict__ elist, const int* __restrict__ ecnt,
        int* __restrict__ rel)
{
    int total = *ecnt; if (total > MAXE) total = MAXE;
    int wg = blockIdx.x * 8 + (threadIdx.x >> 5);
    int nw = gridDim.x * 8;
    int lane = threadIdx.x & 31;

    for (int e = wg; e < total; e += nw) {
        int2 ed = elist[e];
        int bu = ed.x, v = ed.y;
        int bb = bu >> 7;
        const float* A = ap + (long)bu * DD;
        const float* B = bp + ((long)(bb * SS + v)) * DD;
        float acc[RR];
#pragma unroll
        for (int r = 0; r < RR; r++) acc[r] = 0.f;
#pragma unroll
        for (int c = 0; c < 4; c++) {
            int d = c * 128 + lane * 4;
            float4 a4 = *(const float4*)(A + d);
            float4 b4 = *(const float4*)(B + d);
            float4 c4 = *(const float4*)(rc_b1 + d);
            float hs[4];
            hs[0] = fmaxf(a4.x + b4.x + c4.x, 0.f);
            hs[1] = fmaxf(a4.y + b4.y + c4.y, 0.f);
            hs[2] = fmaxf(a4.z + b4.z + c4.z, 0.f);
            hs[3] = fmaxf(a4.w + b4.w + c4.w, 0.f);
#pragma unroll
            for (int j = 0; j < 4; j++) {
                float4 w0 = *(const float4*)(rc_w2 + (long)(d + j) * RR);
                float4 w1 = *(const float4*)(rc_w2 + (long)(d + j) * RR + 4);
                acc[0] += hs[j] * w0.x; acc[1] += hs[j] * w0.y;
                acc[2] += hs[j] * w0.z; acc[3] += hs[j] * w0.w;
                acc[4] += hs[j] * w1.x; acc[5] += hs[j] * w1.y;
                acc[6] += hs[j] * w1.z; acc[7] += hs[j] * w1.w;
            }
        }
#pragma unroll
        for (int r = 0; r < RR; r++)
#pragma unroll
            for (int o = 16; o > 0; o >>= 1)
                acc[r] += __shfl_xor_sync(0xffffffffu, acc[r], o);
        if (lane == 0) {
            int pred = 0; float best = acc[0] + rc_b2[0];
#pragma unroll
            for (int r = 1; r < RR; r++) {
                float lg = acc[r] + rc_b2[r];
                if (lg > best) { best = lg; pred = r; }
            }
            if (pred != 0) rel[(long)bu * SS + v] = pred;
        }
    }
}

// ============= nu: reduce split-K partials + bias + bf16 hi/lo + fp16 =============
__global__ void conv_nu_k(const float* __restrict__ P, const float* __restrict__ b2,
                          float* __restrict__ nu, bf16* __restrict__ H, bf16* __restrict__ L,
                          __half* __restrict__ N16)
{
    int row = blockIdx.x, t = threadIdx.x;  // 256
    for (int c = t; c < DD; c += 256) {
        long i = (long)row * DD + c;
        float v = b2[c] + P[i] + P[UU + i] + P[2L*UU + i] + P[3L*UU + i];
        nu[i] = v;
        bf16 h = __float2bfloat16(v);
        H[i] = h; L[i] = __float2bfloat16(v - __bfloat162float(h));
        N16[i] = __float2half(v);
    }
}

// ======================= edge aggregation (writes reasoned fp16) =======================
__global__ void agg_k(const int* __restrict__ rel, const float* __restrict__ trans,
                      const float* __restrict__ nu, __half* __restrict__ r16)
{
    int bv = blockIdx.x;                 // b*S + v
    int b = bv >> 7, v = bv & 127, t = threadIdx.x;   // 256
    __shared__ int sr[SS];
    if (t < SS) sr[t] = rel[((long)b * SS + t) * SS + v];
    __syncthreads();
    float a0 = 0.f, a1 = 0.f;
    for (int u = 0; u < SS; u++) {
        int r = sr[u];
        if (r) {
            const float* tr = trans + (long)r * UU + (long)(b * SS + u) * DD;
            a0 += tr[t]; a1 += tr[t + 256];
        }
    }
    long row = (long)bv * DD;
    r16[row + t]       = __float2half(nu[row + t] + a0);
    r16[row + t + 256] = __float2half(nu[row + t + 256] + a1);
}

// ======================= launch =======================
extern "C" void kernel_launch(void* const* d_in, const int* in_sizes, int n_in,
                              void* d_out, int out_size)
{
    const float* x     = (const float*)d_in[0];
    const float* ln1_g = (const float*)d_in[1];
    const float* ln1_b = (const float*)d_in[2];
    const float* wq    = (const float*)d_in[3];
    const float* bq    = (const float*)d_in[4];
    const float* wk    = (const float*)d_in[5];
    const float* bk    = (const float*)d_in[6];
    const float* wv    = (const float*)d_in[7];
    const float* bvv   = (const float*)d_in[8];
    const float* wo    = (const float*)d_in[9];
    const float* bo    = (const float*)d_in[10];
    const float* w1    = (const float*)d_in[11];
    const float* b1    = (const float*)d_in[12];
    const float* w2    = (const float*)d_in[13];
    const float* b2    = (const float*)d_in[14];
    const float* rc_w1 = (const float*)d_in[15];
    const float* rc_b1 = (const float*)d_in[16];
    const float* rc_w2 = (const float*)d_in[17];
    const float* rc_b2 = (const float*)d_in[18];
    const float* kg_w  = (const float*)d_in[19];
    const float* s2n_w = (const float*)d_in[20];
    const float* s2n_b = (const float*)d_in[21];
    const float* ln2_g = (const float*)d_in[22];
    const float* ln2_b = (const float*)d_in[23];
    float* out = (float*)d_out;

    bf16 *wTh, *wTl, *xnh, *xnl, *ctxh, *ctxl, *aoh, *aol, *hidh, *hidl, *nuh, *nul;
    __half *wT16, *nu16, *rs16;
    float *b3, *qkv, *attn, *nupart, *nu, *ab, *trans, *nr;
    int *rel, *ecnt;
    int2 *elist;
    cudaGetSymbolAddress((void**)&wTh, g_wTh);   cudaGetSymbolAddress((void**)&wTl, g_wTl);
    cudaGetSymbolAddress((void**)&wT16, g_wT16);
    cudaGetSymbolAddress((void**)&b3, g_b3);
    cudaGetSymbolAddress((void**)&xnh, g_xnh);   cudaGetSymbolAddress((void**)&xnl, g_xnl);
    cudaGetSymbolAddress((void**)&qkv, g_qkv);
    cudaGetSymbolAddress((void**)&attn, g_attn);
    cudaGetSymbolAddress((void**)&ctxh, g_ctxh); cudaGetSymbolAddress((void**)&ctxl, g_ctxl);
    cudaGetSymbolAddress((void**)&aoh, g_aoh);   cudaGetSymbolAddress((void**)&aol, g_aol);
    cudaGetSymbolAddress((void**)&hidh, g_hidh); cudaGetSymbolAddress((void**)&hidl, g_hidl);
    cudaGetSymbolAddress((void**)&nupart, g_nupart);
    cudaGetSymbolAddress((void**)&nu, g_nu);
    cudaGetSymbolAddress((void**)&nuh, g_nuh);   cudaGetSymbolAddress((void**)&nul, g_nul);
    cudaGetSymbolAddress((void**)&nu16, g_nu16);
    cudaGetSymbolAddress((void**)&ab, g_ab);
    cudaGetSymbolAddress((void**)&trans, g_trans);
    cudaGetSymbolAddress((void**)&rel, g_rel);
    cudaGetSymbolAddress((void**)&rs16, g_rs16);
    cudaGetSymbolAddress((void**)&nr, g_nr);
    cudaGetSymbolAddress((void**)&elist, g_elist);
    cudaGetSymbolAddress((void**)&ecnt, g_ecnt);

    cudaFuncSetAttribute(gemm_mma, cudaFuncAttributeMaxDynamicSharedMemorySize, GSM);
    cudaFuncSetAttribute(gemm_mma, cudaFuncAttributePreferredSharedMemoryCarveout, 100);
    cudaFuncSetAttribute(gemm_sm, cudaFuncAttributeMaxDynamicSharedMemorySize, GSM2);
    cudaFuncSetAttribute(gemm_sm, cudaFuncAttributePreferredSharedMemoryCarveout, 100);
    cudaFuncSetAttribute(gemm_h1, cudaFuncAttributeMaxDynamicSharedMemorySize, GSMH);
    cudaFuncSetAttribute(gemm_h1, cudaFuncAttributePreferredSharedMemoryCarveout, 100);

    // fused prep: weight transpose/convert + ln1 + bias pack + edge-counter reset
    prep_k<<<WBLK + BS, 256>>>(wq, wk, wv, wo, w1, w2, rc_w1, kg_w, s2n_w,
                               bq, bk, bvv, x, ln1_g, ln1_b, xnh, xnl);

    // QKV (z=3), fp32 out — small tile for 384 CTAs
    gemm_sm<<<dim3(8, 16, 3), 256, GSM2>>>(xnh, xnl, DD, 0, wTh, wTl, UU, DD,
                                           b3, DD, qkv, UU, DD, nullptr, nullptr, 0,
                                           DD, FL_F32);
    // fused attention (scores + softmax + ctx) + edge extraction
    attn_fused_k<<<dim3(8, HH, BB), 256>>>(qkv, qkv + UU, qkv + 2 * UU, attn, ctxh, ctxl);
    edges_k<<<BS, 128>>>(attn, rel, elist, ecnt);

    // ao = ctx @ wo + bo  (hi/lo only) — small tile
    gemm_sm<<<dim3(8, 16, 1), 256, GSM2>>>(ctxh, ctxl, DD, 0, wTh + 3L*UU, wTl + 3L*UU, 0, DD,
                                           bo, 0, nullptr, 0, 0, aoh, aol, DD,
                                           DD, FL_HILO);
    // hid = relu(ao @ w1 + b1) (hi/lo only, N=2048) — big tile
    gemm_mma<<<dim3(32, 8, 1), 256, GSM>>>(aoh, aol, DD, 0, wTh + 4L*UU, wTl + 4L*UU, 0, DD,
                                           b1, 0, nullptr, 0, 0, hidh, hidl, FF,
                                           DD, FL_HILO | FL_RELU);
    // nu partials = hid @ w2  (split-K z=4 into 4 slabs)
    gemm_mma<<<dim3(8, 8, 4), 256, GSM>>>(hidh, hidl, FF, DD, wTh + 8L*UU, wTl + 8L*UU, DD, FF,
                                          nullptr, 0, nupart, UU, DD, nullptr, nullptr, 0,
                                          DD, FL_F32);
    conv_nu_k<<<BS, 256>>>(nupart, b2, nu, nuh, nul, nu16);

    // a/b parts (z=2), bf16 3-pass — feeds discrete argmax
    gemm_mma<<<dim3(8, 8, 2), 256, GSM>>>(nuh, nul, DD, 0, wTh + 12L*UU, wTl + 12L*UU, UU, DD,
                                          nullptr, 0, ab, UU, DD, nullptr, nullptr, 0,
                                          DD, FL_F32);
    // relation classifier on compacted edges only
    pair2_k<<<64, 256>>>(ab, ab + UU, rc_b1, rc_w2, rc_b2, elist, ecnt, rel);

    // RGCN transforms: relations 1..7 only, fp16 single pass (continuous path)
    gemm_h1<<<dim3(8, 16, 7), 256, GSMH>>>(nu16, wT16 + UU, UU,
                                           nullptr, trans + UU, UU, DD);
    // aggregation -> reasoned fp16
    agg_k<<<BS, 256>>>(rel, trans, nu, rs16);

    // s2n projection, fp16 single pass (continuous path)
    gemm_h1<<<dim3(8, 16, 1), 256, GSMH>>>(rs16, wT16 + 8L*UU, 0,
                                           s2n_b, nr, 0, DD);
    // final residual LN
    ln2_k<<<BS, 256>>>(nr, x, ln2_g, ln2_b, out);
}